// round 3
// baseline (speedup 1.0000x reference)
#include <cuda_runtime.h>

#define CC    112
#define CLSN  20
#define NSMAX 8192
#define NQMAX 20000
#define GRID  16
#define GRID3 (GRID * GRID * GRID)
#define CELLH 8.0f
#define INVH  0.125f

// ---------------- scratch (device globals; no allocation) ----------------
__device__ float  g_logits[NSMAX];
__device__ float  g_a[NSMAX];
__device__ float  g_part[256 * CC];
__device__ float  g_gate[CC];
__device__ float  g_Wf[CC * CLSN];
__device__ float4 g_s4[NSMAX];      // original order
__device__ int    g_cellid[NSMAX];
__device__ int    g_cellcnt[GRID3];
__device__ int    g_celloff[GRID3];
__device__ int    g_cellstart[GRID3 + 1];
__device__ float4 g_sp4[NSMAX];     // cell-sorted
__device__ int    g_sidx[NSMAX];    // original index, cell-sorted
__device__ float  g_FS1[NSMAX * CC];
__device__ float  g_XW[NQMAX * CC];

// ---------------- K0: s4, cell histogram, Wf = W2@Wcls ---------------------
__global__ void k_prep(const float* __restrict__ coords_s,
                       const float* __restrict__ W2,
                       const float* __restrict__ Wcls, int NS)
{
    int idx = blockIdx.x * blockDim.x + threadIdx.x;
    if (idx < NS) {
        float x = coords_s[idx * 3 + 0];
        float y = coords_s[idx * 3 + 1];
        float z = coords_s[idx * 3 + 2];
        g_s4[idx] = make_float4(x, y, z, x * x + y * y + z * z);
        int cx = min(GRID - 1, max(0, (int)(x * INVH)));
        int cy = min(GRID - 1, max(0, (int)(y * INVH)));
        int cz = min(GRID - 1, max(0, (int)(z * INVH)));
        int cell = (cz * GRID + cy) * GRID + cx;
        g_cellid[idx] = cell;
        atomicAdd(&g_cellcnt[cell], 1);
    } else {
        int j = idx - NS;
        if (j < CC * CLSN) {
            int c = j / CLSN, o = j % CLSN;
            float s = 0.f;
            #pragma unroll 8
            for (int k = 0; k < CC; k++)
                s = fmaf(W2[c * CC + k], Wcls[k * CLSN + o], s);
            g_Wf[j] = s;
        }
    }
}

// ---------------- K0b: exclusive prefix sum over 4096 cell counts ----------
__global__ void k_scan()
{
    __shared__ int sh[1024];
    int t = threadIdx.x;
    int base = t * 4;
    int c0 = g_cellcnt[base], c1 = g_cellcnt[base + 1];
    int c2 = g_cellcnt[base + 2], c3 = g_cellcnt[base + 3];
    int local = c0 + c1 + c2 + c3;
    sh[t] = local;
    __syncthreads();
    for (int off = 1; off < 1024; off <<= 1) {
        int v = sh[t];
        int u = (t >= off) ? sh[t - off] : 0;
        __syncthreads();
        sh[t] = v + u;
        __syncthreads();
    }
    int excl = sh[t] - local;
    g_cellstart[base]     = excl;
    g_cellstart[base + 1] = excl + c0;
    g_cellstart[base + 2] = excl + c0 + c1;
    g_cellstart[base + 3] = excl + c0 + c1 + c2;
    if (t == 1023) g_cellstart[GRID3] = sh[1023];
}

// ---------------- K0c: scatter points into cell order ----------------------
__global__ void k_scatter(int NS)
{
    int i = blockIdx.x * blockDim.x + threadIdx.x;
    if (i < NS) {
        int cell = g_cellid[i];
        int pos = g_cellstart[cell] + atomicAdd(&g_celloff[cell], 1);
        g_sp4[pos] = g_s4[i];
        g_sidx[pos] = i;
    }
}

// ---------------- K0d: per-cell insertion sort by original index -----------
__global__ void k_cellsort()
{
    int cell = blockIdx.x * blockDim.x + threadIdx.x;
    if (cell >= GRID3) return;
    int s = g_cellstart[cell], e = g_cellstart[cell + 1];
    for (int i = s + 1; i < e; i++) {
        int   ki = g_sidx[i];
        float4 kv = g_sp4[i];
        int j = i - 1;
        while (j >= s && g_sidx[j] > ki) {
            g_sidx[j + 1] = g_sidx[j];
            g_sp4[j + 1] = g_sp4[j];
            j--;
        }
        g_sidx[j + 1] = ki;
        g_sp4[j + 1] = kv;
    }
}

// ---------------- K1: logits[i] = feat_s7[i,:] . w_attn --------------------
__global__ void k_logits(const float* __restrict__ F,
                         const float* __restrict__ w, int NS)
{
    int gt   = blockIdx.x * blockDim.x + threadIdx.x;
    int warp = gt >> 5;
    int lane = gt & 31;
    int nwarps = (gridDim.x * blockDim.x) >> 5;
    float w0 = w[lane], w1 = w[lane + 32], w2 = w[lane + 64];
    float w3 = (lane < 16) ? w[lane + 96] : 0.f;
    for (int i = warp; i < NS; i += nwarps) {
        const float* row = F + i * CC;
        float s = row[lane] * w0 + row[lane + 32] * w1 + row[lane + 64] * w2;
        if (lane < 16) s += row[lane + 96] * w3;
        #pragma unroll
        for (int o = 16; o; o >>= 1) s += __shfl_xor_sync(0xffffffffu, s, o);
        if (lane == 0) g_logits[i] = s;
    }
}

// ---------------- K2: softmax over logits -> g_a --------------------------
__global__ void k_softmax(int NS)
{
    __shared__ float red[1024];
    int t = threadIdx.x;
    float mx = -1e30f;
    for (int i = t; i < NS; i += 1024) mx = fmaxf(mx, g_logits[i]);
    red[t] = mx; __syncthreads();
    for (int s = 512; s; s >>= 1) { if (t < s) red[t] = fmaxf(red[t], red[t + s]); __syncthreads(); }
    mx = red[0]; __syncthreads();
    float sum = 0.f;
    for (int i = t; i < NS; i += 1024) sum += __expf(g_logits[i] - mx);
    red[t] = sum; __syncthreads();
    for (int s = 512; s; s >>= 1) { if (t < s) red[t] += red[t + s]; __syncthreads(); }
    float inv = 1.f / red[0];
    for (int i = t; i < NS; i += 1024) g_a[i] = __expf(g_logits[i] - mx) * inv;
}

// ---------------- K3: partial weighted sums (32 rows / block) --------------
__global__ void k_gpool(const float* __restrict__ F, int NS)
{
    __shared__ float sacc[8][CC];
    int w = threadIdx.x >> 5, lane = threadIdx.x & 31;
    float p0 = 0.f, p1 = 0.f, p2 = 0.f, p3 = 0.f;
    int base = blockIdx.x * 32 + w * 4;        // 4 rows per warp
    #pragma unroll
    for (int t = 0; t < 4; t++) {
        int i = base + t;
        if (i < NS) {
            float ai = g_a[i];
            const float* row = F + i * CC;
            p0 = fmaf(ai, row[lane], p0);
            p1 = fmaf(ai, row[lane + 32], p1);
            p2 = fmaf(ai, row[lane + 64], p2);
            if (lane < 16) p3 = fmaf(ai, row[lane + 96], p3);
        }
    }
    sacc[w][lane]      = p0;
    sacc[w][lane + 32] = p1;
    sacc[w][lane + 64] = p2;
    if (lane < 16) sacc[w][lane + 96] = p3;
    __syncthreads();
    if (threadIdx.x < CC) {
        float s = 0.f;
        #pragma unroll
        for (int k = 0; k < 8; k++) s += sacc[k][threadIdx.x];
        g_part[blockIdx.x * CC + threadIdx.x] = s;
    }
}

// ---------------- K4: gate[c] = sigmoid(sum_b part[b][c]) ------------------
__global__ void k_gate(int nparts)
{
    int c = threadIdx.x;
    if (c < CC) {
        float s = 0.f;
        for (int b = 0; b < nparts; b++) s += g_part[b * CC + c];
        g_gate[c] = 1.f / (1.f + __expf(-s));
    }
}

// ---------------- K5/K6: tiled SGEMM, 128x112 tile, 8x7 per thread ---------
__global__ void k_sgemm112(const float* __restrict__ A,
                           const float* __restrict__ B,
                           float* __restrict__ Cm,
                           int M, int use_gate,
                           const float* __restrict__ colscale)
{
    __shared__ float As[128][29];
    __shared__ float Bs[28][112];
    int tx = threadIdx.x;
    int m0 = blockIdx.x * 128;
    float acc[8][7];
    #pragma unroll
    for (int i = 0; i < 8; i++)
        #pragma unroll
        for (int j = 0; j < 7; j++) acc[i][j] = 0.f;
    int rg = (tx >> 4) * 8;      // 0..120 step 8
    int cg = (tx & 15) * 7;      // 0..105 step 7
    for (int k0 = 0; k0 < CC; k0 += 28) {
        #pragma unroll 4
        for (int idx = tx; idx < 128 * 28; idx += 256) {
            int r = idx / 28, k = idx - r * 28;
            int gr = m0 + r;
            As[r][k] = (gr < M) ? A[gr * CC + k0 + k] : 0.f;
        }
        #pragma unroll 4
        for (int idx = tx; idx < 28 * 112; idx += 256) {
            int k = idx / 112, c = idx - k * 112;
            float v = B[(k0 + k) * CC + c];
            if (use_gate) v *= g_gate[k0 + k];
            Bs[k][c] = v;
        }
        __syncthreads();
        #pragma unroll 7
        for (int k = 0; k < 28; k++) {
            float a[8], b[7];
            #pragma unroll
            for (int i = 0; i < 8; i++) a[i] = As[rg + i][k];
            #pragma unroll
            for (int j = 0; j < 7; j++) b[j] = Bs[k][cg + j];
            #pragma unroll
            for (int i = 0; i < 8; i++)
                #pragma unroll
                for (int j = 0; j < 7; j++)
                    acc[i][j] = fmaf(a[i], b[j], acc[i][j]);
        }
        __syncthreads();
    }
    float cs[7];
    #pragma unroll
    for (int j = 0; j < 7; j++) cs[j] = colscale[cg + j];
    #pragma unroll
    for (int i = 0; i < 8; i++) {
        int gr = m0 + rg + i;
        if (gr < M) {
            #pragma unroll
            for (int j = 0; j < 7; j++)
                Cm[gr * CC + cg + j] = acc[i][j] * cs[j];
        }
    }
}

// ---------------- top-3 insert helper --------------------------------------
__device__ __forceinline__ void ins3(float v, int jj,
                                     float& b0, float& b1, float& b2,
                                     int& i0, int& i1, int& i2)
{
    if (v < b2) {
        if (v < b1) {
            b2 = b1; i2 = i1;
            if (v < b0) { b1 = b0; i1 = i0; b0 = v; i0 = jj; }
            else        { b1 = v;  i1 = jj; }
        } else { b2 = v; i2 = jj; }
    }
}

// ---------------- K7: grid kNN + gather + ReLU + classifier ----------------
__global__ void k_final(const float* __restrict__ coords_q,
                        const float* __restrict__ beta,
                        const float* __restrict__ bcls,
                        float* __restrict__ out,
                        int NQ)
{
    __shared__ float Wf[CC * CLSN];
    __shared__ float sbeta[CC];
    __shared__ float sb[CLSN];
    int tx = threadIdx.x;
    for (int i = tx; i < CC * CLSN; i += 128) Wf[i] = g_Wf[i];
    if (tx < CC)   sbeta[tx] = beta[tx];
    if (tx < CLSN) sb[tx] = bcls[tx];
    __syncthreads();

    int q = blockIdx.x * 128 + tx;
    if (q >= NQ) return;

    float qx = coords_q[q * 3 + 0];
    float qy = coords_q[q * 3 + 1];
    float qz = coords_q[q * 3 + 2];
    float nx = -2.f * qx, ny = -2.f * qy, nz = -2.f * qz;
    float q2 = qx * qx + qy * qy + qz * qz;

    int cx = min(GRID - 1, max(0, (int)(qx * INVH)));
    int cy = min(GRID - 1, max(0, (int)(qy * INVH)));
    int cz = min(GRID - 1, max(0, (int)(qz * INVH)));

    // top-3 smallest of v = |s|^2 - 2 q.s  (= d2 - |q|^2)
    float b0 = 1e30f, b1 = 1e30f, b2 = 1e30f;
    int   i0 = 0, i1 = 0, i2 = 0;

    for (int D = 0; D < GRID; D++) {
        int z0 = max(cz - D, 0), z1 = min(cz + D, GRID - 1);
        int y0 = max(cy - D, 0), y1 = min(cy + D, GRID - 1);
        int x0 = max(cx - D, 0), x1 = min(cx + D, GRID - 1);
        for (int z = z0; z <= z1; z++) {
            int adz = abs(z - cz);
            for (int y = y0; y <= y1; y++) {
                int ady = max(adz, abs(y - cy));
                for (int x = x0; x <= x1; x++) {
                    int ch = max(ady, abs(x - cx));
                    if (ch != D) continue;
                    int cell = (z * GRID + y) * GRID + x;
                    int p  = g_cellstart[cell];
                    int pe = g_cellstart[cell + 1];
                    for (; p < pe; p++) {
                        float4 s = g_sp4[p];
                        float v = fmaf(s.x, nx, fmaf(s.y, ny, fmaf(s.z, nz, s.w)));
                        ins3(v, g_sidx[p], b0, b1, b2, i0, i1, i2);
                    }
                }
            }
        }
        float dd = (float)D * CELLH;
        if (b2 + q2 <= dd * dd) break;   // ring D complete; farther points >= D*h
    }

    // softmax(-d2) over the 3 (shift-invariant)
    float e1 = __expf(b0 - b1);
    float e2 = __expf(b0 - b2);
    float inv = 1.f / (1.f + e1 + e2);
    float w0 = inv, w1 = e1 * inv, w2 = e2 * inv;

    const float4* xw = (const float4*)(g_XW + (size_t)q * CC);
    const float4* f0 = (const float4*)(g_FS1 + (size_t)i0 * CC);
    const float4* f1 = (const float4*)(g_FS1 + (size_t)i1 * CC);
    const float4* f2 = (const float4*)(g_FS1 + (size_t)i2 * CC);

    float acc[CLSN];
    #pragma unroll
    for (int o = 0; o < CLSN; o++) acc[o] = sb[o];

    #pragma unroll 4
    for (int c4 = 0; c4 < CC / 4; c4++) {
        float4 x  = xw[c4];
        float4 a0 = f0[c4];
        float4 a1 = f1[c4];
        float4 a2 = f2[c4];
        int cb = c4 * 4;
        float h[4];
        h[0] = x.x + w0 * a0.x + w1 * a1.x + w2 * a2.x + sbeta[cb + 0];
        h[1] = x.y + w0 * a0.y + w1 * a1.y + w2 * a2.y + sbeta[cb + 1];
        h[2] = x.z + w0 * a0.z + w1 * a1.z + w2 * a2.z + sbeta[cb + 2];
        h[3] = x.w + w0 * a0.w + w1 * a1.w + w2 * a2.w + sbeta[cb + 3];
        #pragma unroll
        for (int u = 0; u < 4; u++) {
            float hv = fmaxf(h[u], 0.f);
            const float* wrow = &Wf[(cb + u) * CLSN];
            #pragma unroll
            for (int o = 0; o < CLSN; o++) acc[o] = fmaf(hv, wrow[o], acc[o]);
        }
    }

    float* op = out + (size_t)q * CLSN;
    #pragma unroll
    for (int o = 0; o < CLSN; o++) op[o] = acc[o];
}

// ---------------- launch ---------------------------------------------------
extern "C" void kernel_launch(void* const* d_in, const int* in_sizes, int n_in,
                              void* d_out, int out_size)
{
    const float* coords_q = (const float*)d_in[0];
    const float* coords_s = (const float*)d_in[1];
    const float* x7       = (const float*)d_in[2];
    const float* feat_s7  = (const float*)d_in[3];
    const float* feat_s   = (const float*)d_in[4];
    const float* w_attn   = (const float*)d_in[5];
    const float* W1       = (const float*)d_in[6];
    const float* gamma    = (const float*)d_in[7];
    const float* beta     = (const float*)d_in[8];
    const float* W2       = (const float*)d_in[9];
    const float* W_cls    = (const float*)d_in[10];
    const float* b_cls    = (const float*)d_in[11];
    float* out = (float*)d_out;

    int NQ = in_sizes[0] / 3;
    int NS = in_sizes[1] / 3;
    int nparts = (NS + 31) / 32;          // k_gpool blocks (<=256)

    float* g_FS1p; cudaGetSymbolAddress((void**)&g_FS1p, g_FS1);
    float* g_XWp;  cudaGetSymbolAddress((void**)&g_XWp,  g_XW);
    int* cntp;  cudaGetSymbolAddress((void**)&cntp,  g_cellcnt);
    int* offp;  cudaGetSymbolAddress((void**)&offp,  g_celloff);

    cudaMemsetAsync(cntp, 0, GRID3 * sizeof(int));
    cudaMemsetAsync(offp, 0, GRID3 * sizeof(int));

    k_prep<<<(NS + CC * CLSN + 255) / 256, 256>>>(coords_s, W2, W_cls, NS);
    k_scan<<<1, 1024>>>();
    k_scatter<<<(NS + 255) / 256, 256>>>(NS);
    k_cellsort<<<(GRID3 + 255) / 256, 256>>>();
    k_logits<<<128, 256>>>(feat_s7, w_attn, NS);
    k_softmax<<<1, 1024>>>(NS);
    k_gpool<<<nparts, 256>>>(feat_s7, NS);
    k_gate<<<1, 128>>>(nparts);
    // FS1 = (feat_s @ W1_bot) * gamma (cols)
    k_sgemm112<<<(NS + 127) / 128, 256>>>(feat_s, W1 + CC * CC, g_FS1p, NS, 0, gamma);
    // XW  = (x7 @ diag(gate) W1_top) * gamma (cols)
    k_sgemm112<<<(NQ + 127) / 128, 256>>>(x7, W1, g_XWp, NQ, 1, gamma);
    k_final<<<(NQ + 127) / 128, 128>>>(coords_q, beta, b_cls, out, NQ);
}

// round 4
// speedup vs baseline: 1.5352x; 1.5352x over previous
#include <cuda_runtime.h>

#define CC    112
#define CLSN  20
#define NSMAX 8192
#define NQMAX 20000
#define PARTS 16

// ---------------- scratch (device globals; no allocation) ----------------
__device__ float  g_logits[NSMAX];
__device__ float  g_a[NSMAX];
__device__ float  g_part[128 * CC];
__device__ float  g_gate[CC];
__device__ float  g_Wf[CC * CLSN];
__device__ float4 g_pkA[NSMAX / 2 + 1];   // (x0,x1,y0,y1) per point pair
__device__ float4 g_pkB[NSMAX / 2 + 1];   // (z0,z1,w0,w1) per point pair
__device__ float  g_FS1[NSMAX * CC];
__device__ float  g_XW[NQMAX * CC];

// ---------------- K0: pair-packed SoA coords, Wf = W2@Wcls ------------------
__global__ void k_prep(const float* __restrict__ coords_s,
                       const float* __restrict__ W2,
                       const float* __restrict__ Wcls, int NS, int npairs)
{
    int idx = blockIdx.x * blockDim.x + threadIdx.x;
    if (idx < npairs) {
        int i0 = 2 * idx, i1 = 2 * idx + 1;
        float x0 = coords_s[i0 * 3 + 0];
        float y0 = coords_s[i0 * 3 + 1];
        float z0 = coords_s[i0 * 3 + 2];
        float w0 = x0 * x0 + y0 * y0 + z0 * z0;
        float x1 = 0.f, y1 = 0.f, z1 = 0.f, w1 = 1e30f;
        if (i1 < NS) {
            x1 = coords_s[i1 * 3 + 0];
            y1 = coords_s[i1 * 3 + 1];
            z1 = coords_s[i1 * 3 + 2];
            w1 = x1 * x1 + y1 * y1 + z1 * z1;
        }
        g_pkA[idx] = make_float4(x0, x1, y0, y1);
        g_pkB[idx] = make_float4(z0, z1, w0, w1);
    } else {
        int j = idx - npairs;
        if (j < CC * CLSN) {
            int c = j / CLSN, o = j % CLSN;
            float s = 0.f;
            #pragma unroll 8
            for (int k = 0; k < CC; k++)
                s = fmaf(W2[c * CC + k], Wcls[k * CLSN + o], s);
            g_Wf[j] = s;
        }
    }
}

// ---------------- K1: logits[i] = feat_s7[i,:] . w_attn --------------------
__global__ void k_logits(const float* __restrict__ F,
                         const float* __restrict__ w, int NS)
{
    int gt   = blockIdx.x * blockDim.x + threadIdx.x;
    int warp = gt >> 5;
    int lane = gt & 31;
    int nwarps = (gridDim.x * blockDim.x) >> 5;
    float w0 = w[lane], w1 = w[lane + 32], w2 = w[lane + 64];
    float w3 = (lane < 16) ? w[lane + 96] : 0.f;
    for (int i = warp; i < NS; i += nwarps) {
        const float* row = F + i * CC;
        float s = row[lane] * w0 + row[lane + 32] * w1 + row[lane + 64] * w2;
        if (lane < 16) s += row[lane + 96] * w3;
        #pragma unroll
        for (int o = 16; o; o >>= 1) s += __shfl_xor_sync(0xffffffffu, s, o);
        if (lane == 0) g_logits[i] = s;
    }
}

// ---------------- K2: softmax over logits -> g_a --------------------------
__global__ void k_softmax(int NS)
{
    __shared__ float red[1024];
    int t = threadIdx.x;
    float mx = -1e30f;
    for (int i = t; i < NS; i += 1024) mx = fmaxf(mx, g_logits[i]);
    red[t] = mx; __syncthreads();
    for (int s = 512; s; s >>= 1) { if (t < s) red[t] = fmaxf(red[t], red[t + s]); __syncthreads(); }
    mx = red[0]; __syncthreads();
    float sum = 0.f;
    for (int i = t; i < NS; i += 1024) sum += __expf(g_logits[i] - mx);
    red[t] = sum; __syncthreads();
    for (int s = 512; s; s >>= 1) { if (t < s) red[t] += red[t + s]; __syncthreads(); }
    float inv = 1.f / red[0];
    for (int i = t; i < NS; i += 1024) g_a[i] = __expf(g_logits[i] - mx) * inv;
}

// ---------------- K3: partial weighted sums g_part[b][c] -------------------
__global__ void k_gpool(const float* __restrict__ F, int NS)
{
    __shared__ float sacc[8][CC];
    int w = threadIdx.x >> 5, lane = threadIdx.x & 31;
    float p0 = 0.f, p1 = 0.f, p2 = 0.f, p3 = 0.f;
    int base = blockIdx.x * 64 + w * 8;
    #pragma unroll
    for (int t = 0; t < 8; t++) {
        int i = base + t;
        if (i < NS) {
            float ai = g_a[i];
            const float* row = F + i * CC;
            p0 = fmaf(ai, row[lane], p0);
            p1 = fmaf(ai, row[lane + 32], p1);
            p2 = fmaf(ai, row[lane + 64], p2);
            if (lane < 16) p3 = fmaf(ai, row[lane + 96], p3);
        }
    }
    sacc[w][lane]      = p0;
    sacc[w][lane + 32] = p1;
    sacc[w][lane + 64] = p2;
    if (lane < 16) sacc[w][lane + 96] = p3;
    __syncthreads();
    if (threadIdx.x < CC) {
        float s = 0.f;
        #pragma unroll
        for (int k = 0; k < 8; k++) s += sacc[k][threadIdx.x];
        g_part[blockIdx.x * CC + threadIdx.x] = s;
    }
}

// ---------------- K4: gate[c] = sigmoid(sum_b part[b][c]) ------------------
__global__ void k_gate(int nparts)
{
    int c = threadIdx.x;
    if (c < CC) {
        float s = 0.f;
        for (int b = 0; b < nparts; b++) s += g_part[b * CC + c];
        g_gate[c] = 1.f / (1.f + __expf(-s));
    }
}

// ---------------- K5/K6: tiled SGEMM, N=K=112 (round-2 proven tile) --------
__global__ void k_sgemm112(const float* __restrict__ A,
                           const float* __restrict__ B,
                           float* __restrict__ Cm,
                           int M, int use_gate,
                           const float* __restrict__ colscale)
{
    __shared__ float As[64][57];
    __shared__ float Bs[56][112];
    int tx = threadIdx.x;
    int m0 = blockIdx.x * 64;
    float acc[4][7];
    #pragma unroll
    for (int i = 0; i < 4; i++)
        #pragma unroll
        for (int j = 0; j < 7; j++) acc[i][j] = 0.f;
    int rg = (tx >> 4) << 2;
    int cg = (tx & 15) * 7;
    for (int k0 = 0; k0 < CC; k0 += 56) {
        for (int idx = tx; idx < 64 * 56; idx += 256) {
            int r = idx / 56, k = idx - r * 56;
            int gr = m0 + r;
            As[r][k] = (gr < M) ? A[gr * CC + k0 + k] : 0.f;
        }
        for (int idx = tx; idx < 56 * 112; idx += 256) {
            int k = idx / 112, c = idx - k * 112;
            float v = B[(k0 + k) * CC + c];
            if (use_gate) v *= g_gate[k0 + k];
            Bs[k][c] = v;
        }
        __syncthreads();
        #pragma unroll 4
        for (int k = 0; k < 56; k++) {
            float a0 = As[rg][k], a1 = As[rg + 1][k], a2 = As[rg + 2][k], a3 = As[rg + 3][k];
            float b[7];
            #pragma unroll
            for (int j = 0; j < 7; j++) b[j] = Bs[k][cg + j];
            #pragma unroll
            for (int j = 0; j < 7; j++) {
                acc[0][j] = fmaf(a0, b[j], acc[0][j]);
                acc[1][j] = fmaf(a1, b[j], acc[1][j]);
                acc[2][j] = fmaf(a2, b[j], acc[2][j]);
                acc[3][j] = fmaf(a3, b[j], acc[3][j]);
            }
        }
        __syncthreads();
    }
    float cs[7];
    #pragma unroll
    for (int j = 0; j < 7; j++) cs[j] = colscale[cg + j];
    #pragma unroll
    for (int i = 0; i < 4; i++) {
        int gr = m0 + rg + i;
        if (gr < M) {
            #pragma unroll
            for (int j = 0; j < 7; j++)
                Cm[gr * CC + cg + j] = acc[i][j] * cs[j];
        }
    }
}

// ---------------- top-3 insert helper --------------------------------------
__device__ __forceinline__ void ins3(float v, int jj,
                                     float& b0, float& b1, float& b2,
                                     int& i0, int& i1, int& i2)
{
    if (v < b2) {
        if (v < b1) {
            b2 = b1; i2 = i1;
            if (v < b0) { b1 = b0; i1 = i0; b0 = v; i0 = jj; }
            else        { b1 = v;  i1 = jj; }
        } else { b2 = v; i2 = jj; }
    }
}

__device__ __forceinline__ unsigned long long fma_f32x2(unsigned long long a,
                                                        unsigned long long b,
                                                        unsigned long long c)
{
    unsigned long long d;
    asm("fma.rn.f32x2 %0, %1, %2, %3;" : "=l"(d) : "l"(a), "l"(b), "l"(c));
    return d;
}

// ---------------- K7: split-scan kNN (f32x2) + gather + ReLU + classifier --
__global__ void __launch_bounds__(512, 2)
k_final(const float* __restrict__ coords_q,
        const float* __restrict__ beta,
        const float* __restrict__ bcls,
        float* __restrict__ out,
        int NQ, int npairs)
{
    __shared__ float Wf[CC * CLSN];
    __shared__ float sbeta[CC];
    __shared__ float sb[CLSN];
    __shared__ float cv[PARTS][32][3];
    __shared__ int   ci[PARTS][32][3];
    int tx = threadIdx.x;
    int qlocal = tx & 31, part = tx >> 5;

    for (int i = tx; i < CC * CLSN; i += 512) Wf[i] = g_Wf[i];
    if (tx < CC)   sbeta[tx] = beta[tx];
    if (tx < CLSN) sb[tx] = bcls[tx];
    __syncthreads();

    int q = blockIdx.x * 32 + qlocal;
    bool valid = (q < NQ);
    float nx = 0.f, ny = 0.f, nz = 0.f;
    if (valid) {
        nx = -2.f * coords_q[q * 3 + 0];
        ny = -2.f * coords_q[q * 3 + 1];
        nz = -2.f * coords_q[q * 3 + 2];
    }
    unsigned xb = __float_as_uint(nx), yb = __float_as_uint(ny), zb = __float_as_uint(nz);
    unsigned long long nxx = (unsigned long long)xb | ((unsigned long long)xb << 32);
    unsigned long long nyy = (unsigned long long)yb | ((unsigned long long)yb << 32);
    unsigned long long nzz = (unsigned long long)zb | ((unsigned long long)zb << 32);

    int per = npairs / PARTS;
    int jb = part * per;
    int je = (part == PARTS - 1) ? npairs : jb + per;

    // top-3 smallest of v = |s|^2 - 2 q.s
    float b0 = 1e30f, b1 = 1e30f, b2 = 1e30f;
    int   i0 = 0, i1 = 0, i2 = 0;

    const ulonglong2* PA = (const ulonglong2*)g_pkA;
    const ulonglong2* PB = (const ulonglong2*)g_pkB;

    int j = jb;
    for (; j + 1 < je; j += 2) {
        ulonglong2 a0 = __ldg(&PA[j]);      // (x0x1, y0y1)
        ulonglong2 c0 = __ldg(&PB[j]);      // (z0z1, w0w1)
        ulonglong2 a1 = __ldg(&PA[j + 1]);
        ulonglong2 c1 = __ldg(&PB[j + 1]);
        unsigned long long v0 = fma_f32x2(a0.x, nxx, c0.y);
        unsigned long long v1 = fma_f32x2(a1.x, nxx, c1.y);
        v0 = fma_f32x2(a0.y, nyy, v0);
        v1 = fma_f32x2(a1.y, nyy, v1);
        v0 = fma_f32x2(c0.x, nzz, v0);
        v1 = fma_f32x2(c1.x, nzz, v1);
        float v0l = __uint_as_float((unsigned)v0);
        float v0h = __uint_as_float((unsigned)(v0 >> 32));
        float v1l = __uint_as_float((unsigned)v1);
        float v1h = __uint_as_float((unsigned)(v1 >> 32));
        float m = fminf(fminf(v0l, v0h), fminf(v1l, v1h));
        if (m < b2) {
            ins3(v0l, 2 * j,     b0, b1, b2, i0, i1, i2);
            ins3(v0h, 2 * j + 1, b0, b1, b2, i0, i1, i2);
            ins3(v1l, 2 * j + 2, b0, b1, b2, i0, i1, i2);
            ins3(v1h, 2 * j + 3, b0, b1, b2, i0, i1, i2);
        }
    }
    for (; j < je; j++) {
        ulonglong2 a0 = __ldg(&PA[j]);
        ulonglong2 c0 = __ldg(&PB[j]);
        unsigned long long v0 = fma_f32x2(a0.x, nxx, c0.y);
        v0 = fma_f32x2(a0.y, nyy, v0);
        v0 = fma_f32x2(c0.x, nzz, v0);
        float v0l = __uint_as_float((unsigned)v0);
        float v0h = __uint_as_float((unsigned)(v0 >> 32));
        if (fminf(v0l, v0h) < b2) {
            ins3(v0l, 2 * j,     b0, b1, b2, i0, i1, i2);
            ins3(v0h, 2 * j + 1, b0, b1, b2, i0, i1, i2);
        }
    }

    cv[part][qlocal][0] = b0; ci[part][qlocal][0] = i0;
    cv[part][qlocal][1] = b1; ci[part][qlocal][1] = i1;
    cv[part][qlocal][2] = b2; ci[part][qlocal][2] = i2;
    __syncthreads();

    if (part != 0 || !valid) return;

    b0 = cv[0][qlocal][0]; i0 = ci[0][qlocal][0];
    b1 = cv[0][qlocal][1]; i1 = ci[0][qlocal][1];
    b2 = cv[0][qlocal][2]; i2 = ci[0][qlocal][2];
    #pragma unroll
    for (int p = 1; p < PARTS; p++) {
        #pragma unroll
        for (int k = 0; k < 3; k++)
            ins3(cv[p][qlocal][k], ci[p][qlocal][k], b0, b1, b2, i0, i1, i2);
    }

    float e1 = __expf(b0 - b1);
    float e2 = __expf(b0 - b2);
    float inv = 1.f / (1.f + e1 + e2);
    float w0 = inv, w1 = e1 * inv, w2 = e2 * inv;

    const float4* xw = (const float4*)(g_XW + (size_t)q * CC);
    const float4* f0 = (const float4*)(g_FS1 + (size_t)i0 * CC);
    const float4* f1 = (const float4*)(g_FS1 + (size_t)i1 * CC);
    const float4* f2 = (const float4*)(g_FS1 + (size_t)i2 * CC);

    float acc[CLSN];
    #pragma unroll
    for (int o = 0; o < CLSN; o++) acc[o] = sb[o];

    for (int c4 = 0; c4 < CC / 4; c4++) {
        float4 x  = xw[c4];
        float4 a0 = f0[c4];
        float4 a1 = f1[c4];
        float4 a2 = f2[c4];
        int cb = c4 * 4;
        float h[4];
        h[0] = x.x + w0 * a0.x + w1 * a1.x + w2 * a2.x + sbeta[cb + 0];
        h[1] = x.y + w0 * a0.y + w1 * a1.y + w2 * a2.y + sbeta[cb + 1];
        h[2] = x.z + w0 * a0.z + w1 * a1.z + w2 * a2.z + sbeta[cb + 2];
        h[3] = x.w + w0 * a0.w + w1 * a1.w + w2 * a2.w + sbeta[cb + 3];
        #pragma unroll
        for (int u = 0; u < 4; u++) {
            float hv = fmaxf(h[u], 0.f);
            const float* wrow = &Wf[(cb + u) * CLSN];
            #pragma unroll
            for (int o = 0; o < CLSN; o++) acc[o] = fmaf(hv, wrow[o], acc[o]);
        }
    }

    float* op = out + (size_t)q * CLSN;
    #pragma unroll
    for (int o = 0; o < CLSN; o++) op[o] = acc[o];
}

// ---------------- launch ---------------------------------------------------
extern "C" void kernel_launch(void* const* d_in, const int* in_sizes, int n_in,
                              void* d_out, int out_size)
{
    const float* coords_q = (const float*)d_in[0];
    const float* coords_s = (const float*)d_in[1];
    const float* x7       = (const float*)d_in[2];
    const float* feat_s7  = (const float*)d_in[3];
    const float* feat_s   = (const float*)d_in[4];
    const float* w_attn   = (const float*)d_in[5];
    const float* W1       = (const float*)d_in[6];
    const float* gamma    = (const float*)d_in[7];
    const float* beta     = (const float*)d_in[8];
    const float* W2       = (const float*)d_in[9];
    const float* W_cls    = (const float*)d_in[10];
    const float* b_cls    = (const float*)d_in[11];
    float* out = (float*)d_out;

    int NQ = in_sizes[0] / 3;
    int NS = in_sizes[1] / 3;
    int npairs = (NS + 1) / 2;
    int nparts = (NS + 63) / 64;

    float* g_FS1p; cudaGetSymbolAddress((void**)&g_FS1p, g_FS1);
    float* g_XWp;  cudaGetSymbolAddress((void**)&g_XWp,  g_XW);

    k_prep<<<(npairs + CC * CLSN + 255) / 256, 256>>>(coords_s, W2, W_cls, NS, npairs);
    k_logits<<<64, 256>>>(feat_s7, w_attn, NS);
    k_softmax<<<1, 1024>>>(NS);
    k_gpool<<<nparts, 256>>>(feat_s7, NS);
    k_gate<<<1, 128>>>(nparts);
    k_sgemm112<<<(NS + 63) / 64, 256>>>(feat_s, W1 + CC * CC, g_FS1p, NS, 0, gamma);
    k_sgemm112<<<(NQ + 63) / 64, 256>>>(x7, W1, g_XWp, NQ, 1, gamma);
    k_final<<<(NQ + 31) / 32, 512>>>(coords_q, beta, b_cls, out, NQ, npairs);
}

// round 5
// speedup vs baseline: 1.6099x; 1.0486x over previous
#include <cuda_runtime.h>

#define CC    112
#define CLSN  20
#define NSMAX 8192
#define NQMAX 20000
#define PARTS 16

// ---------------- scratch (device globals; no allocation) ----------------
__device__ float  g_part[128 * CC];
__device__ float  g_esum[128];
__device__ float  g_Wf[CC * CLSN];
__device__ float4 g_pkA[NSMAX / 2 + 1];   // (x0,x1,y0,y1) per point pair
__device__ float4 g_pkB[NSMAX / 2 + 1];   // (z0,z1,w0,w1) per point pair
__device__ float  g_FS1[NSMAX * CC];
__device__ float  g_XW[NQMAX * CC];

// ---------------- K0: pair-packed SoA coords, Wf = W2@Wcls ------------------
__global__ void k_prep(const float* __restrict__ coords_s,
                       const float* __restrict__ W2,
                       const float* __restrict__ Wcls, int NS, int npairs)
{
    int idx = blockIdx.x * blockDim.x + threadIdx.x;
    if (idx < npairs) {
        int i0 = 2 * idx, i1 = 2 * idx + 1;
        float x0 = coords_s[i0 * 3 + 0];
        float y0 = coords_s[i0 * 3 + 1];
        float z0 = coords_s[i0 * 3 + 2];
        float w0 = x0 * x0 + y0 * y0 + z0 * z0;
        float x1 = 0.f, y1 = 0.f, z1 = 0.f, w1 = 1e30f;
        if (i1 < NS) {
            x1 = coords_s[i1 * 3 + 0];
            y1 = coords_s[i1 * 3 + 1];
            z1 = coords_s[i1 * 3 + 2];
            w1 = x1 * x1 + y1 * y1 + z1 * z1;
        }
        g_pkA[idx] = make_float4(x0, x1, y0, y1);
        g_pkB[idx] = make_float4(z0, z1, w0, w1);
    } else {
        int j = idx - npairs;
        if (j < CC * CLSN) {
            int c = j / CLSN, o = j % CLSN;
            float s = 0.f;
            #pragma unroll 8
            for (int k = 0; k < CC; k++)
                s = fmaf(W2[c * CC + k], Wcls[k * CLSN + o], s);
            g_Wf[j] = s;
        }
    }
}

// ---------------- K1: fused logits+exp+weighted pool (single pass) ---------
// partial[b][c] = sum_{i in block} exp(f_i.w) * f_i[c];  esum[b] = sum exp
__global__ void k_pool(const float* __restrict__ F,
                       const float* __restrict__ w, int NS)
{
    __shared__ float sacc[8][CC];
    __shared__ float sesum[8];
    int wp = threadIdx.x >> 5, lane = threadIdx.x & 31;
    float w0 = w[lane], w1 = w[lane + 32], w2 = w[lane + 64];
    float w3 = (lane < 16) ? w[lane + 96] : 0.f;
    float p0 = 0.f, p1 = 0.f, p2 = 0.f, p3 = 0.f, es = 0.f;
    int base = blockIdx.x * 64 + wp * 8;
    #pragma unroll
    for (int t = 0; t < 8; t++) {
        int i = base + t;
        if (i < NS) {
            const float* row = F + i * CC;
            float f0 = row[lane];
            float f1 = row[lane + 32];
            float f2 = row[lane + 64];
            float f3 = (lane < 16) ? row[lane + 96] : 0.f;
            float s = f0 * w0 + f1 * w1 + f2 * w2 + f3 * w3;
            #pragma unroll
            for (int o = 16; o; o >>= 1) s += __shfl_xor_sync(0xffffffffu, s, o);
            float e = __expf(s);
            es += e;
            p0 = fmaf(e, f0, p0);
            p1 = fmaf(e, f1, p1);
            p2 = fmaf(e, f2, p2);
            if (lane < 16) p3 = fmaf(e, f3, p3);
        }
    }
    sacc[wp][lane]      = p0;
    sacc[wp][lane + 32] = p1;
    sacc[wp][lane + 64] = p2;
    if (lane < 16) sacc[wp][lane + 96] = p3;
    if (lane == 0) sesum[wp] = es;
    __syncthreads();
    if (threadIdx.x < CC) {
        float s = 0.f;
        #pragma unroll
        for (int k = 0; k < 8; k++) s += sacc[k][threadIdx.x];
        g_part[blockIdx.x * CC + threadIdx.x] = s;
    } else if (threadIdx.x == CC) {
        float s = 0.f;
        #pragma unroll
        for (int k = 0; k < 8; k++) s += sesum[k];
        g_esum[blockIdx.x] = s;
    }
}

// ---------------- K2/K3: tiled SGEMM, N=K=112, vectorized staging ----------
// use_gate: compute gate[k] = sigmoid(pool_mean[k]) in prologue, scale B rows.
__global__ void k_sgemm112(const float* __restrict__ A,
                           const float* __restrict__ B,
                           float* __restrict__ Cm,
                           int M, int use_gate, int nparts,
                           const float* __restrict__ colscale)
{
    __shared__ float As[64][57];
    __shared__ float Bs[56][112];
    __shared__ float sgate[CC];
    __shared__ float sred[128];
    int tx = threadIdx.x;
    int m0 = blockIdx.x * 64;

    if (use_gate) {
        if (tx < 128) sred[tx] = (tx < nparts) ? g_esum[tx] : 0.f;
        __syncthreads();
        if (tx < 64) sred[tx] += sred[tx + 64];
        __syncthreads();
        if (tx < 32) {
            float v = sred[tx] + sred[tx + 32];
            #pragma unroll
            for (int o = 16; o; o >>= 1) v += __shfl_xor_sync(0xffffffffu, v, o);
            sred[tx] = v;
        }
        __syncthreads();
        float inv_es = 1.f / sred[0];
        if (tx < CC) {
            float s = 0.f;
            for (int b = 0; b < nparts; b++) s += g_part[b * CC + tx];
            sgate[tx] = 1.f / (1.f + __expf(-s * inv_es));
        }
        __syncthreads();
    }

    float acc[4][7];
    #pragma unroll
    for (int i = 0; i < 4; i++)
        #pragma unroll
        for (int j = 0; j < 7; j++) acc[i][j] = 0.f;
    int rg = (tx >> 4) << 2;
    int cg = (tx & 15) * 7;
    for (int k0 = 0; k0 < CC; k0 += 56) {
        // stage A: 64 rows x 14 float4
        for (int idx = tx; idx < 64 * 14; idx += 256) {
            int r = idx / 14, k4 = idx - r * 14;
            int gr = m0 + r;
            float4 v = (gr < M) ? *(const float4*)&A[gr * CC + k0 + k4 * 4]
                                : make_float4(0.f, 0.f, 0.f, 0.f);
            As[r][k4 * 4 + 0] = v.x;
            As[r][k4 * 4 + 1] = v.y;
            As[r][k4 * 4 + 2] = v.z;
            As[r][k4 * 4 + 3] = v.w;
        }
        // stage B: 56 rows x 28 float4
        for (int idx = tx; idx < 56 * 28; idx += 256) {
            int k = idx / 28, c4 = idx - k * 28;
            float4 v = *(const float4*)&B[(k0 + k) * CC + c4 * 4];
            if (use_gate) {
                float gsc = sgate[k0 + k];
                v.x *= gsc; v.y *= gsc; v.z *= gsc; v.w *= gsc;
            }
            *(float4*)&Bs[k][c4 * 4] = v;
        }
        __syncthreads();
        #pragma unroll 4
        for (int k = 0; k < 56; k++) {
            float a0 = As[rg][k], a1 = As[rg + 1][k], a2 = As[rg + 2][k], a3 = As[rg + 3][k];
            float b[7];
            #pragma unroll
            for (int j = 0; j < 7; j++) b[j] = Bs[k][cg + j];
            #pragma unroll
            for (int j = 0; j < 7; j++) {
                acc[0][j] = fmaf(a0, b[j], acc[0][j]);
                acc[1][j] = fmaf(a1, b[j], acc[1][j]);
                acc[2][j] = fmaf(a2, b[j], acc[2][j]);
                acc[3][j] = fmaf(a3, b[j], acc[3][j]);
            }
        }
        __syncthreads();
    }
    float cs[7];
    #pragma unroll
    for (int j = 0; j < 7; j++) cs[j] = colscale[cg + j];
    #pragma unroll
    for (int i = 0; i < 4; i++) {
        int gr = m0 + rg + i;
        if (gr < M) {
            #pragma unroll
            for (int j = 0; j < 7; j++)
                Cm[gr * CC + cg + j] = acc[i][j] * cs[j];
        }
    }
}

// ---------------- top-3 insert helper --------------------------------------
__device__ __forceinline__ void ins3(float v, int jj,
                                     float& b0, float& b1, float& b2,
                                     int& i0, int& i1, int& i2)
{
    if (v < b2) {
        if (v < b1) {
            b2 = b1; i2 = i1;
            if (v < b0) { b1 = b0; i1 = i0; b0 = v; i0 = jj; }
            else        { b1 = v;  i1 = jj; }
        } else { b2 = v; i2 = jj; }
    }
}

__device__ __forceinline__ unsigned long long fma_f32x2(unsigned long long a,
                                                        unsigned long long b,
                                                        unsigned long long c)
{
    unsigned long long d;
    asm("fma.rn.f32x2 %0, %1, %2, %3;" : "=l"(d) : "l"(a), "l"(b), "l"(c));
    return d;
}

// ---------------- K4: split-scan kNN (f32x2) + gather + ReLU + classifier --
__global__ void __launch_bounds__(512, 2)
k_final(const float* __restrict__ coords_q,
        const float* __restrict__ beta,
        const float* __restrict__ bcls,
        float* __restrict__ out,
        int NQ, int npairs)
{
    __shared__ float Wf[CC * CLSN];
    __shared__ float sbeta[CC];
    __shared__ float sb[CLSN];
    __shared__ float cv[PARTS][32][3];
    __shared__ int   ci[PARTS][32][3];
    int tx = threadIdx.x;
    int qlocal = tx & 31, part = tx >> 5;

    for (int i = tx; i < CC * CLSN; i += 512) Wf[i] = g_Wf[i];
    if (tx < CC)   sbeta[tx] = beta[tx];
    if (tx < CLSN) sb[tx] = bcls[tx];
    __syncthreads();

    int q = blockIdx.x * 32 + qlocal;
    bool valid = (q < NQ);
    float nx = 0.f, ny = 0.f, nz = 0.f;
    if (valid) {
        nx = -2.f * coords_q[q * 3 + 0];
        ny = -2.f * coords_q[q * 3 + 1];
        nz = -2.f * coords_q[q * 3 + 2];
    }
    unsigned xb = __float_as_uint(nx), yb = __float_as_uint(ny), zb = __float_as_uint(nz);
    unsigned long long nxx = (unsigned long long)xb | ((unsigned long long)xb << 32);
    unsigned long long nyy = (unsigned long long)yb | ((unsigned long long)yb << 32);
    unsigned long long nzz = (unsigned long long)zb | ((unsigned long long)zb << 32);

    int per = npairs / PARTS;
    int jb = part * per;
    int je = (part == PARTS - 1) ? npairs : jb + per;

    float b0 = 1e30f, b1 = 1e30f, b2 = 1e30f;
    int   i0 = 0, i1 = 0, i2 = 0;

    const ulonglong2* PA = (const ulonglong2*)g_pkA;
    const ulonglong2* PB = (const ulonglong2*)g_pkB;

    int j = jb;
    for (; j + 1 < je; j += 2) {
        ulonglong2 a0 = __ldg(&PA[j]);
        ulonglong2 c0 = __ldg(&PB[j]);
        ulonglong2 a1 = __ldg(&PA[j + 1]);
        ulonglong2 c1 = __ldg(&PB[j + 1]);
        unsigned long long v0 = fma_f32x2(a0.x, nxx, c0.y);
        unsigned long long v1 = fma_f32x2(a1.x, nxx, c1.y);
        v0 = fma_f32x2(a0.y, nyy, v0);
        v1 = fma_f32x2(a1.y, nyy, v1);
        v0 = fma_f32x2(c0.x, nzz, v0);
        v1 = fma_f32x2(c1.x, nzz, v1);
        float v0l = __uint_as_float((unsigned)v0);
        float v0h = __uint_as_float((unsigned)(v0 >> 32));
        float v1l = __uint_as_float((unsigned)v1);
        float v1h = __uint_as_float((unsigned)(v1 >> 32));
        float m = fminf(fminf(v0l, v0h), fminf(v1l, v1h));
        if (m < b2) {
            ins3(v0l, 2 * j,     b0, b1, b2, i0, i1, i2);
            ins3(v0h, 2 * j + 1, b0, b1, b2, i0, i1, i2);
            ins3(v1l, 2 * j + 2, b0, b1, b2, i0, i1, i2);
            ins3(v1h, 2 * j + 3, b0, b1, b2, i0, i1, i2);
        }
    }
    for (; j < je; j++) {
        ulonglong2 a0 = __ldg(&PA[j]);
        ulonglong2 c0 = __ldg(&PB[j]);
        unsigned long long v0 = fma_f32x2(a0.x, nxx, c0.y);
        v0 = fma_f32x2(a0.y, nyy, v0);
        v0 = fma_f32x2(c0.x, nzz, v0);
        float v0l = __uint_as_float((unsigned)v0);
        float v0h = __uint_as_float((unsigned)(v0 >> 32));
        if (fminf(v0l, v0h) < b2) {
            ins3(v0l, 2 * j,     b0, b1, b2, i0, i1, i2);
            ins3(v0h, 2 * j + 1, b0, b1, b2, i0, i1, i2);
        }
    }

    cv[part][qlocal][0] = b0; ci[part][qlocal][0] = i0;
    cv[part][qlocal][1] = b1; ci[part][qlocal][1] = i1;
    cv[part][qlocal][2] = b2; ci[part][qlocal][2] = i2;
    __syncthreads();

    if (part != 0 || !valid) return;

    b0 = cv[0][qlocal][0]; i0 = ci[0][qlocal][0];
    b1 = cv[0][qlocal][1]; i1 = ci[0][qlocal][1];
    b2 = cv[0][qlocal][2]; i2 = ci[0][qlocal][2];
    #pragma unroll
    for (int p = 1; p < PARTS; p++) {
        #pragma unroll
        for (int k = 0; k < 3; k++)
            ins3(cv[p][qlocal][k], ci[p][qlocal][k], b0, b1, b2, i0, i1, i2);
    }

    float e1 = __expf(b0 - b1);
    float e2 = __expf(b0 - b2);
    float inv = 1.f / (1.f + e1 + e2);
    float w0 = inv, w1 = e1 * inv, w2 = e2 * inv;

    const float4* xw = (const float4*)(g_XW + (size_t)q * CC);
    const float4* f0 = (const float4*)(g_FS1 + (size_t)i0 * CC);
    const float4* f1 = (const float4*)(g_FS1 + (size_t)i1 * CC);
    const float4* f2 = (const float4*)(g_FS1 + (size_t)i2 * CC);

    float acc[CLSN];
    #pragma unroll
    for (int o = 0; o < CLSN; o++) acc[o] = sb[o];

    for (int c4 = 0; c4 < CC / 4; c4++) {
        float4 x  = xw[c4];
        float4 a0 = f0[c4];
        float4 a1 = f1[c4];
        float4 a2 = f2[c4];
        int cb = c4 * 4;
        float h[4];
        h[0] = x.x + w0 * a0.x + w1 * a1.x + w2 * a2.x + sbeta[cb + 0];
        h[1] = x.y + w0 * a0.y + w1 * a1.y + w2 * a2.y + sbeta[cb + 1];
        h[2] = x.z + w0 * a0.z + w1 * a1.z + w2 * a2.z + sbeta[cb + 2];
        h[3] = x.w + w0 * a0.w + w1 * a1.w + w2 * a2.w + sbeta[cb + 3];
        #pragma unroll
        for (int u = 0; u < 4; u++) {
            float hv = fmaxf(h[u], 0.f);
            const float* wrow = &Wf[(cb + u) * CLSN];
            #pragma unroll
            for (int o = 0; o < CLSN; o++) acc[o] = fmaf(hv, wrow[o], acc[o]);
        }
    }

    float* op = out + (size_t)q * CLSN;
    #pragma unroll
    for (int o = 0; o < CLSN; o++) op[o] = acc[o];
}

// ---------------- launch ---------------------------------------------------
extern "C" void kernel_launch(void* const* d_in, const int* in_sizes, int n_in,
                              void* d_out, int out_size)
{
    const float* coords_q = (const float*)d_in[0];
    const float* coords_s = (const float*)d_in[1];
    const float* x7       = (const float*)d_in[2];
    const float* feat_s7  = (const float*)d_in[3];
    const float* feat_s   = (const float*)d_in[4];
    const float* w_attn   = (const float*)d_in[5];
    const float* W1       = (const float*)d_in[6];
    const float* gamma    = (const float*)d_in[7];
    const float* beta     = (const float*)d_in[8];
    const float* W2       = (const float*)d_in[9];
    const float* W_cls    = (const float*)d_in[10];
    const float* b_cls    = (const float*)d_in[11];
    float* out = (float*)d_out;

    int NQ = in_sizes[0] / 3;
    int NS = in_sizes[1] / 3;
    int npairs = (NS + 1) / 2;
    int nparts = (NS + 63) / 64;

    float* g_FS1p; cudaGetSymbolAddress((void**)&g_FS1p, g_FS1);
    float* g_XWp;  cudaGetSymbolAddress((void**)&g_XWp,  g_XW);

    k_prep<<<(npairs + CC * CLSN + 255) / 256, 256>>>(coords_s, W2, W_cls, NS, npairs);
    k_pool<<<nparts, 256>>>(feat_s7, w_attn, NS);
    // FS1 = (feat_s @ W1_bot) * gamma (cols) — independent of pool chain
    k_sgemm112<<<(NS + 63) / 64, 256>>>(feat_s, W1 + CC * CC, g_FS1p, NS, 0, nparts, gamma);
    // XW  = (x7 @ diag(gate) W1_top) * gamma (cols) — gate computed in prologue
    k_sgemm112<<<(NQ + 63) / 64, 256>>>(x7, W1, g_XWp, NQ, 1, nparts, gamma);
    k_final<<<(NQ + 31) / 32, 512>>>(coords_q, beta, b_cls, out, NQ, npairs);
}

// round 6
// speedup vs baseline: 1.6851x; 1.0468x over previous
#include <cuda_runtime.h>

#define CC    112
#define CLSN  20
#define NSMAX 8192
#define NQMAX 20000
#define PARTS 16

// ---------------- scratch (device globals; no allocation) ----------------
__device__ float  g_part[128 * CC];
__device__ float  g_esum[128];
__device__ float  g_Wf[CC * CLSN];
__device__ float4 g_pkA[NSMAX / 2 + 1];   // (x0,x1,y0,y1) per point pair
__device__ float4 g_pkB[NSMAX / 2 + 1];   // (z0,z1,w0,w1) per point pair
__device__ float  g_FS1[NSMAX * CC];
__device__ float  g_XW[NQMAX * CC];

// ---------------- K1: merged prep (coords pack + Wf) and pooling -----------
// blocks [0, nparts): fused logits+exp+weighted pool over feat_s7
// blocks [nparts, ...): pair-packed SoA coords + Wf = W2@Wcls
__global__ void k_prep_pool(const float* __restrict__ F,
                            const float* __restrict__ w,
                            const float* __restrict__ coords_s,
                            const float* __restrict__ W2,
                            const float* __restrict__ Wcls,
                            int NS, int npairs, int nparts)
{
    int tx = threadIdx.x;
    if (blockIdx.x < nparts) {
        __shared__ float sacc[8][CC];
        __shared__ float sesum[8];
        int wp = tx >> 5, lane = tx & 31;
        float w0 = w[lane], w1 = w[lane + 32], w2 = w[lane + 64];
        float w3 = (lane < 16) ? w[lane + 96] : 0.f;
        float p0 = 0.f, p1 = 0.f, p2 = 0.f, p3 = 0.f, es = 0.f;
        int base = blockIdx.x * 64 + wp * 8;
        #pragma unroll
        for (int t = 0; t < 8; t++) {
            int i = base + t;
            if (i < NS) {
                const float* row = F + i * CC;
                float f0 = row[lane];
                float f1 = row[lane + 32];
                float f2 = row[lane + 64];
                float f3 = (lane < 16) ? row[lane + 96] : 0.f;
                float s = f0 * w0 + f1 * w1 + f2 * w2 + f3 * w3;
                #pragma unroll
                for (int o = 16; o; o >>= 1) s += __shfl_xor_sync(0xffffffffu, s, o);
                float e = __expf(s);
                es += e;
                p0 = fmaf(e, f0, p0);
                p1 = fmaf(e, f1, p1);
                p2 = fmaf(e, f2, p2);
                if (lane < 16) p3 = fmaf(e, f3, p3);
            }
        }
        sacc[wp][lane]      = p0;
        sacc[wp][lane + 32] = p1;
        sacc[wp][lane + 64] = p2;
        if (lane < 16) sacc[wp][lane + 96] = p3;
        if (lane == 0) sesum[wp] = es;
        __syncthreads();
        if (tx < CC) {
            float s = 0.f;
            #pragma unroll
            for (int k = 0; k < 8; k++) s += sacc[k][tx];
            g_part[blockIdx.x * CC + tx] = s;
        } else if (tx == CC) {
            float s = 0.f;
            #pragma unroll
            for (int k = 0; k < 8; k++) s += sesum[k];
            g_esum[blockIdx.x] = s;
        }
    } else {
        int idx = (blockIdx.x - nparts) * 256 + tx;
        if (idx < npairs) {
            int i0 = 2 * idx, i1 = 2 * idx + 1;
            float x0 = coords_s[i0 * 3 + 0];
            float y0 = coords_s[i0 * 3 + 1];
            float z0 = coords_s[i0 * 3 + 2];
            float w0 = x0 * x0 + y0 * y0 + z0 * z0;
            float x1 = 0.f, y1 = 0.f, z1 = 0.f, w1 = 1e30f;
            if (i1 < NS) {
                x1 = coords_s[i1 * 3 + 0];
                y1 = coords_s[i1 * 3 + 1];
                z1 = coords_s[i1 * 3 + 2];
                w1 = x1 * x1 + y1 * y1 + z1 * z1;
            }
            g_pkA[idx] = make_float4(x0, x1, y0, y1);
            g_pkB[idx] = make_float4(z0, z1, w0, w1);
        } else {
            int j = idx - npairs;
            if (j < CC * CLSN) {
                int c = j / CLSN, o = j % CLSN;
                float s = 0.f;
                #pragma unroll 8
                for (int k = 0; k < CC; k++)
                    s = fmaf(W2[c * CC + k], Wcls[k * CLSN + o], s);
                g_Wf[j] = s;
            }
        }
    }
}

// ---------------- K2: combined SGEMM (FS1 + XW), 128x112 tile, 8x7/thread --
// A-tile stored k-major so A operands are 2x LDS.128 per k.
__global__ void __launch_bounds__(256)
k_gemm(const float* __restrict__ Afs,   // feat_s  [NS, 112]
       const float* __restrict__ Axw,   // x7      [NQ, 112]
       const float* __restrict__ W1,    // [224, 112]
       int tilesFS1, int MFS1, int MXW, int nparts,
       const float* __restrict__ colscale)
{
    __shared__ float As[28][136];        // k-major, padded
    __shared__ float Bs[28][112];
    __shared__ float sgate[CC];
    __shared__ float sred[128];
    int tx = threadIdx.x;

    bool isXW = (blockIdx.x >= tilesFS1);
    const float* A = isXW ? Axw : Afs;
    const float* B = isXW ? W1 : (W1 + CC * CC);
    float* Cm;
    { float* p0; float* p1;
      asm("cvta.global.u64 %0, %1;" : "=l"(p0) : "l"((unsigned long long)0)); (void)p0; (void)p1; }
    int M = isXW ? MXW : MFS1;
    int m0 = (isXW ? (blockIdx.x - tilesFS1) : blockIdx.x) * 128;

    if (isXW) {
        // gate[k] = sigmoid( (sum_b part[b][k]) / (sum_b esum[b]) )
        if (tx < 128) sred[tx] = (tx < nparts) ? g_esum[tx] : 0.f;
        __syncthreads();
        if (tx < 64) sred[tx] += sred[tx + 64];
        __syncthreads();
        if (tx < 32) {
            float v = sred[tx] + sred[tx + 32];
            #pragma unroll
            for (int o = 16; o; o >>= 1) v += __shfl_xor_sync(0xffffffffu, v, o);
            sred[tx] = v;
        }
        __syncthreads();
        float inv_es = 1.f / sred[0];
        if (tx < CC) {
            float s = 0.f;
            for (int b = 0; b < nparts; b++) s += g_part[b * CC + tx];
            sgate[tx] = 1.f / (1.f + __expf(-s * inv_es));
        }
        __syncthreads();
    }

    float acc[8][7];
    #pragma unroll
    for (int i = 0; i < 8; i++)
        #pragma unroll
        for (int j = 0; j < 7; j++) acc[i][j] = 0.f;
    int rg = (tx >> 4) * 8;      // 0..120 step 8
    int cg = (tx & 15) * 7;      // 0..105 step 7

    for (int k0 = 0; k0 < CC; k0 += 28) {
        // stage A (transposed): 128 rows x 7 float4
        for (int idx = tx; idx < 128 * 7; idx += 256) {
            int r = idx / 7, k4 = idx - r * 7;
            int gr = m0 + r;
            float4 v = (gr < M) ? *(const float4*)&A[gr * CC + k0 + k4 * 4]
                                : make_float4(0.f, 0.f, 0.f, 0.f);
            As[k4 * 4 + 0][r] = v.x;
            As[k4 * 4 + 1][r] = v.y;
            As[k4 * 4 + 2][r] = v.z;
            As[k4 * 4 + 3][r] = v.w;
        }
        // stage B: 28 k-rows x 28 float4
        for (int idx = tx; idx < 28 * 28; idx += 256) {
            int k = idx / 28, c4 = idx - k * 28;
            float4 v = *(const float4*)&B[(k0 + k) * CC + c4 * 4];
            if (isXW) {
                float gsc = sgate[k0 + k];
                v.x *= gsc; v.y *= gsc; v.z *= gsc; v.w *= gsc;
            }
            *(float4*)&Bs[k][c4 * 4] = v;
        }
        __syncthreads();
        #pragma unroll 4
        for (int k = 0; k < 28; k++) {
            float4 alo = *(const float4*)&As[k][rg];
            float4 ahi = *(const float4*)&As[k][rg + 4];
            float a[8] = {alo.x, alo.y, alo.z, alo.w, ahi.x, ahi.y, ahi.z, ahi.w};
            float b[7];
            #pragma unroll
            for (int j = 0; j < 7; j++) b[j] = Bs[k][cg + j];
            #pragma unroll
            for (int i = 0; i < 8; i++)
                #pragma unroll
                for (int j = 0; j < 7; j++)
                    acc[i][j] = fmaf(a[i], b[j], acc[i][j]);
        }
        __syncthreads();
    }

    float* Cout = isXW ? g_XW : g_FS1;
    float cs[7];
    #pragma unroll
    for (int j = 0; j < 7; j++) cs[j] = colscale[cg + j];
    #pragma unroll
    for (int i = 0; i < 8; i++) {
        int gr = m0 + rg + i;
        if (gr < M) {
            #pragma unroll
            for (int j = 0; j < 7; j++)
                Cout[(size_t)gr * CC + cg + j] = acc[i][j] * cs[j];
        }
    }
}

// ---------------- top-3 insert helper --------------------------------------
__device__ __forceinline__ void ins3(float v, int jj,
                                     float& b0, float& b1, float& b2,
                                     int& i0, int& i1, int& i2)
{
    if (v < b2) {
        if (v < b1) {
            b2 = b1; i2 = i1;
            if (v < b0) { b1 = b0; i1 = i0; b0 = v; i0 = jj; }
            else        { b1 = v;  i1 = jj; }
        } else { b2 = v; i2 = jj; }
    }
}

__device__ __forceinline__ unsigned long long fma_f32x2(unsigned long long a,
                                                        unsigned long long b,
                                                        unsigned long long c)
{
    unsigned long long d;
    asm("fma.rn.f32x2 %0, %1, %2, %3;" : "=l"(d) : "l"(a), "l"(b), "l"(c));
    return d;
}

// ---------------- K3: split-scan kNN (f32x2) + gather + ReLU + classifier --
__global__ void __launch_bounds__(512, 2)
k_final(const float* __restrict__ coords_q,
        const float* __restrict__ beta,
        const float* __restrict__ bcls,
        float* __restrict__ out,
        int NQ, int npairs)
{
    __shared__ float Wf[CC * CLSN];
    __shared__ float sbeta[CC];
    __shared__ float sb[CLSN];
    __shared__ float cv[PARTS][32][3];
    __shared__ int   ci[PARTS][32][3];
    int tx = threadIdx.x;
    int qlocal = tx & 31, part = tx >> 5;

    for (int i = tx; i < CC * CLSN; i += 512) Wf[i] = g_Wf[i];
    if (tx < CC)   sbeta[tx] = beta[tx];
    if (tx < CLSN) sb[tx] = bcls[tx];
    __syncthreads();

    int q = blockIdx.x * 32 + qlocal;
    bool valid = (q < NQ);
    float nx = 0.f, ny = 0.f, nz = 0.f;
    if (valid) {
        nx = -2.f * coords_q[q * 3 + 0];
        ny = -2.f * coords_q[q * 3 + 1];
        nz = -2.f * coords_q[q * 3 + 2];
    }
    unsigned xb = __float_as_uint(nx), yb = __float_as_uint(ny), zb = __float_as_uint(nz);
    unsigned long long nxx = (unsigned long long)xb | ((unsigned long long)xb << 32);
    unsigned long long nyy = (unsigned long long)yb | ((unsigned long long)yb << 32);
    unsigned long long nzz = (unsigned long long)zb | ((unsigned long long)zb << 32);

    int per = npairs / PARTS;
    int jb = part * per;
    int je = (part == PARTS - 1) ? npairs : jb + per;

    float b0 = 1e30f, b1 = 1e30f, b2 = 1e30f;
    int   i0 = 0, i1 = 0, i2 = 0;

    const ulonglong2* PA = (const ulonglong2*)g_pkA;
    const ulonglong2* PB = (const ulonglong2*)g_pkB;

    int j = jb;
    for (; j + 1 < je; j += 2) {
        ulonglong2 a0 = __ldg(&PA[j]);
        ulonglong2 c0 = __ldg(&PB[j]);
        ulonglong2 a1 = __ldg(&PA[j + 1]);
        ulonglong2 c1 = __ldg(&PB[j + 1]);
        unsigned long long v0 = fma_f32x2(a0.x, nxx, c0.y);
        unsigned long long v1 = fma_f32x2(a1.x, nxx, c1.y);
        v0 = fma_f32x2(a0.y, nyy, v0);
        v1 = fma_f32x2(a1.y, nyy, v1);
        v0 = fma_f32x2(c0.x, nzz, v0);
        v1 = fma_f32x2(c1.x, nzz, v1);
        float v0l = __uint_as_float((unsigned)v0);
        float v0h = __uint_as_float((unsigned)(v0 >> 32));
        float v1l = __uint_as_float((unsigned)v1);
        float v1h = __uint_as_float((unsigned)(v1 >> 32));
        float m = fminf(fminf(v0l, v0h), fminf(v1l, v1h));
        if (m < b2) {
            ins3(v0l, 2 * j,     b0, b1, b2, i0, i1, i2);
            ins3(v0h, 2 * j + 1, b0, b1, b2, i0, i1, i2);
            ins3(v1l, 2 * j + 2, b0, b1, b2, i0, i1, i2);
            ins3(v1h, 2 * j + 3, b0, b1, b2, i0, i1, i2);
        }
    }
    for (; j < je; j++) {
        ulonglong2 a0 = __ldg(&PA[j]);
        ulonglong2 c0 = __ldg(&PB[j]);
        unsigned long long v0 = fma_f32x2(a0.x, nxx, c0.y);
        v0 = fma_f32x2(a0.y, nyy, v0);
        v0 = fma_f32x2(c0.x, nzz, v0);
        float v0l = __uint_as_float((unsigned)v0);
        float v0h = __uint_as_float((unsigned)(v0 >> 32));
        if (fminf(v0l, v0h) < b2) {
            ins3(v0l, 2 * j,     b0, b1, b2, i0, i1, i2);
            ins3(v0h, 2 * j + 1, b0, b1, b2, i0, i1, i2);
        }
    }

    cv[part][qlocal][0] = b0; ci[part][qlocal][0] = i0;
    cv[part][qlocal][1] = b1; ci[part][qlocal][1] = i1;
    cv[part][qlocal][2] = b2; ci[part][qlocal][2] = i2;
    __syncthreads();

    if (part != 0 || !valid) return;

    b0 = cv[0][qlocal][0]; i0 = ci[0][qlocal][0];
    b1 = cv[0][qlocal][1]; i1 = ci[0][qlocal][1];
    b2 = cv[0][qlocal][2]; i2 = ci[0][qlocal][2];
    #pragma unroll
    for (int p = 1; p < PARTS; p++) {
        #pragma unroll
        for (int k = 0; k < 3; k++)
            ins3(cv[p][qlocal][k], ci[p][qlocal][k], b0, b1, b2, i0, i1, i2);
    }

    float e1 = __expf(b0 - b1);
    float e2 = __expf(b0 - b2);
    float inv = 1.f / (1.f + e1 + e2);
    float w0 = inv, w1 = e1 * inv, w2 = e2 * inv;

    const float4* xw = (const float4*)(g_XW + (size_t)q * CC);
    const float4* f0 = (const float4*)(g_FS1 + (size_t)i0 * CC);
    const float4* f1 = (const float4*)(g_FS1 + (size_t)i1 * CC);
    const float4* f2 = (const float4*)(g_FS1 + (size_t)i2 * CC);

    float acc[CLSN];
    #pragma unroll
    for (int o = 0; o < CLSN; o++) acc[o] = sb[o];

    for (int c4 = 0; c4 < CC / 4; c4++) {
        float4 x  = xw[c4];
        float4 a0 = f0[c4];
        float4 a1 = f1[c4];
        float4 a2 = f2[c4];
        int cb = c4 * 4;
        float h[4];
        h[0] = x.x + w0 * a0.x + w1 * a1.x + w2 * a2.x + sbeta[cb + 0];
        h[1] = x.y + w0 * a0.y + w1 * a1.y + w2 * a2.y + sbeta[cb + 1];
        h[2] = x.z + w0 * a0.z + w1 * a1.z + w2 * a2.z + sbeta[cb + 2];
        h[3] = x.w + w0 * a0.w + w1 * a1.w + w2 * a2.w + sbeta[cb + 3];
        #pragma unroll
        for (int u = 0; u < 4; u++) {
            float hv = fmaxf(h[u], 0.f);
            const float* wrow = &Wf[(cb + u) * CLSN];
            #pragma unroll
            for (int o = 0; o < CLSN; o++) acc[o] = fmaf(hv, wrow[o], acc[o]);
        }
    }

    float* op = out + (size_t)q * CLSN;
    #pragma unroll
    for (int o = 0; o < CLSN; o++) op[o] = acc[o];
}

// ---------------- launch ---------------------------------------------------
extern "C" void kernel_launch(void* const* d_in, const int* in_sizes, int n_in,
                              void* d_out, int out_size)
{
    const float* coords_q = (const float*)d_in[0];
    const float* coords_s = (const float*)d_in[1];
    const float* x7       = (const float*)d_in[2];
    const float* feat_s7  = (const float*)d_in[3];
    const float* feat_s   = (const float*)d_in[4];
    const float* w_attn   = (const float*)d_in[5];
    const float* W1       = (const float*)d_in[6];
    const float* gamma    = (const float*)d_in[7];
    const float* beta     = (const float*)d_in[8];
    const float* W2       = (const float*)d_in[9];
    const float* W_cls    = (const float*)d_in[10];
    const float* b_cls    = (const float*)d_in[11];
    float* out = (float*)d_out;

    int NQ = in_sizes[0] / 3;
    int NS = in_sizes[1] / 3;
    int npairs = (NS + 1) / 2;
    int nparts = (NS + 63) / 64;
    int prepBlocks = (npairs + CC * CLSN + 255) / 256;
    int tilesFS1 = (NS + 127) / 128;
    int tilesXW  = (NQ + 127) / 128;

    k_prep_pool<<<nparts + prepBlocks, 256>>>(feat_s7, w_attn, coords_s,
                                              W2, W_cls, NS, npairs, nparts);
    k_gemm<<<tilesFS1 + tilesXW, 256>>>(feat_s, x7, W1,
                                        tilesFS1, NS, NQ, nparts, gamma);
    k_final<<<(NQ + 31) / 32, 512>>>(coords_q, beta, b_cls, out, NQ, npairs);
}

// round 7
// speedup vs baseline: 1.8711x; 1.1103x over previous
#include <cuda_runtime.h>

#define CC    112
#define CLSN  20
#define NSMAX 8192
#define NQMAX 20000
#define PARTS 16
#define NPOOL 256
#define IDXMASK 0x1FFFu
#define KEYMASK 0xFFFFE000u

// ---------------- scratch (device globals; no allocation) ----------------
__device__ float  g_part[NPOOL * CC];
__device__ float  g_esum[NPOOL];
__device__ float  g_Wf[CC * CLSN];
__device__ float4 g_pkA[NSMAX / 2 + 1];   // (x0,x1,y0,y1) per point pair
__device__ float4 g_pkB[NSMAX / 2 + 1];   // (z0,z1,w0,w1) per point pair
__device__ float  g_FS1[NSMAX * CC];
__device__ float  g_XW[NQMAX * CC];

// ---------------- K1: merged prep (coords pack + Wf) and pooling -----------
__global__ void k_prep_pool(const float* __restrict__ F,
                            const float* __restrict__ w,
                            const float* __restrict__ coords_s,
                            const float* __restrict__ W2,
                            const float* __restrict__ Wcls,
                            int NS, int npairs, int nparts)
{
    int tx = threadIdx.x;
    if (blockIdx.x < nparts) {
        __shared__ float sacc[8][CC];
        __shared__ float sesum[8];
        int wp = tx >> 5, lane = tx & 31;
        float w0 = w[lane], w1 = w[lane + 32], w2 = w[lane + 64];
        float w3 = (lane < 16) ? w[lane + 96] : 0.f;
        float p0 = 0.f, p1 = 0.f, p2 = 0.f, p3 = 0.f, es = 0.f;
        int base = blockIdx.x * 32 + wp * 4;
        #pragma unroll
        for (int t = 0; t < 4; t++) {
            int i = base + t;
            if (i < NS) {
                const float* row = F + i * CC;
                float f0 = row[lane];
                float f1 = row[lane + 32];
                float f2 = row[lane + 64];
                float f3 = (lane < 16) ? row[lane + 96] : 0.f;
                float s = f0 * w0 + f1 * w1 + f2 * w2 + f3 * w3;
                #pragma unroll
                for (int o = 16; o; o >>= 1) s += __shfl_xor_sync(0xffffffffu, s, o);
                float e = __expf(s);
                es += e;
                p0 = fmaf(e, f0, p0);
                p1 = fmaf(e, f1, p1);
                p2 = fmaf(e, f2, p2);
                if (lane < 16) p3 = fmaf(e, f3, p3);
            }
        }
        sacc[wp][lane]      = p0;
        sacc[wp][lane + 32] = p1;
        sacc[wp][lane + 64] = p2;
        if (lane < 16) sacc[wp][lane + 96] = p3;
        if (lane == 0) sesum[wp] = es;
        __syncthreads();
        if (tx < CC) {
            float s = 0.f;
            #pragma unroll
            for (int k = 0; k < 8; k++) s += sacc[k][tx];
            g_part[blockIdx.x * CC + tx] = s;
        } else if (tx == CC) {
            float s = 0.f;
            #pragma unroll
            for (int k = 0; k < 8; k++) s += sesum[k];
            g_esum[blockIdx.x] = s;
        }
    } else {
        int idx = (blockIdx.x - nparts) * 256 + tx;
        if (idx < npairs) {
            int i0 = 2 * idx, i1 = 2 * idx + 1;
            float x0 = coords_s[i0 * 3 + 0];
            float y0 = coords_s[i0 * 3 + 1];
            float z0 = coords_s[i0 * 3 + 2];
            float w0 = x0 * x0 + y0 * y0 + z0 * z0;
            float x1 = 0.f, y1 = 0.f, z1 = 0.f, w1 = 1e30f;
            if (i1 < NS) {
                x1 = coords_s[i1 * 3 + 0];
                y1 = coords_s[i1 * 3 + 1];
                z1 = coords_s[i1 * 3 + 2];
                w1 = x1 * x1 + y1 * y1 + z1 * z1;
            }
            g_pkA[idx] = make_float4(x0, x1, y0, y1);
            g_pkB[idx] = make_float4(z0, z1, w0, w1);
        } else {
            int j = idx - npairs;
            if (j < CC * CLSN) {
                int c = j / CLSN, o = j % CLSN;
                float s = 0.f;
                #pragma unroll 8
                for (int k = 0; k < CC; k++)
                    s = fmaf(W2[c * CC + k], Wcls[k * CLSN + o], s);
                g_Wf[j] = s;
            }
        }
    }
}

// ---------------- K2: combined SGEMM (FS1 + XW), 128x112 tile, 8x7/thread --
__global__ void __launch_bounds__(256)
k_gemm(const float* __restrict__ Afs,
       const float* __restrict__ Axw,
       const float* __restrict__ W1,
       int tilesFS1, int MFS1, int MXW, int nparts,
       const float* __restrict__ colscale)
{
    __shared__ float As[28][136];
    __shared__ float Bs[28][112];
    __shared__ float sgate[CC];
    __shared__ float sred[256];
    int tx = threadIdx.x;

    bool isXW = (blockIdx.x >= tilesFS1);
    const float* A = isXW ? Axw : Afs;
    const float* B = isXW ? W1 : (W1 + CC * CC);
    int M = isXW ? MXW : MFS1;
    int m0 = (isXW ? (blockIdx.x - tilesFS1) : blockIdx.x) * 128;

    if (isXW) {
        sred[tx] = (tx < nparts) ? g_esum[tx] : 0.f;
        __syncthreads();
        if (tx < 128) sred[tx] += sred[tx + 128];
        __syncthreads();
        if (tx < 64) sred[tx] += sred[tx + 64];
        __syncthreads();
        if (tx < 32) {
            float v = sred[tx] + sred[tx + 32];
            #pragma unroll
            for (int o = 16; o; o >>= 1) v += __shfl_xor_sync(0xffffffffu, v, o);
            sred[tx] = v;
        }
        __syncthreads();
        float inv_es = 1.f / sred[0];
        if (tx < CC) {
            float s = 0.f;
            #pragma unroll 8
            for (int b = 0; b < nparts; b++) s += g_part[b * CC + tx];
            sgate[tx] = 1.f / (1.f + __expf(-s * inv_es));
        }
        __syncthreads();
    }

    float acc[8][7];
    #pragma unroll
    for (int i = 0; i < 8; i++)
        #pragma unroll
        for (int j = 0; j < 7; j++) acc[i][j] = 0.f;
    int rg = (tx >> 4) * 8;
    int cg = (tx & 15) * 7;

    for (int k0 = 0; k0 < CC; k0 += 28) {
        for (int idx = tx; idx < 128 * 7; idx += 256) {
            int r = idx / 7, k4 = idx - r * 7;
            int gr = m0 + r;
            float4 v = (gr < M) ? *(const float4*)&A[gr * CC + k0 + k4 * 4]
                                : make_float4(0.f, 0.f, 0.f, 0.f);
            As[k4 * 4 + 0][r] = v.x;
            As[k4 * 4 + 1][r] = v.y;
            As[k4 * 4 + 2][r] = v.z;
            As[k4 * 4 + 3][r] = v.w;
        }
        for (int idx = tx; idx < 28 * 28; idx += 256) {
            int k = idx / 28, c4 = idx - k * 28;
            float4 v = *(const float4*)&B[(k0 + k) * CC + c4 * 4];
            if (isXW) {
                float gsc = sgate[k0 + k];
                v.x *= gsc; v.y *= gsc; v.z *= gsc; v.w *= gsc;
            }
            *(float4*)&Bs[k][c4 * 4] = v;
        }
        __syncthreads();
        #pragma unroll 4
        for (int k = 0; k < 28; k++) {
            float4 alo = *(const float4*)&As[k][rg];
            float4 ahi = *(const float4*)&As[k][rg + 4];
            float a[8] = {alo.x, alo.y, alo.z, alo.w, ahi.x, ahi.y, ahi.z, ahi.w};
            float b[7];
            #pragma unroll
            for (int j = 0; j < 7; j++) b[j] = Bs[k][cg + j];
            #pragma unroll
            for (int i = 0; i < 8; i++)
                #pragma unroll
                for (int j = 0; j < 7; j++)
                    acc[i][j] = fmaf(a[i], b[j], acc[i][j]);
        }
        __syncthreads();
    }

    float* Cout = isXW ? g_XW : g_FS1;
    float cs[7];
    #pragma unroll
    for (int j = 0; j < 7; j++) cs[j] = colscale[cg + j];
    #pragma unroll
    for (int i = 0; i < 8; i++) {
        int gr = m0 + rg + i;
        if (gr < M) {
            #pragma unroll
            for (int j = 0; j < 7; j++)
                Cout[(size_t)gr * CC + cg + j] = acc[i][j] * cs[j];
        }
    }
}

// ---------------- branchless packed top-3 ----------------------------------
__device__ __forceinline__ float packkey(float v, unsigned jj)
{
    return __uint_as_float((__float_as_uint(v) & KEYMASK) | jj);
}
__device__ __forceinline__ void ins3b(float v, float& b0, float& b1, float& b2)
{
    float h0 = fmaxf(v, b0);  b0 = fminf(v, b0);
    float h1 = fmaxf(h0, b1); b1 = fminf(h0, b1);
    b2 = fminf(h1, b2);
}

__device__ __forceinline__ unsigned long long fma_f32x2(unsigned long long a,
                                                        unsigned long long b,
                                                        unsigned long long c)
{
    unsigned long long d;
    asm("fma.rn.f32x2 %0, %1, %2, %3;" : "=l"(d) : "l"(a), "l"(b), "l"(c));
    return d;
}
__device__ __forceinline__ unsigned long long add_f32x2(unsigned long long a,
                                                        unsigned long long b)
{
    unsigned long long d;
    asm("add.rn.f32x2 %0, %1, %2;" : "=l"(d) : "l"(a), "l"(b));
    return d;
}

// ---------------- K3: split-scan kNN (branchless) + gather + classifier ----
__global__ void __launch_bounds__(512, 2)
k_final(const float* __restrict__ coords_q,
        const float* __restrict__ beta,
        const float* __restrict__ bcls,
        float* __restrict__ out,
        int NQ, int npairs)
{
    __shared__ float Wf[CC * CLSN];
    __shared__ float sbeta[CC];
    __shared__ float sb[CLSN];
    __shared__ float cv[PARTS][32][3];
    int tx = threadIdx.x;
    int qlocal = tx & 31, part = tx >> 5;

    for (int i = tx; i < CC * CLSN; i += 512) Wf[i] = g_Wf[i];
    if (tx < CC)   sbeta[tx] = beta[tx];
    if (tx < CLSN) sb[tx] = bcls[tx];
    __syncthreads();

    int q = blockIdx.x * 32 + qlocal;
    bool valid = (q < NQ);
    float nx = 0.f, ny = 0.f, nz = 0.f, q2 = 0.f;
    if (valid) {
        float qx = coords_q[q * 3 + 0];
        float qy = coords_q[q * 3 + 1];
        float qz = coords_q[q * 3 + 2];
        nx = -2.f * qx; ny = -2.f * qy; nz = -2.f * qz;
        q2 = qx * qx + qy * qy + qz * qz;
    }
    unsigned xb = __float_as_uint(nx), yb = __float_as_uint(ny), zb = __float_as_uint(nz);
    unsigned qb = __float_as_uint(q2);
    unsigned long long nxx = (unsigned long long)xb | ((unsigned long long)xb << 32);
    unsigned long long nyy = (unsigned long long)yb | ((unsigned long long)yb << 32);
    unsigned long long nzz = (unsigned long long)zb | ((unsigned long long)zb << 32);
    unsigned long long q22 = (unsigned long long)qb | ((unsigned long long)qb << 32);

    int per = npairs / PARTS;
    int jb = part * per;
    int je = (part == PARTS - 1) ? npairs : jb + per;

    float b0 = 1e30f, b1 = 1e30f, b2 = 1e30f;

    const ulonglong2* PA = (const ulonglong2*)g_pkA;
    const ulonglong2* PB = (const ulonglong2*)g_pkB;

    int j = jb;
    for (; j + 1 < je; j += 2) {
        ulonglong2 a0 = __ldg(&PA[j]);
        ulonglong2 c0 = __ldg(&PB[j]);
        ulonglong2 a1 = __ldg(&PA[j + 1]);
        ulonglong2 c1 = __ldg(&PB[j + 1]);
        unsigned long long v0 = fma_f32x2(a0.x, nxx, c0.y);
        unsigned long long v1 = fma_f32x2(a1.x, nxx, c1.y);
        v0 = fma_f32x2(a0.y, nyy, v0);
        v1 = fma_f32x2(a1.y, nyy, v1);
        v0 = fma_f32x2(c0.x, nzz, v0);
        v1 = fma_f32x2(c1.x, nzz, v1);
        v0 = add_f32x2(v0, q22);        // d2 >= 0
        v1 = add_f32x2(v1, q22);
        unsigned base4 = 2u * (unsigned)j;
        float k0 = __uint_as_float(((unsigned)v0 & KEYMASK) | base4);
        float k1 = __uint_as_float(((unsigned)(v0 >> 32) & KEYMASK) | (base4 + 1));
        float k2 = __uint_as_float(((unsigned)v1 & KEYMASK) | (base4 + 2));
        float k3 = __uint_as_float(((unsigned)(v1 >> 32) & KEYMASK) | (base4 + 3));
        ins3b(k0, b0, b1, b2);
        ins3b(k1, b0, b1, b2);
        ins3b(k2, b0, b1, b2);
        ins3b(k3, b0, b1, b2);
    }
    for (; j < je; j++) {
        ulonglong2 a0 = __ldg(&PA[j]);
        ulonglong2 c0 = __ldg(&PB[j]);
        unsigned long long v0 = fma_f32x2(a0.x, nxx, c0.y);
        v0 = fma_f32x2(a0.y, nyy, v0);
        v0 = fma_f32x2(c0.x, nzz, v0);
        v0 = add_f32x2(v0, q22);
        unsigned base4 = 2u * (unsigned)j;
        ins3b(__uint_as_float(((unsigned)v0 & KEYMASK) | base4), b0, b1, b2);
        ins3b(__uint_as_float(((unsigned)(v0 >> 32) & KEYMASK) | (base4 + 1)), b0, b1, b2);
    }

    cv[part][qlocal][0] = b0;
    cv[part][qlocal][1] = b1;
    cv[part][qlocal][2] = b2;
    __syncthreads();

    if (part != 0 || !valid) return;

    b0 = cv[0][qlocal][0];
    b1 = cv[0][qlocal][1];
    b2 = cv[0][qlocal][2];
    #pragma unroll
    for (int p = 1; p < PARTS; p++) {
        ins3b(cv[p][qlocal][0], b0, b1, b2);
        ins3b(cv[p][qlocal][1], b0, b1, b2);
        ins3b(cv[p][qlocal][2], b0, b1, b2);
    }

    int i0 = __float_as_uint(b0) & IDXMASK;
    int i1 = __float_as_uint(b1) & IDXMASK;
    int i2 = __float_as_uint(b2) & IDXMASK;

    // softmax(-d2) over the 3 (masked d2 values; perturbation ~1e-4 relative)
    float e1 = __expf(b0 - b1);
    float e2 = __expf(b0 - b2);
    float inv = 1.f / (1.f + e1 + e2);
    float w0 = inv, w1 = e1 * inv, w2 = e2 * inv;

    const float4* xw = (const float4*)(g_XW + (size_t)q * CC);
    const float4* f0 = (const float4*)(g_FS1 + (size_t)i0 * CC);
    const float4* f1 = (const float4*)(g_FS1 + (size_t)i1 * CC);
    const float4* f2 = (const float4*)(g_FS1 + (size_t)i2 * CC);

    float acc[CLSN];
    #pragma unroll
    for (int o = 0; o < CLSN; o++) acc[o] = sb[o];

    for (int c4 = 0; c4 < CC / 4; c4++) {
        float4 x  = xw[c4];
        float4 a0 = f0[c4];
        float4 a1 = f1[c4];
        float4 a2 = f2[c4];
        int cb = c4 * 4;
        float h[4];
        h[0] = x.x + w0 * a0.x + w1 * a1.x + w2 * a2.x + sbeta[cb + 0];
        h[1] = x.y + w0 * a0.y + w1 * a1.y + w2 * a2.y + sbeta[cb + 1];
        h[2] = x.z + w0 * a0.z + w1 * a1.z + w2 * a2.z + sbeta[cb + 2];
        h[3] = x.w + w0 * a0.w + w1 * a1.w + w2 * a2.w + sbeta[cb + 3];
        #pragma unroll
        for (int u = 0; u < 4; u++) {
            float hv = fmaxf(h[u], 0.f);
            const float* wrow = &Wf[(cb + u) * CLSN];
            #pragma unroll
            for (int o = 0; o < CLSN; o++) acc[o] = fmaf(hv, wrow[o], acc[o]);
        }
    }

    float* op = out + (size_t)q * CLSN;
    #pragma unroll
    for (int o = 0; o < CLSN; o++) op[o] = acc[o];
}

// ---------------- launch ---------------------------------------------------
extern "C" void kernel_launch(void* const* d_in, const int* in_sizes, int n_in,
                              void* d_out, int out_size)
{
    const float* coords_q = (const float*)d_in[0];
    const float* coords_s = (const float*)d_in[1];
    const float* x7       = (const float*)d_in[2];
    const float* feat_s7  = (const float*)d_in[3];
    const float* feat_s   = (const float*)d_in[4];
    const float* w_attn   = (const float*)d_in[5];
    const float* W1       = (const float*)d_in[6];
    const float* gamma    = (const float*)d_in[7];
    const float* beta     = (const float*)d_in[8];
    const float* W2       = (const float*)d_in[9];
    const float* W_cls    = (const float*)d_in[10];
    const float* b_cls    = (const float*)d_in[11];
    float* out = (float*)d_out;

    int NQ = in_sizes[0] / 3;
    int NS = in_sizes[1] / 3;
    int npairs = (NS + 1) / 2;
    int nparts = (NS + 31) / 32;          // pool blocks (256 for NS=8192)
    if (nparts > NPOOL) nparts = NPOOL;
    int prepBlocks = (npairs + CC * CLSN + 255) / 256;
    int tilesFS1 = (NS + 127) / 128;
    int tilesXW  = (NQ + 127) / 128;

    k_prep_pool<<<nparts + prepBlocks, 256>>>(feat_s7, w_attn, coords_s,
                                              W2, W_cls, NS, npairs, nparts);
    k_gemm<<<tilesFS1 + tilesXW, 256>>>(feat_s, x7, W1,
                                        tilesFS1, NS, NQ, nparts, gamma);
    k_final<<<(NQ + 31) / 32, 512>>>(coords_q, beta, b_cls, out, NQ, npairs);
}

// round 8
// speedup vs baseline: 2.4413x; 1.3048x over previous
#include <cuda_runtime.h>

#define CC    112
#define CLSN  20
#define NSMAX 8192
#define NQMAX 20000
#define PARTS 16
#define NPOOL 256
#define IDXMASK 0x1FFFu
#define KEYMASK 0xFFFFE000u
#define BS    512

// ---------------- scratch (device globals; no allocation) ----------------
__device__ float  g_part[NPOOL * CC];
__device__ float  g_esum[NPOOL];
__device__ float  g_Wf[CC * CLSN];
__device__ float4 g_pkA[NSMAX / 2 + 1];   // (x0,x1,y0,y1) per point pair
__device__ float4 g_pkB[NSMAX / 2 + 1];   // (z0,z1,w0,w1) per point pair
__device__ float  g_FS1[NSMAX * CC];
__device__ float  g_XW[NQMAX * CC];
__device__ float4 g_sel[NQMAX];           // packed top-3 keys per query
__device__ int    g_done[2];              // [0]=pool blocks done, [1]=pack blocks done

// ---------------- helpers --------------------------------------------------
__device__ __forceinline__ void ins3b(float v, float& b0, float& b1, float& b2)
{
    float h0 = fmaxf(v, b0);  b0 = fminf(v, b0);
    float h1 = fmaxf(h0, b1); b1 = fminf(h0, b1);
    b2 = fminf(h1, b2);
}
__device__ __forceinline__ unsigned long long fma_f32x2(unsigned long long a,
                                                        unsigned long long b,
                                                        unsigned long long c)
{
    unsigned long long d;
    asm("fma.rn.f32x2 %0, %1, %2, %3;" : "=l"(d) : "l"(a), "l"(b), "l"(c));
    return d;
}
__device__ __forceinline__ unsigned long long add_f32x2(unsigned long long a,
                                                        unsigned long long b)
{
    unsigned long long d;
    asm("add.rn.f32x2 %0, %1, %2;" : "=l"(d) : "l"(a), "l"(b));
    return d;
}

// ---------------- K1: mega kernel (pool | pack | gemmFS1 | gemmXW | scan) --
__global__ void __launch_bounds__(BS, 2)
k_mega(const float* __restrict__ F,        // feat_s7
       const float* __restrict__ w,        // w_attn
       const float* __restrict__ coords_s,
       const float* __restrict__ W2,
       const float* __restrict__ Wcls,
       const float* __restrict__ Afs,      // feat_s
       const float* __restrict__ Axw,      // x7
       const float* __restrict__ W1,
       const float* __restrict__ colscale, // gamma
       const float* __restrict__ coords_q,
       int NS, int NQ, int npairs, int nparts, int packB,
       int tilesFS1, int tilesXW)
{
    __shared__ __align__(16) char smraw[29248];
    int tx = threadIdx.x;
    int b = blockIdx.x;

    if (b < nparts) {
        // ================= pool: 32 rows/block, 2 rows/warp =================
        float (*sacc)[CC] = (float (*)[CC])smraw;
        float* sesum = (float*)(smraw + 16 * CC * 4);
        int wp = tx >> 5, lane = tx & 31;
        float w0 = w[lane], w1 = w[lane + 32], w2 = w[lane + 64];
        float w3 = (lane < 16) ? w[lane + 96] : 0.f;
        float p0 = 0.f, p1 = 0.f, p2 = 0.f, p3 = 0.f, es = 0.f;
        int base = b * 32 + wp * 2;
        #pragma unroll
        for (int t = 0; t < 2; t++) {
            int i = base + t;
            if (i < NS) {
                const float* row = F + i * CC;
                float f0 = row[lane];
                float f1 = row[lane + 32];
                float f2 = row[lane + 64];
                float f3 = (lane < 16) ? row[lane + 96] : 0.f;
                float s = f0 * w0 + f1 * w1 + f2 * w2 + f3 * w3;
                #pragma unroll
                for (int o = 16; o; o >>= 1) s += __shfl_xor_sync(0xffffffffu, s, o);
                float e = __expf(s);
                es += e;
                p0 = fmaf(e, f0, p0);
                p1 = fmaf(e, f1, p1);
                p2 = fmaf(e, f2, p2);
                if (lane < 16) p3 = fmaf(e, f3, p3);
            }
        }
        sacc[wp][lane]      = p0;
        sacc[wp][lane + 32] = p1;
        sacc[wp][lane + 64] = p2;
        if (lane < 16) sacc[wp][lane + 96] = p3;
        if (lane == 0) sesum[wp] = es;
        __syncthreads();
        if (tx < CC) {
            float s = 0.f;
            #pragma unroll
            for (int k = 0; k < 16; k++) s += sacc[k][tx];
            g_part[b * CC + tx] = s;
        } else if (tx == CC) {
            float s = 0.f;
            #pragma unroll
            for (int k = 0; k < 16; k++) s += sesum[k];
            g_esum[b] = s;
        }
        __syncthreads();
        if (tx == 0) { __threadfence(); atomicAdd(&g_done[0], 1); }
        return;
    }
    b -= nparts;

    if (b < packB) {
        // ================= pack: pair-packed SoA coords + Wf ================
        int idx = b * BS + tx;
        if (idx < npairs) {
            int i0 = 2 * idx, i1 = 2 * idx + 1;
            float x0 = coords_s[i0 * 3 + 0];
            float y0 = coords_s[i0 * 3 + 1];
            float z0 = coords_s[i0 * 3 + 2];
            float w0 = x0 * x0 + y0 * y0 + z0 * z0;
            float x1 = 0.f, y1 = 0.f, z1 = 0.f, w1 = 1e30f;
            if (i1 < NS) {
                x1 = coords_s[i1 * 3 + 0];
                y1 = coords_s[i1 * 3 + 1];
                z1 = coords_s[i1 * 3 + 2];
                w1 = x1 * x1 + y1 * y1 + z1 * z1;
            }
            g_pkA[idx] = make_float4(x0, x1, y0, y1);
            g_pkB[idx] = make_float4(z0, z1, w0, w1);
        } else {
            int j = idx - npairs;
            if (j < CC * CLSN) {
                int c = j / CLSN, o = j % CLSN;
                float s = 0.f;
                #pragma unroll 8
                for (int k = 0; k < CC; k++)
                    s = fmaf(W2[c * CC + k], Wcls[k * CLSN + o], s);
                g_Wf[j] = s;
            }
        }
        __syncthreads();
        if (tx == 0) { __threadfence(); atomicAdd(&g_done[1], 1); }
        return;
    }
    b -= packB;

    if (b < tilesFS1 + tilesXW) {
        // ================= gemm: 128x112 tile, 4x7 per thread ===============
        bool isXW = (b >= tilesFS1);
        const float* A  = isXW ? Axw : Afs;
        const float* Bm = isXW ? W1 : (W1 + CC * CC);
        int M  = isXW ? NQ : NS;
        int m0 = (isXW ? (b - tilesFS1) : b) * 128;

        float (*As)[136] = (float (*)[136])smraw;
        float (*Bs)[112] = (float (*)[112])(smraw + 15232);
        float* sgate = (float*)(smraw + 27776);
        float* sred  = (float*)(smraw + 28224);

        if (isXW) {
            if (tx == 0) {
                while (atomicAdd(&g_done[0], 0) < nparts) __nanosleep(64);
                __threadfence();
            }
            __syncthreads();
            if (tx < 256) sred[tx] = (tx < nparts) ? g_esum[tx] : 0.f;
            __syncthreads();
            if (tx < 128) sred[tx] += sred[tx + 128];
            __syncthreads();
            if (tx < 64) sred[tx] += sred[tx + 64];
            __syncthreads();
            if (tx < 32) {
                float v = sred[tx] + sred[tx + 32];
                #pragma unroll
                for (int o = 16; o; o >>= 1) v += __shfl_xor_sync(0xffffffffu, v, o);
                sred[tx] = v;
            }
            __syncthreads();
            float inv_es = 1.f / sred[0];
            if (tx < CC) {
                float s = 0.f;
                #pragma unroll 8
                for (int p = 0; p < nparts; p++) s += g_part[p * CC + tx];
                sgate[tx] = 1.f / (1.f + __expf(-s * inv_es));
            }
            __syncthreads();
        }

        float acc[4][7];
        #pragma unroll
        for (int i = 0; i < 4; i++)
            #pragma unroll
            for (int j = 0; j < 7; j++) acc[i][j] = 0.f;
        int rg = (tx >> 4) * 4;     // 0..124 step 4
        int cg = (tx & 15) * 7;     // 0..105 step 7

        for (int k0 = 0; k0 < CC; k0 += 28) {
            for (int idx = tx; idx < 128 * 7; idx += BS) {
                int r = idx / 7, k4 = idx - r * 7;
                int gr = m0 + r;
                float4 v = (gr < M) ? *(const float4*)&A[gr * CC + k0 + k4 * 4]
                                    : make_float4(0.f, 0.f, 0.f, 0.f);
                As[k4 * 4 + 0][r] = v.x;
                As[k4 * 4 + 1][r] = v.y;
                As[k4 * 4 + 2][r] = v.z;
                As[k4 * 4 + 3][r] = v.w;
            }
            for (int idx = tx; idx < 28 * 28; idx += BS) {
                int k = idx / 28, c4 = idx - k * 28;
                float4 v = *(const float4*)&Bm[(k0 + k) * CC + c4 * 4];
                if (isXW) {
                    float gsc = sgate[k0 + k];
                    v.x *= gsc; v.y *= gsc; v.z *= gsc; v.w *= gsc;
                }
                *(float4*)&Bs[k][c4 * 4] = v;
            }
            __syncthreads();
            #pragma unroll 4
            for (int k = 0; k < 28; k++) {
                float4 av = *(const float4*)&As[k][rg];
                float a[4] = {av.x, av.y, av.z, av.w};
                float bb[7];
                #pragma unroll
                for (int j = 0; j < 7; j++) bb[j] = Bs[k][cg + j];
                #pragma unroll
                for (int i = 0; i < 4; i++)
                    #pragma unroll
                    for (int j = 0; j < 7; j++)
                        acc[i][j] = fmaf(a[i], bb[j], acc[i][j]);
            }
            __syncthreads();
        }

        float* Cout = isXW ? g_XW : g_FS1;
        float cs[7];
        #pragma unroll
        for (int j = 0; j < 7; j++) cs[j] = colscale[cg + j];
        #pragma unroll
        for (int i = 0; i < 4; i++) {
            int gr = m0 + rg + i;
            if (gr < M) {
                #pragma unroll
                for (int j = 0; j < 7; j++)
                    Cout[(size_t)gr * CC + cg + j] = acc[i][j] * cs[j];
            }
        }
        return;
    }
    b -= tilesFS1 + tilesXW;

    // ================= scan: branchless packed top-3 =======================
    {
        float (*cv)[32][3] = (float (*)[32][3])smraw;
        int qlocal = tx & 31, part = tx >> 5;

        if (tx == 0) {
            while (atomicAdd(&g_done[1], 0) < packB) __nanosleep(64);
            __threadfence();
        }
        __syncthreads();

        int q = b * 32 + qlocal;
        bool valid = (q < NQ);
        float nx = 0.f, ny = 0.f, nz = 0.f, q2 = 0.f;
        if (valid) {
            float qx = coords_q[q * 3 + 0];
            float qy = coords_q[q * 3 + 1];
            float qz = coords_q[q * 3 + 2];
            nx = -2.f * qx; ny = -2.f * qy; nz = -2.f * qz;
            q2 = qx * qx + qy * qy + qz * qz;
        }
        unsigned xb = __float_as_uint(nx), yb = __float_as_uint(ny), zb = __float_as_uint(nz);
        unsigned qb = __float_as_uint(q2);
        unsigned long long nxx = (unsigned long long)xb | ((unsigned long long)xb << 32);
        unsigned long long nyy = (unsigned long long)yb | ((unsigned long long)yb << 32);
        unsigned long long nzz = (unsigned long long)zb | ((unsigned long long)zb << 32);
        unsigned long long q22 = (unsigned long long)qb | ((unsigned long long)qb << 32);

        int per = npairs / PARTS;
        int jb = part * per;
        int je = (part == PARTS - 1) ? npairs : jb + per;

        float b0 = 1e30f, b1 = 1e30f, b2 = 1e30f;

        const ulonglong2* PA = (const ulonglong2*)g_pkA;
        const ulonglong2* PB = (const ulonglong2*)g_pkB;

        int j = jb;
        for (; j + 1 < je; j += 2) {
            ulonglong2 a0 = __ldg(&PA[j]);
            ulonglong2 c0 = __ldg(&PB[j]);
            ulonglong2 a1 = __ldg(&PA[j + 1]);
            ulonglong2 c1 = __ldg(&PB[j + 1]);
            unsigned long long v0 = fma_f32x2(a0.x, nxx, c0.y);
            unsigned long long v1 = fma_f32x2(a1.x, nxx, c1.y);
            v0 = fma_f32x2(a0.y, nyy, v0);
            v1 = fma_f32x2(a1.y, nyy, v1);
            v0 = fma_f32x2(c0.x, nzz, v0);
            v1 = fma_f32x2(c1.x, nzz, v1);
            v0 = add_f32x2(v0, q22);        // d2 >= 0
            v1 = add_f32x2(v1, q22);
            unsigned base4 = 2u * (unsigned)j;
            ins3b(__uint_as_float(((unsigned)v0 & KEYMASK) | base4),           b0, b1, b2);
            ins3b(__uint_as_float(((unsigned)(v0 >> 32) & KEYMASK) | (base4 + 1)), b0, b1, b2);
            ins3b(__uint_as_float(((unsigned)v1 & KEYMASK) | (base4 + 2)),     b0, b1, b2);
            ins3b(__uint_as_float(((unsigned)(v1 >> 32) & KEYMASK) | (base4 + 3)), b0, b1, b2);
        }
        for (; j < je; j++) {
            ulonglong2 a0 = __ldg(&PA[j]);
            ulonglong2 c0 = __ldg(&PB[j]);
            unsigned long long v0 = fma_f32x2(a0.x, nxx, c0.y);
            v0 = fma_f32x2(a0.y, nyy, v0);
            v0 = fma_f32x2(c0.x, nzz, v0);
            v0 = add_f32x2(v0, q22);
            unsigned base4 = 2u * (unsigned)j;
            ins3b(__uint_as_float(((unsigned)v0 & KEYMASK) | base4), b0, b1, b2);
            ins3b(__uint_as_float(((unsigned)(v0 >> 32) & KEYMASK) | (base4 + 1)), b0, b1, b2);
        }

        cv[part][qlocal][0] = b0;
        cv[part][qlocal][1] = b1;
        cv[part][qlocal][2] = b2;
        __syncthreads();

        if (part == 0 && valid) {
            b0 = cv[0][qlocal][0];
            b1 = cv[0][qlocal][1];
            b2 = cv[0][qlocal][2];
            #pragma unroll
            for (int p = 1; p < PARTS; p++) {
                ins3b(cv[p][qlocal][0], b0, b1, b2);
                ins3b(cv[p][qlocal][1], b0, b1, b2);
                ins3b(cv[p][qlocal][2], b0, b1, b2);
            }
            g_sel[q] = make_float4(b0, b1, b2, 0.f);
        }
    }
}

// ---------------- K2: epilogue — exact d2, softmax, gather, classify -------
__global__ void k_epi(const float* __restrict__ coords_q,
                      const float* __restrict__ beta,
                      const float* __restrict__ bcls,
                      float* __restrict__ out,
                      int NQ)
{
    __shared__ float Wf[CC * CLSN];
    __shared__ float sbeta[CC];
    __shared__ float sb[CLSN];
    int tx = threadIdx.x;
    for (int i = tx; i < CC * CLSN; i += 128) Wf[i] = g_Wf[i];
    if (tx < CC)   sbeta[tx] = beta[tx];
    if (tx < CLSN) sb[tx] = bcls[tx];
    __syncthreads();

    int q = blockIdx.x * 128 + tx;
    if (q >= NQ) return;

    float qx = coords_q[q * 3 + 0];
    float qy = coords_q[q * 3 + 1];
    float qz = coords_q[q * 3 + 2];
    float nx = -2.f * qx, ny = -2.f * qy, nz = -2.f * qz;
    float q2 = qx * qx + qy * qy + qz * qz;

    float4 sel = g_sel[q];
    int i0 = __float_as_uint(sel.x) & IDXMASK;
    int i1 = __float_as_uint(sel.y) & IDXMASK;
    int i2 = __float_as_uint(sel.z) & IDXMASK;

    // exact d2 recompute for the 3 selected points
    float d[3];
    int idx3[3] = {i0, i1, i2};
    #pragma unroll
    for (int k = 0; k < 3; k++) {
        int ii = idx3[k], pj = ii >> 1, hi = ii & 1;
        float4 A = g_pkA[pj];
        float4 B = g_pkB[pj];
        float sx = hi ? A.y : A.x;
        float sy = hi ? A.w : A.z;
        float sz = hi ? B.y : B.x;
        float sw = hi ? B.w : B.z;
        d[k] = fmaf(sx, nx, fmaf(sy, ny, fmaf(sz, nz, sw))) + q2;
    }
    float m = fminf(d[0], fminf(d[1], d[2]));
    float e0 = __expf(m - d[0]);
    float e1 = __expf(m - d[1]);
    float e2 = __expf(m - d[2]);
    float inv = 1.f / (e0 + e1 + e2);
    float w0 = e0 * inv, w1 = e1 * inv, w2 = e2 * inv;

    const float4* xw = (const float4*)(g_XW + (size_t)q * CC);
    const float4* f0 = (const float4*)(g_FS1 + (size_t)i0 * CC);
    const float4* f1 = (const float4*)(g_FS1 + (size_t)i1 * CC);
    const float4* f2 = (const float4*)(g_FS1 + (size_t)i2 * CC);

    float acc[CLSN];
    #pragma unroll
    for (int o = 0; o < CLSN; o++) acc[o] = sb[o];

    for (int c4 = 0; c4 < CC / 4; c4++) {
        float4 x  = xw[c4];
        float4 a0 = f0[c4];
        float4 a1 = f1[c4];
        float4 a2 = f2[c4];
        int cb = c4 * 4;
        float h[4];
        h[0] = x.x + w0 * a0.x + w1 * a1.x + w2 * a2.x + sbeta[cb + 0];
        h[1] = x.y + w0 * a0.y + w1 * a1.y + w2 * a2.y + sbeta[cb + 1];
        h[2] = x.z + w0 * a0.z + w1 * a1.z + w2 * a2.z + sbeta[cb + 2];
        h[3] = x.w + w0 * a0.w + w1 * a1.w + w2 * a2.w + sbeta[cb + 3];
        #pragma unroll
        for (int u = 0; u < 4; u++) {
            float hv = fmaxf(h[u], 0.f);
            const float* wrow = &Wf[(cb + u) * CLSN];
            #pragma unroll
            for (int o = 0; o < CLSN; o++) acc[o] = fmaf(hv, wrow[o], acc[o]);
        }
    }

    float* op = out + (size_t)q * CLSN;
    #pragma unroll
    for (int o = 0; o < CLSN; o++) op[o] = acc[o];
}

// ---------------- launch ---------------------------------------------------
extern "C" void kernel_launch(void* const* d_in, const int* in_sizes, int n_in,
                              void* d_out, int out_size)
{
    const float* coords_q = (const float*)d_in[0];
    const float* coords_s = (const float*)d_in[1];
    const float* x7       = (const float*)d_in[2];
    const float* feat_s7  = (const float*)d_in[3];
    const float* feat_s   = (const float*)d_in[4];
    const float* w_attn   = (const float*)d_in[5];
    const float* W1       = (const float*)d_in[6];
    const float* gamma    = (const float*)d_in[7];
    const float* beta     = (const float*)d_in[8];
    const float* W2       = (const float*)d_in[9];
    const float* W_cls    = (const float*)d_in[10];
    const float* b_cls    = (const float*)d_in[11];
    float* out = (float*)d_out;

    int NQ = in_sizes[0] / 3;
    int NS = in_sizes[1] / 3;
    int npairs = (NS + 1) / 2;
    int nparts = (NS + 31) / 32;
    if (nparts > NPOOL) nparts = NPOOL;
    int packB    = (npairs + CC * CLSN + BS - 1) / BS;
    int tilesFS1 = (NS + 127) / 128;
    int tilesXW  = (NQ + 127) / 128;
    int scanB    = (NQ + 31) / 32;
    int grid     = nparts + packB + tilesFS1 + tilesXW + scanB;

    int* donep;
    cudaGetSymbolAddress((void**)&donep, g_done);
    cudaMemsetAsync(donep, 0, 2 * sizeof(int));

    k_mega<<<grid, BS>>>(feat_s7, w_attn, coords_s, W2, W_cls,
                         feat_s, x7, W1, gamma, coords_q,
                         NS, NQ, npairs, nparts, packB, tilesFS1, tilesXW);
    k_epi<<<(NQ + 127) / 128, 128>>>(coords_q, beta, b_cls, out, NQ);
}

// round 9
// speedup vs baseline: 2.5063x; 1.0266x over previous
#include <cuda_runtime.h>

#define CC    112
#define CLSN  20
#define NSMAX 8192
#define NQMAX 20000
#define PARTS 16
#define NPOOL 256
#define IDXMASK 0x1FFFu
#define KEYMASK 0xFFFFE000u
#define BS    512

// ---------------- scratch (device globals; no allocation) ----------------
__device__ float  g_part[NPOOL * CC];
__device__ float  g_esum[NPOOL];
__device__ float  g_Wf[CC * CLSN];
__device__ float4 g_pkA[NSMAX / 2 + 1];   // (x0,x1,y0,y1) per point pair
__device__ float4 g_pkB[NSMAX / 2 + 1];   // (z0,z1,w0,w1) per point pair
__device__ float  g_FS1[NSMAX * CC];
__device__ float  g_XW[NQMAX * CC];
__device__ int    g_done[3];  // [0]=pool done, [1]=pack done, [2]=gemm done

// ---------------- helpers --------------------------------------------------
__device__ __forceinline__ void ins3b(float v, float& b0, float& b1, float& b2)
{
    float h0 = fmaxf(v, b0);  b0 = fminf(v, b0);
    float h1 = fmaxf(h0, b1); b1 = fminf(h0, b1);
    b2 = fminf(h1, b2);
}
__device__ __forceinline__ unsigned long long fma_f32x2(unsigned long long a,
                                                        unsigned long long b,
                                                        unsigned long long c)
{
    unsigned long long d;
    asm("fma.rn.f32x2 %0, %1, %2, %3;" : "=l"(d) : "l"(a), "l"(b), "l"(c));
    return d;
}
__device__ __forceinline__ unsigned long long add_f32x2(unsigned long long a,
                                                        unsigned long long b)
{
    unsigned long long d;
    asm("add.rn.f32x2 %0, %1, %2;" : "=l"(d) : "l"(a), "l"(b));
    return d;
}

// ---------------- mega kernel: pool | pack | gemm | scan+epilogue ----------
__global__ void __launch_bounds__(BS, 2)
k_mega(const float* __restrict__ F,        // feat_s7
       const float* __restrict__ w,        // w_attn
       const float* __restrict__ coords_s,
       const float* __restrict__ W2,
       const float* __restrict__ Wcls,
       const float* __restrict__ Afs,      // feat_s
       const float* __restrict__ Axw,      // x7
       const float* __restrict__ W1,
       const float* __restrict__ colscale, // gamma
       const float* __restrict__ coords_q,
       const float* __restrict__ beta,
       const float* __restrict__ bcls,
       float* __restrict__ out,
       int NS, int NQ, int npairs, int nparts, int packB,
       int tilesFS1, int tilesXW)
{
    __shared__ __align__(16) char smraw[29248];
    int tx = threadIdx.x;
    int b = blockIdx.x;
    int ngemm = tilesFS1 + tilesXW;

    if (b < nparts) {
        // ================= pool: 32 rows/block, 2 rows/warp =================
        float (*sacc)[CC] = (float (*)[CC])smraw;
        float* sesum = (float*)(smraw + 16 * CC * 4);
        int wp = tx >> 5, lane = tx & 31;
        float w0 = w[lane], w1 = w[lane + 32], w2 = w[lane + 64];
        float w3 = (lane < 16) ? w[lane + 96] : 0.f;
        float p0 = 0.f, p1 = 0.f, p2 = 0.f, p3 = 0.f, es = 0.f;
        int base = b * 32 + wp * 2;
        #pragma unroll
        for (int t = 0; t < 2; t++) {
            int i = base + t;
            if (i < NS) {
                const float* row = F + i * CC;
                float f0 = row[lane];
                float f1 = row[lane + 32];
                float f2 = row[lane + 64];
                float f3 = (lane < 16) ? row[lane + 96] : 0.f;
                float s = f0 * w0 + f1 * w1 + f2 * w2 + f3 * w3;
                #pragma unroll
                for (int o = 16; o; o >>= 1) s += __shfl_xor_sync(0xffffffffu, s, o);
                float e = __expf(s);
                es += e;
                p0 = fmaf(e, f0, p0);
                p1 = fmaf(e, f1, p1);
                p2 = fmaf(e, f2, p2);
                if (lane < 16) p3 = fmaf(e, f3, p3);
            }
        }
        sacc[wp][lane]      = p0;
        sacc[wp][lane + 32] = p1;
        sacc[wp][lane + 64] = p2;
        if (lane < 16) sacc[wp][lane + 96] = p3;
        if (lane == 0) sesum[wp] = es;
        __syncthreads();
        if (tx < CC) {
            float s = 0.f;
            #pragma unroll
            for (int k = 0; k < 16; k++) s += sacc[k][tx];
            g_part[b * CC + tx] = s;
        } else if (tx == CC) {
            float s = 0.f;
            #pragma unroll
            for (int k = 0; k < 16; k++) s += sesum[k];
            g_esum[b] = s;
        }
        __syncthreads();
        if (tx == 0) { __threadfence(); atomicAdd(&g_done[0], 1); }
        return;
    }
    b -= nparts;

    if (b < packB) {
        // ================= pack: pair-packed SoA coords + Wf ================
        int idx = b * BS + tx;
        if (idx < npairs) {
            int i0 = 2 * idx, i1 = 2 * idx + 1;
            float x0 = coords_s[i0 * 3 + 0];
            float y0 = coords_s[i0 * 3 + 1];
            float z0 = coords_s[i0 * 3 + 2];
            float w0 = x0 * x0 + y0 * y0 + z0 * z0;
            float x1 = 0.f, y1 = 0.f, z1 = 0.f, w1 = 1e30f;
            if (i1 < NS) {
                x1 = coords_s[i1 * 3 + 0];
                y1 = coords_s[i1 * 3 + 1];
                z1 = coords_s[i1 * 3 + 2];
                w1 = x1 * x1 + y1 * y1 + z1 * z1;
            }
            g_pkA[idx] = make_float4(x0, x1, y0, y1);
            g_pkB[idx] = make_float4(z0, z1, w0, w1);
        } else {
            int j = idx - npairs;
            if (j < CC * CLSN) {
                int c = j / CLSN, o = j % CLSN;
                float s = 0.f;
                #pragma unroll 8
                for (int k = 0; k < CC; k++)
                    s = fmaf(W2[c * CC + k], Wcls[k * CLSN + o], s);
                g_Wf[j] = s;
            }
        }
        __syncthreads();
        if (tx == 0) { __threadfence(); atomicAdd(&g_done[1], 1); }
        return;
    }
    b -= packB;

    if (b < ngemm) {
        // ================= gemm: 128x112 tile, 4x7 per thread ===============
        bool isXW = (b >= tilesFS1);
        const float* A  = isXW ? Axw : Afs;
        const float* Bm = isXW ? W1 : (W1 + CC * CC);
        int M  = isXW ? NQ : NS;
        int m0 = (isXW ? (b - tilesFS1) : b) * 128;

        float (*As)[136] = (float (*)[136])smraw;
        float (*Bs)[112] = (float (*)[112])(smraw + 15232);
        float* sgate = (float*)(smraw + 27776);
        float* sred  = (float*)(smraw + 28224);

        if (isXW) {
            if (tx == 0) {
                while (atomicAdd(&g_done[0], 0) < nparts) __nanosleep(64);
                __threadfence();
            }
            __syncthreads();
            if (tx < 256) sred[tx] = (tx < nparts) ? g_esum[tx] : 0.f;
            __syncthreads();
            if (tx < 128) sred[tx] += sred[tx + 128];
            __syncthreads();
            if (tx < 64) sred[tx] += sred[tx + 64];
            __syncthreads();
            if (tx < 32) {
                float v = sred[tx] + sred[tx + 32];
                #pragma unroll
                for (int o = 16; o; o >>= 1) v += __shfl_xor_sync(0xffffffffu, v, o);
                sred[tx] = v;
            }
            __syncthreads();
            float inv_es = 1.f / sred[0];
            if (tx < CC) {
                float s = 0.f;
                #pragma unroll 8
                for (int p = 0; p < nparts; p++) s += g_part[p * CC + tx];
                sgate[tx] = 1.f / (1.f + __expf(-s * inv_es));
            }
            __syncthreads();
        }

        float acc[4][7];
        #pragma unroll
        for (int i = 0; i < 4; i++)
            #pragma unroll
            for (int j = 0; j < 7; j++) acc[i][j] = 0.f;
        int rg = (tx >> 4) * 4;
        int cg = (tx & 15) * 7;

        for (int k0 = 0; k0 < CC; k0 += 28) {
            for (int idx = tx; idx < 128 * 7; idx += BS) {
                int r = idx / 7, k4 = idx - r * 7;
                int gr = m0 + r;
                float4 v = (gr < M) ? *(const float4*)&A[gr * CC + k0 + k4 * 4]
                                    : make_float4(0.f, 0.f, 0.f, 0.f);
                As[k4 * 4 + 0][r] = v.x;
                As[k4 * 4 + 1][r] = v.y;
                As[k4 * 4 + 2][r] = v.z;
                As[k4 * 4 + 3][r] = v.w;
            }
            for (int idx = tx; idx < 28 * 28; idx += BS) {
                int k = idx / 28, c4 = idx - k * 28;
                float4 v = *(const float4*)&Bm[(k0 + k) * CC + c4 * 4];
                if (isXW) {
                    float gsc = sgate[k0 + k];
                    v.x *= gsc; v.y *= gsc; v.z *= gsc; v.w *= gsc;
                }
                *(float4*)&Bs[k][c4 * 4] = v;
            }
            __syncthreads();
            #pragma unroll 4
            for (int k = 0; k < 28; k++) {
                float4 av = *(const float4*)&As[k][rg];
                float a[4] = {av.x, av.y, av.z, av.w};
                float bb[7];
                #pragma unroll
                for (int j = 0; j < 7; j++) bb[j] = Bs[k][cg + j];
                #pragma unroll
                for (int i = 0; i < 4; i++)
                    #pragma unroll
                    for (int j = 0; j < 7; j++)
                        acc[i][j] = fmaf(a[i], bb[j], acc[i][j]);
            }
            __syncthreads();
        }

        float* Cout = isXW ? g_XW : g_FS1;
        float cs[7];
        #pragma unroll
        for (int j = 0; j < 7; j++) cs[j] = colscale[cg + j];
        #pragma unroll
        for (int i = 0; i < 4; i++) {
            int gr = m0 + rg + i;
            if (gr < M) {
                #pragma unroll
                for (int j = 0; j < 7; j++)
                    Cout[(size_t)gr * CC + cg + j] = acc[i][j] * cs[j];
            }
        }
        __syncthreads();
        if (tx == 0) { __threadfence(); atomicAdd(&g_done[2], 1); }
        return;
    }
    b -= ngemm;

    // ================= scan + fused epilogue ===============================
    {
        float (*cv)[32][3] = (float (*)[32][3])smraw;            // 6144 B
        float* Wf    = (float*)(smraw + 6144);                   // 8960 B
        float* sbeta = (float*)(smraw + 15104);                  // 448 B
        float* sb    = (float*)(smraw + 15552);                  // 80 B
        int qlocal = tx & 31, part = tx >> 5;

        // preload epilogue constants (Wf written by pack blocks — wait first)
        if (tx == 0) {
            while (atomicAdd(&g_done[1], 0) < packB) __nanosleep(64);
            __threadfence();
        }
        __syncthreads();
        for (int i = tx; i < CC * CLSN; i += BS) Wf[i] = g_Wf[i];
        if (tx < CC)   sbeta[tx] = beta[tx];
        if (tx < CLSN) sb[tx] = bcls[tx];

        int q = b * 32 + qlocal;
        bool valid = (q < NQ);
        float nx = 0.f, ny = 0.f, nz = 0.f, q2 = 0.f;
        if (valid) {
            float qx = coords_q[q * 3 + 0];
            float qy = coords_q[q * 3 + 1];
            float qz = coords_q[q * 3 + 2];
            nx = -2.f * qx; ny = -2.f * qy; nz = -2.f * qz;
            q2 = qx * qx + qy * qy + qz * qz;
        }
        unsigned xb = __float_as_uint(nx), yb = __float_as_uint(ny), zb = __float_as_uint(nz);
        unsigned qb = __float_as_uint(q2);
        unsigned long long nxx = (unsigned long long)xb | ((unsigned long long)xb << 32);
        unsigned long long nyy = (unsigned long long)yb | ((unsigned long long)yb << 32);
        unsigned long long nzz = (unsigned long long)zb | ((unsigned long long)zb << 32);
        unsigned long long q22 = (unsigned long long)qb | ((unsigned long long)qb << 32);

        int per = npairs / PARTS;
        int jb = part * per;
        int je = (part == PARTS - 1) ? npairs : jb + per;

        float b0 = 1e30f, b1 = 1e30f, b2 = 1e30f;

        const ulonglong2* PA = (const ulonglong2*)g_pkA;
        const ulonglong2* PB = (const ulonglong2*)g_pkB;

        int j = jb;
        for (; j + 1 < je; j += 2) {
            ulonglong2 a0 = __ldg(&PA[j]);
            ulonglong2 c0 = __ldg(&PB[j]);
            ulonglong2 a1 = __ldg(&PA[j + 1]);
            ulonglong2 c1 = __ldg(&PB[j + 1]);
            unsigned long long v0 = fma_f32x2(a0.x, nxx, c0.y);
            unsigned long long v1 = fma_f32x2(a1.x, nxx, c1.y);
            v0 = fma_f32x2(a0.y, nyy, v0);
            v1 = fma_f32x2(a1.y, nyy, v1);
            v0 = fma_f32x2(c0.x, nzz, v0);
            v1 = fma_f32x2(c1.x, nzz, v1);
            v0 = add_f32x2(v0, q22);
            v1 = add_f32x2(v1, q22);
            unsigned base4 = 2u * (unsigned)j;
            ins3b(__uint_as_float(((unsigned)v0 & KEYMASK) | base4),           b0, b1, b2);
            ins3b(__uint_as_float(((unsigned)(v0 >> 32) & KEYMASK) | (base4 + 1)), b0, b1, b2);
            ins3b(__uint_as_float(((unsigned)v1 & KEYMASK) | (base4 + 2)),     b0, b1, b2);
            ins3b(__uint_as_float(((unsigned)(v1 >> 32) & KEYMASK) | (base4 + 3)), b0, b1, b2);
        }
        for (; j < je; j++) {
            ulonglong2 a0 = __ldg(&PA[j]);
            ulonglong2 c0 = __ldg(&PB[j]);
            unsigned long long v0 = fma_f32x2(a0.x, nxx, c0.y);
            v0 = fma_f32x2(a0.y, nyy, v0);
            v0 = fma_f32x2(c0.x, nzz, v0);
            v0 = add_f32x2(v0, q22);
            unsigned base4 = 2u * (unsigned)j;
            ins3b(__uint_as_float(((unsigned)v0 & KEYMASK) | base4), b0, b1, b2);
            ins3b(__uint_as_float(((unsigned)(v0 >> 32) & KEYMASK) | (base4 + 1)), b0, b1, b2);
        }

        cv[part][qlocal][0] = b0;
        cv[part][qlocal][1] = b1;
        cv[part][qlocal][2] = b2;
        __syncthreads();

        if (part != 0 || !valid) return;

        b0 = cv[0][qlocal][0];
        b1 = cv[0][qlocal][1];
        b2 = cv[0][qlocal][2];
        #pragma unroll
        for (int p = 1; p < PARTS; p++) {
            ins3b(cv[p][qlocal][0], b0, b1, b2);
            ins3b(cv[p][qlocal][1], b0, b1, b2);
            ins3b(cv[p][qlocal][2], b0, b1, b2);
        }

        int i0 = __float_as_uint(b0) & IDXMASK;
        int i1 = __float_as_uint(b1) & IDXMASK;
        int i2 = __float_as_uint(b2) & IDXMASK;

        // exact d2 recompute for the selected 3 (fp32 precision)
        float d[3];
        int idx3[3] = {i0, i1, i2};
        #pragma unroll
        for (int k = 0; k < 3; k++) {
            int ii = idx3[k], pj = ii >> 1, hi = ii & 1;
            float4 A = g_pkA[pj];
            float4 B = g_pkB[pj];
            float sx = hi ? A.y : A.x;
            float sy = hi ? A.w : A.z;
            float sz = hi ? B.y : B.x;
            float sw = hi ? B.w : B.z;
            d[k] = fmaf(sx, nx, fmaf(sy, ny, fmaf(sz, nz, sw))) + q2;
        }
        float mn = fminf(d[0], fminf(d[1], d[2]));
        float e0 = __expf(mn - d[0]);
        float e1 = __expf(mn - d[1]);
        float e2 = __expf(mn - d[2]);
        float inv = 1.f / (e0 + e1 + e2);
        float w0 = e0 * inv, w1 = e1 * inv, w2 = e2 * inv;

        // wait for gemm outputs (gemm blocks precede scan blocks; no deadlock)
        {
            int lane = tx & 31;
            if (lane == 0) {
                while (atomicAdd(&g_done[2], 0) < ngemm) __nanosleep(64);
                __threadfence();
            }
            __syncwarp();
        }

        const float4* xw = (const float4*)(g_XW + (size_t)q * CC);
        const float4* f0 = (const float4*)(g_FS1 + (size_t)i0 * CC);
        const float4* f1 = (const float4*)(g_FS1 + (size_t)i1 * CC);
        const float4* f2 = (const float4*)(g_FS1 + (size_t)i2 * CC);

        float acc[CLSN];
        #pragma unroll
        for (int o = 0; o < CLSN; o++) acc[o] = sb[o];

        for (int c4 = 0; c4 < CC / 4; c4++) {
            float4 x  = xw[c4];
            float4 a0 = f0[c4];
            float4 a1 = f1[c4];
            float4 a2 = f2[c4];
            int cb = c4 * 4;
            float h[4];
            h[0] = x.x + w0 * a0.x + w1 * a1.x + w2 * a2.x + sbeta[cb + 0];
            h[1] = x.y + w0 * a0.y + w1 * a1.y + w2 * a2.y + sbeta[cb + 1];
            h[2] = x.z + w0 * a0.z + w1 * a1.z + w2 * a2.z + sbeta[cb + 2];
            h[3] = x.w + w0 * a0.w + w1 * a1.w + w2 * a2.w + sbeta[cb + 3];
            #pragma unroll
            for (int u = 0; u < 4; u++) {
                float hv = fmaxf(h[u], 0.f);
                const float* wrow = &Wf[(cb + u) * CLSN];
                #pragma unroll
                for (int o = 0; o < CLSN; o++) acc[o] = fmaf(hv, wrow[o], acc[o]);
            }
        }

        float* op = out + (size_t)q * CLSN;
        #pragma unroll
        for (int o = 0; o < CLSN; o++) op[o] = acc[o];
    }
}

// ---------------- launch ---------------------------------------------------
extern "C" void kernel_launch(void* const* d_in, const int* in_sizes, int n_in,
                              void* d_out, int out_size)
{
    const float* coords_q = (const float*)d_in[0];
    const float* coords_s = (const float*)d_in[1];
    const float* x7       = (const float*)d_in[2];
    const float* feat_s7  = (const float*)d_in[3];
    const float* feat_s   = (const float*)d_in[4];
    const float* w_attn   = (const float*)d_in[5];
    const float* W1       = (const float*)d_in[6];
    const float* gamma    = (const float*)d_in[7];
    const float* beta     = (const float*)d_in[8];
    const float* W2       = (const float*)d_in[9];
    const float* W_cls    = (const float*)d_in[10];
    const float* b_cls    = (const float*)d_in[11];
    float* out = (float*)d_out;

    int NQ = in_sizes[0] / 3;
    int NS = in_sizes[1] / 3;
    int npairs = (NS + 1) / 2;
    int nparts = (NS + 31) / 32;
    if (nparts > NPOOL) nparts = NPOOL;
    int packB    = (npairs + CC * CLSN + BS - 1) / BS;
    int tilesFS1 = (NS + 127) / 128;
    int tilesXW  = (NQ + 127) / 128;
    int scanB    = (NQ + 31) / 32;
    int grid     = nparts + packB + tilesFS1 + tilesXW + scanB;

    int* donep;
    cudaGetSymbolAddress((void**)&donep, g_done);
    cudaMemsetAsync(donep, 0, 3 * sizeof(int));

    k_mega<<<grid, BS>>>(feat_s7, w_attn, coords_s, W2, W_cls,
                         feat_s, x7, W1, gamma, coords_q,
                         beta, b_cls, out,
                         NS, NQ, npairs, nparts, packB, tilesFS1, tilesXW);
}

// round 11
// speedup vs baseline: 2.6839x; 1.0709x over previous
#include <cuda_runtime.h>

#define CC    112
#define CLSN  20
#define NSMAX 8192
#define NQMAX 20000
#define PARTS 16
#define NPOOL 256
#define IDXMASK 0x1FFFu
#define KEYMASK 0xFFFFE000u
#define BS    512

// ---------------- scratch (device globals; no allocation) ----------------
__device__ float  g_part[NPOOL * CC];
__device__ float  g_esum[NPOOL];
__device__ float  g_Wf[CC * CLSN];
__device__ float4 g_pkA[NSMAX / 2 + 1];   // (x0,x1,y0,y1) per point pair
__device__ float4 g_pkB[NSMAX / 2 + 1];   // (z0,z1,w0,w1) per point pair
__device__ float  g_FS1[NSMAX * CC];
__device__ float  g_XW[NQMAX * CC];
__device__ int    g_done[3];  // [0]=pool done, [1]=pack done, [2]=gemm done

typedef unsigned long long u64;

// ---------------- helpers --------------------------------------------------
__device__ __forceinline__ void ins3b(float v, float& b0, float& b1, float& b2)
{
    float h0 = fmaxf(v, b0);  b0 = fminf(v, b0);
    float h1 = fmaxf(h0, b1); b1 = fminf(h0, b1);
    b2 = fminf(h1, b2);
}
__device__ __forceinline__ u64 fma_f32x2(u64 a, u64 b, u64 c)
{
    u64 d;
    asm("fma.rn.f32x2 %0, %1, %2, %3;" : "=l"(d) : "l"(a), "l"(b), "l"(c));
    return d;
}
__device__ __forceinline__ u64 add_f32x2(u64 a, u64 b)
{
    u64 d;
    asm("add.rn.f32x2 %0, %1, %2;" : "=l"(d) : "l"(a), "l"(b));
    return d;
}

// ---------------- mega kernel: pool | pack | gemm | scan+epilogue ----------
__global__ void __launch_bounds__(BS, 2)
k_mega(const float* __restrict__ F,        // feat_s7
       const float* __restrict__ w,        // w_attn
       const float* __restrict__ coords_s,
       const float* __restrict__ W2,
       const float* __restrict__ Wcls,
       const float* __restrict__ Afs,      // feat_s
       const float* __restrict__ Axw,      // x7
       const float* __restrict__ W1,
       const float* __restrict__ colscale, // gamma
       const float* __restrict__ coords_q,
       const float* __restrict__ beta,
       const float* __restrict__ bcls,
       float* __restrict__ out,
       int NS, int NQ, int npairs, int nparts, int packB,
       int tilesFS1, int tilesXW)
{
    __shared__ __align__(16) char smraw[32768];
    int tx = threadIdx.x;
    int b = blockIdx.x;
    int ngemm = tilesFS1 + tilesXW;

    if (b < nparts) {
        // ================= pool: 32 rows/block, 2 rows/warp =================
        float (*sacc)[CC] = (float (*)[CC])smraw;
        float* sesum = (float*)(smraw + 16 * CC * 4);
        int wp = tx >> 5, lane = tx & 31;
        float w0 = w[lane], w1 = w[lane + 32], w2 = w[lane + 64];
        float w3 = (lane < 16) ? w[lane + 96] : 0.f;
        float p0 = 0.f, p1 = 0.f, p2 = 0.f, p3 = 0.f, es = 0.f;
        int base = b * 32 + wp * 2;
        #pragma unroll
        for (int t = 0; t < 2; t++) {
            int i = base + t;
            if (i < NS) {
                const float* row = F + i * CC;
                float f0 = row[lane];
                float f1 = row[lane + 32];
                float f2 = row[lane + 64];
                float f3 = (lane < 16) ? row[lane + 96] : 0.f;
                float s = f0 * w0 + f1 * w1 + f2 * w2 + f3 * w3;
                #pragma unroll
                for (int o = 16; o; o >>= 1) s += __shfl_xor_sync(0xffffffffu, s, o);
                float e = __expf(s);
                es += e;
                p0 = fmaf(e, f0, p0);
                p1 = fmaf(e, f1, p1);
                p2 = fmaf(e, f2, p2);
                if (lane < 16) p3 = fmaf(e, f3, p3);
            }
        }
        sacc[wp][lane]      = p0;
        sacc[wp][lane + 32] = p1;
        sacc[wp][lane + 64] = p2;
        if (lane < 16) sacc[wp][lane + 96] = p3;
        if (lane == 0) sesum[wp] = es;
        __syncthreads();
        if (tx < CC) {
            float s = 0.f;
            #pragma unroll
            for (int k = 0; k < 16; k++) s += sacc[k][tx];
            g_part[b * CC + tx] = s;
        } else if (tx == CC) {
            float s = 0.f;
            #pragma unroll
            for (int k = 0; k < 16; k++) s += sesum[k];
            g_esum[b] = s;
        }
        __syncthreads();
        if (tx == 0) { __threadfence(); atomicAdd(&g_done[0], 1); }
        return;
    }
    b -= nparts;

    if (b < packB) {
        // ================= pack: pair-packed SoA coords + Wf ================
        int idx = b * BS + tx;
        if (idx < npairs) {
            int i0 = 2 * idx, i1 = 2 * idx + 1;
            float x0 = coords_s[i0 * 3 + 0];
            float y0 = coords_s[i0 * 3 + 1];
            float z0 = coords_s[i0 * 3 + 2];
            float w0 = x0 * x0 + y0 * y0 + z0 * z0;
            float x1 = 0.f, y1 = 0.f, z1 = 0.f, w1 = 1e30f;
            if (i1 < NS) {
                x1 = coords_s[i1 * 3 + 0];
                y1 = coords_s[i1 * 3 + 1];
                z1 = coords_s[i1 * 3 + 2];
                w1 = x1 * x1 + y1 * y1 + z1 * z1;
            }
            g_pkA[idx] = make_float4(x0, x1, y0, y1);
            g_pkB[idx] = make_float4(z0, z1, w0, w1);
        } else {
            int j = idx - npairs;
            if (j < CC * CLSN) {
                int c = j / CLSN, o = j % CLSN;
                float s = 0.f;
                #pragma unroll 8
                for (int k = 0; k < CC; k++)
                    s = fmaf(W2[c * CC + k], Wcls[k * CLSN + o], s);
                g_Wf[j] = s;
            }
        }
        __syncthreads();
        if (tx == 0) { __threadfence(); atomicAdd(&g_done[1], 1); }
        return;
    }
    b -= packB;

    if (b < ngemm) {
        // ================= gemm: 128x112 tile, 4x7 per thread ===============
        bool isXW = (b >= tilesFS1);
        const float* A  = isXW ? Axw : Afs;
        const float* Bm = isXW ? W1 : (W1 + CC * CC);
        int M  = isXW ? NQ : NS;
        int m0 = (isXW ? (b - tilesFS1) : b) * 128;

        float (*As)[136] = (float (*)[136])smraw;
        float (*Bs)[112] = (float (*)[112])(smraw + 15232);
        float* sgate = (float*)(smraw + 27776);
        float* sred  = (float*)(smraw + 28224);

        if (isXW) {
            if (tx == 0) {
                while (atomicAdd(&g_done[0], 0) < nparts) __nanosleep(64);
                __threadfence();
            }
            __syncthreads();
            if (tx < 256) sred[tx] = (tx < nparts) ? g_esum[tx] : 0.f;
            __syncthreads();
            if (tx < 128) sred[tx] += sred[tx + 128];
            __syncthreads();
            if (tx < 64) sred[tx] += sred[tx + 64];
            __syncthreads();
            if (tx < 32) {
                float v = sred[tx] + sred[tx + 32];
                #pragma unroll
                for (int o = 16; o; o >>= 1) v += __shfl_xor_sync(0xffffffffu, v, o);
                sred[tx] = v;
            }
            __syncthreads();
            float inv_es = 1.f / sred[0];
            if (tx < CC) {
                float s = 0.f;
                #pragma unroll 8
                for (int p = 0; p < nparts; p++) s += g_part[p * CC + tx];
                sgate[tx] = 1.f / (1.f + __expf(-s * inv_es));
            }
            __syncthreads();
        }

        float acc[4][7];
        #pragma unroll
        for (int i = 0; i < 4; i++)
            #pragma unroll
            for (int j = 0; j < 7; j++) acc[i][j] = 0.f;
        int rg = (tx >> 4) * 4;
        int cg = (tx & 15) * 7;

        for (int k0 = 0; k0 < CC; k0 += 28) {
            for (int idx = tx; idx < 128 * 7; idx += BS) {
                int r = idx / 7, k4 = idx - r * 7;
                int gr = m0 + r;
                float4 v = (gr < M) ? *(const float4*)&A[gr * CC + k0 + k4 * 4]
                                    : make_float4(0.f, 0.f, 0.f, 0.f);
                As[k4 * 4 + 0][r] = v.x;
                As[k4 * 4 + 1][r] = v.y;
                As[k4 * 4 + 2][r] = v.z;
                As[k4 * 4 + 3][r] = v.w;
            }
            for (int idx = tx; idx < 28 * 28; idx += BS) {
                int k = idx / 28, c4 = idx - k * 28;
                float4 v = *(const float4*)&Bm[(k0 + k) * CC + c4 * 4];
                if (isXW) {
                    float gsc = sgate[k0 + k];
                    v.x *= gsc; v.y *= gsc; v.z *= gsc; v.w *= gsc;
                }
                *(float4*)&Bs[k][c4 * 4] = v;
            }
            __syncthreads();
            #pragma unroll 4
            for (int k = 0; k < 28; k++) {
                float4 av = *(const float4*)&As[k][rg];
                float a[4] = {av.x, av.y, av.z, av.w};
                float bb[7];
                #pragma unroll
                for (int j = 0; j < 7; j++) bb[j] = Bs[k][cg + j];
                #pragma unroll
                for (int i = 0; i < 4; i++)
                    #pragma unroll
                    for (int j = 0; j < 7; j++)
                        acc[i][j] = fmaf(a[i], bb[j], acc[i][j]);
            }
            __syncthreads();
        }

        float* Cout = isXW ? g_XW : g_FS1;
        float cs[7];
        #pragma unroll
        for (int j = 0; j < 7; j++) cs[j] = colscale[cg + j];
        #pragma unroll
        for (int i = 0; i < 4; i++) {
            int gr = m0 + rg + i;
            if (gr < M) {
                #pragma unroll
                for (int j = 0; j < 7; j++)
                    Cout[(size_t)gr * CC + cg + j] = acc[i][j] * cs[j];
            }
        }
        __syncthreads();
        if (tx == 0) { __threadfence(); atomicAdd(&g_done[2], 1); }
        return;
    }
    b -= ngemm;

    // ================= scan (smem-staged) + fused epilogue =================
    {
        int qlocal = tx & 31, part = tx >> 5;
        // smem layout (32KB): chunks 0..16384 | cv 16384 | Wf 22528 | sbeta 31488 | sb 31936
        float4* chA  = (float4*)(smraw + part * 1024);   // 32 float4 (512B)
        float4* chB  = chA + 32;                         // 32 float4 (512B)
        float (*cv)[32][3] = (float (*)[32][3])(smraw + 16384);
        float* Wf    = (float*)(smraw + 22528);
        float* sbeta = (float*)(smraw + 31488);
        float* sb    = (float*)(smraw + 31936);

        // wait for pack (coords + Wf), then preload epilogue constants
        if (tx == 0) {
            while (atomicAdd(&g_done[1], 0) < packB) __nanosleep(64);
            __threadfence();
        }
        __syncthreads();
        for (int i = tx; i < CC * CLSN; i += BS) Wf[i] = g_Wf[i];
        if (tx < CC)   sbeta[tx] = beta[tx];
        if (tx < CLSN) sb[tx] = bcls[tx];

        int q = b * 32 + qlocal;
        bool valid = (q < NQ);
        float nx = 0.f, ny = 0.f, nz = 0.f, q2 = 0.f;
        if (valid) {
            float qx = coords_q[q * 3 + 0];
            float qy = coords_q[q * 3 + 1];
            float qz = coords_q[q * 3 + 2];
            nx = -2.f * qx; ny = -2.f * qy; nz = -2.f * qz;
            q2 = qx * qx + qy * qy + qz * qz;
        }
        unsigned xb = __float_as_uint(nx), yb = __float_as_uint(ny), zb = __float_as_uint(nz);
        unsigned qb = __float_as_uint(q2);
        u64 nxx = (u64)xb | ((u64)xb << 32);
        u64 nyy = (u64)yb | ((u64)yb << 32);
        u64 nzz = (u64)zb | ((u64)zb << 32);
        u64 q22 = (u64)qb | ((u64)qb << 32);

        int per = npairs / PARTS;
        int jb = part * per;
        int je = (part == PARTS - 1) ? npairs : jb + per;

        float b0 = 1e30f, b1 = 1e30f, b2 = 1e30f;

        for (int base = jb; base < je; base += 32) {
            int cnt = min(32, je - base);
            __syncwarp();
            if (qlocal < cnt) {
                chA[qlocal] = g_pkA[base + qlocal];
                chB[qlocal] = g_pkB[base + qlocal];
            }
            __syncwarp();
            int i = 0;
            for (; i + 1 < cnt; i += 2) {
                ulonglong2 a0 = *(const ulonglong2*)&chA[i];
                ulonglong2 c0 = *(const ulonglong2*)&chB[i];
                ulonglong2 a1 = *(const ulonglong2*)&chA[i + 1];
                ulonglong2 c1 = *(const ulonglong2*)&chB[i + 1];
                u64 v0 = fma_f32x2(a0.x, nxx, c0.y);
                u64 v1 = fma_f32x2(a1.x, nxx, c1.y);
                v0 = fma_f32x2(a0.y, nyy, v0);
                v1 = fma_f32x2(a1.y, nyy, v1);
                v0 = fma_f32x2(c0.x, nzz, v0);
                v1 = fma_f32x2(c1.x, nzz, v1);
                v0 = add_f32x2(v0, q22);   // d2 >= 0
                v1 = add_f32x2(v1, q22);
                unsigned base4 = 2u * (unsigned)(base + i);
                ins3b(__uint_as_float(((unsigned)v0 & KEYMASK) | base4),           b0, b1, b2);
                ins3b(__uint_as_float(((unsigned)(v0 >> 32) & KEYMASK) | (base4 + 1)), b0, b1, b2);
                ins3b(__uint_as_float(((unsigned)v1 & KEYMASK) | (base4 + 2)),     b0, b1, b2);
                ins3b(__uint_as_float(((unsigned)(v1 >> 32) & KEYMASK) | (base4 + 3)), b0, b1, b2);
            }
            if (i < cnt) {
                ulonglong2 a0 = *(const ulonglong2*)&chA[i];
                ulonglong2 c0 = *(const ulonglong2*)&chB[i];
                u64 v0 = fma_f32x2(a0.x, nxx, c0.y);
                v0 = fma_f32x2(a0.y, nyy, v0);
                v0 = fma_f32x2(c0.x, nzz, v0);
                v0 = add_f32x2(v0, q22);
                unsigned base4 = 2u * (unsigned)(base + i);
                ins3b(__uint_as_float(((unsigned)v0 & KEYMASK) | base4), b0, b1, b2);
                ins3b(__uint_as_float(((unsigned)(v0 >> 32) & KEYMASK) | (base4 + 1)), b0, b1, b2);
            }
        }

        cv[part][qlocal][0] = b0;
        cv[part][qlocal][1] = b1;
        cv[part][qlocal][2] = b2;
        __syncthreads();

        if (part != 0 || !valid) return;

        b0 = cv[0][qlocal][0];
        b1 = cv[0][qlocal][1];
        b2 = cv[0][qlocal][2];
        #pragma unroll
        for (int p = 1; p < PARTS; p++) {
            ins3b(cv[p][qlocal][0], b0, b1, b2);
            ins3b(cv[p][qlocal][1], b0, b1, b2);
            ins3b(cv[p][qlocal][2], b0, b1, b2);
        }

        int i0 = __float_as_uint(b0) & IDXMASK;
        int i1 = __float_as_uint(b1) & IDXMASK;
        int i2 = __float_as_uint(b2) & IDXMASK;

        // exact d2 recompute for the selected 3 (fp32 precision)
        float d[3];
        int idx3[3] = {i0, i1, i2};
        #pragma unroll
        for (int k = 0; k < 3; k++) {
            int ii = idx3[k], pj = ii >> 1, hi = ii & 1;
            float4 A = g_pkA[pj];
            float4 B = g_pkB[pj];
            float sx = hi ? A.y : A.x;
            float sy = hi ? A.w : A.z;
            float sz = hi ? B.y : B.x;
            float sw = hi ? B.w : B.z;
            d[k] = fmaf(sx, nx, fmaf(sy, ny, fmaf(sz, nz, sw))) + q2;
        }
        float mn = fminf(d[0], fminf(d[1], d[2]));
        float e0 = __expf(mn - d[0]);
        float e1 = __expf(mn - d[1]);
        float e2 = __expf(mn - d[2]);
        float inv = 1.f / (e0 + e1 + e2);
        float w0 = e0 * inv, w1 = e1 * inv, w2 = e2 * inv;

        // wait for gemm outputs (gemm blocks precede scan blocks; no deadlock)
        {
            int lane = tx & 31;
            if (lane == 0) {
                while (atomicAdd(&g_done[2], 0) < ngemm) __nanosleep(64);
                __threadfence();
            }
            __syncwarp();
        }

        const float4* xw = (const float4*)(g_XW + (size_t)q * CC);
        const float4* f0 = (const float4*)(g_FS1 + (size_t)i0 * CC);
        const float4* f1 = (const float4*)(g_FS1 + (size_t)i1 * CC);
        const float4* f2 = (const float4*)(g_FS1 + (size_t)i2 * CC);

        float acc[CLSN];
        #pragma unroll
        for (int o = 0; o < CLSN; o++) acc[o] = sb[o];

        for (int c4 = 0; c4 < CC / 4; c4++) {
            float4 x  = xw[c4];
            float4 a0 = f0[c4];
            float4 a1 = f1[c4];
            float4 a2 = f2[c4];
            int cb = c4 * 4;
            float h[4];
            h[0] = x.x + w0 * a0.x + w1 * a1.x + w2 * a2.x + sbeta[cb + 0];
            h[1] = x.y + w0 * a0.y + w1 * a1.y + w2 * a2.y + sbeta[cb + 1];
            h[2] = x.z + w0 * a0.z + w1 * a1.z + w2 * a2.z + sbeta[cb + 2];
            h[3] = x.w + w0 * a0.w + w1 * a1.w + w2 * a2.w + sbeta[cb + 3];
            #pragma unroll
            for (int u = 0; u < 4; u++) {
                float hv = fmaxf(h[u], 0.f);
                const float* wrow = &Wf[(cb + u) * CLSN];
                #pragma unroll
                for (int o = 0; o < CLSN; o++) acc[o] = fmaf(hv, wrow[o], acc[o]);
            }
        }

        float* op = out + (size_t)q * CLSN;
        #pragma unroll
        for (int o = 0; o < CLSN; o++) op[o] = acc[o];
    }
}

// ---------------- launch ---------------------------------------------------
extern "C" void kernel_launch(void* const* d_in, const int* in_sizes, int n_in,
                              void* d_out, int out_size)
{
    const float* coords_q = (const float*)d_in[0];
    const float* coords_s = (const float*)d_in[1];
    const float* x7       = (const float*)d_in[2];
    const float* feat_s7  = (const float*)d_in[3];
    const float* feat_s   = (const float*)d_in[4];
    const float* w_attn   = (const float*)d_in[5];
    const float* W1       = (const float*)d_in[6];
    const float* gamma    = (const float*)d_in[7];
    const float* beta     = (const float*)d_in[8];
    const float* W2       = (const float*)d_in[9];
    const float* W_cls    = (const float*)d_in[10];
    const float* b_cls    = (const float*)d_in[11];
    float* out = (float*)d_out;

    int NQ = in_sizes[0] / 3;
    int NS = in_sizes[1] / 3;
    int npairs = (NS + 1) / 2;
    int nparts = (NS + 31) / 32;
    if (nparts > NPOOL) nparts = NPOOL;
    int packB    = (npairs + CC * CLSN + BS - 1) / BS;
    int tilesFS1 = (NS + 127) / 128;
    int tilesXW  = (NQ + 127) / 128;
    int scanB    = (NQ + 31) / 32;
    int grid     = nparts + packB + tilesFS1 + tilesXW + scanB;

    int* donep;
    cudaGetSymbolAddress((void**)&donep, g_done);
    cudaMemsetAsync(donep, 0, 3 * sizeof(int));

    k_mega<<<grid, BS>>>(feat_s7, w_attn, coords_s, W2, W_cls,
                         feat_s, x7, W1, gamma, coords_q,
                         beta, b_cls, out,
                         NS, NQ, npairs, nparts, packB, tilesFS1, tilesXW);
}

// round 14
// speedup vs baseline: 3.2471x; 1.2098x over previous
#include <cuda_runtime.h>

#define CC    112
#define CLSN  20
#define NSMAX 8192
#define NQMAX 20000
#define NPOOL 256
#define IDXMASK 0x1FFFu
#define KEYMASK 0xFFFFE000u
#define BS    512
#define GRID  10
#define GRID3 1000
#define CELLH 12.8f
#define INVH  0.078125f

// ---------------- scratch (device globals; no allocation) ----------------
__device__ float  g_part[NPOOL * CC];
__device__ float  g_esum[NPOOL];
__device__ float  g_Wf[CC * CLSN];
__device__ float4 g_s4[NSMAX];          // original order (x,y,z,|s|^2)
__device__ int    g_pcell[NSMAX];
__device__ float4 g_sp4[NSMAX];         // cell-sorted
__device__ int    g_sidx[NSMAX];        // original index, cell-sorted
__device__ int    g_qcell[NQMAX];
__device__ int    g_qorder[NQMAX];      // queries sorted by cell
__device__ int    g_cellstart[GRID3 + 1];
__device__ int    g_qstart[GRID3 + 1];
__device__ int    g_cnts[4096];         // cellcnt | +1024 qcnt | +2048 celloff | +3072 qoff
__device__ int    g_done[4];            // 0=pool 1=prepA 2=prepB
__device__ float  g_FS1[NSMAX * CC];
__device__ float  g_XW[NQMAX * CC];

// ---------------- helpers --------------------------------------------------
__device__ __forceinline__ void ins3b(float v, float& b0, float& b1, float& b2)
{
    float h0 = fmaxf(v, b0);  b0 = fminf(v, b0);
    float h1 = fmaxf(h0, b1); b1 = fminf(h0, b1);
    b2 = fminf(h1, b2);
}
__device__ __forceinline__ int cellof(float x, float y, float z)
{
    int cx = min(GRID - 1, max(0, (int)(x * INVH)));
    int cy = min(GRID - 1, max(0, (int)(y * INVH)));
    int cz = min(GRID - 1, max(0, (int)(z * INVH)));
    return (cz * GRID + cy) * GRID + cx;
}

// ---------------- K1: mega (pool | prepA | prepB | prepC | gemm) -----------
// Wait topology (proven in round 11): prepB<-prepA, prepC<-prepB, gemmXW<-pool.
// All wait targets have strictly lower block IDs. No other waits.
__global__ void __launch_bounds__(BS, 2)
k_mega(const float* __restrict__ F,        // feat_s7
       const float* __restrict__ w,        // w_attn
       const float* __restrict__ coords_s,
       const float* __restrict__ W2,
       const float* __restrict__ Wcls,
       const float* __restrict__ Afs,      // feat_s
       const float* __restrict__ Axw,      // x7
       const float* __restrict__ W1,
       const float* __restrict__ colscale, // gamma
       const float* __restrict__ coords_q,
       int NS, int NQ, int nparts, int ptsB, int qB, int wfB,
       int tilesFS1, int tilesXW)
{
    __shared__ __align__(16) char smraw[29248];
    int tx = threadIdx.x;
    int b = blockIdx.x;
    int prepAB = ptsB + qB + wfB;
    int prepCB = ptsB + qB;

    if (b < nparts) {
        // ================= pool: 32 rows/block, 2 rows/warp =================
        float (*sacc)[CC] = (float (*)[CC])smraw;
        float* sesum = (float*)(smraw + 16 * CC * 4);
        int wp = tx >> 5, lane = tx & 31;
        float w0 = w[lane], w1 = w[lane + 32], w2 = w[lane + 64];
        float w3 = (lane < 16) ? w[lane + 96] : 0.f;
        float p0 = 0.f, p1 = 0.f, p2 = 0.f, p3 = 0.f, es = 0.f;
        int base = b * 32 + wp * 2;
        #pragma unroll
        for (int t = 0; t < 2; t++) {
            int i = base + t;
            if (i < NS) {
                const float* row = F + i * CC;
                float f0 = row[lane];
                float f1 = row[lane + 32];
                float f2 = row[lane + 64];
                float f3 = (lane < 16) ? row[lane + 96] : 0.f;
                float s = f0 * w0 + f1 * w1 + f2 * w2 + f3 * w3;
                #pragma unroll
                for (int o = 16; o; o >>= 1) s += __shfl_xor_sync(0xffffffffu, s, o);
                float e = __expf(s);
                es += e;
                p0 = fmaf(e, f0, p0);
                p1 = fmaf(e, f1, p1);
                p2 = fmaf(e, f2, p2);
                if (lane < 16) p3 = fmaf(e, f3, p3);
            }
        }
        sacc[wp][lane]      = p0;
        sacc[wp][lane + 32] = p1;
        sacc[wp][lane + 64] = p2;
        if (lane < 16) sacc[wp][lane + 96] = p3;
        if (lane == 0) sesum[wp] = es;
        __syncthreads();
        if (tx < CC) {
            float s = 0.f;
            #pragma unroll
            for (int k = 0; k < 16; k++) s += sacc[k][tx];
            g_part[b * CC + tx] = s;
        } else if (tx == CC) {
            float s = 0.f;
            #pragma unroll
            for (int k = 0; k < 16; k++) s += sesum[k];
            g_esum[b] = s;
        }
        __syncthreads();
        if (tx == 0) { __threadfence(); atomicAdd(&g_done[0], 1); }
        return;
    }
    b -= nparts;

    if (b < prepAB) {
        // ===== prepA: point s4+histogram | query cell+histogram | Wf ========
        if (b < ptsB) {
            int i = b * BS + tx;
            if (i < NS) {
                float x = coords_s[i * 3 + 0];
                float y = coords_s[i * 3 + 1];
                float z = coords_s[i * 3 + 2];
                g_s4[i] = make_float4(x, y, z, x * x + y * y + z * z);
                int cell = cellof(x, y, z);
                g_pcell[i] = cell;
                atomicAdd(&g_cnts[cell], 1);
            }
        } else if (b < ptsB + qB) {
            int i = (b - ptsB) * BS + tx;
            if (i < NQ) {
                float x = coords_q[i * 3 + 0];
                float y = coords_q[i * 3 + 1];
                float z = coords_q[i * 3 + 2];
                int cell = cellof(x, y, z);
                g_qcell[i] = cell;
                atomicAdd(&g_cnts[1024 + cell], 1);
            }
        } else {
            int j = (b - ptsB - qB) * BS + tx;
            if (j < CC * CLSN) {
                int c = j / CLSN, o = j % CLSN;
                float s = 0.f;
                #pragma unroll 8
                for (int k = 0; k < CC; k++)
                    s = fmaf(W2[c * CC + k], Wcls[k * CLSN + o], s);
                g_Wf[j] = s;
            }
        }
        __syncthreads();
        if (tx == 0) { __threadfence(); atomicAdd(&g_done[1], 1); }
        return;
    }
    b -= prepAB;

    if (b < 1) {
        // ===== prepB: exclusive prefix sums (points, queries) ===============
        if (tx == 0) {
            while (atomicAdd(&g_done[1], 0) < prepAB) __nanosleep(64);
            __threadfence();
        }
        __syncthreads();
        int* sh = (int*)smraw;
        for (int pass = 0; pass < 2; pass++) {
            int base = pass ? 1024 : 0;
            int* outp = pass ? g_qstart : g_cellstart;
            int e0 = 2 * tx, e1 = 2 * tx + 1;
            int c0 = (e0 < GRID3) ? g_cnts[base + e0] : 0;
            int c1 = (e1 < GRID3) ? g_cnts[base + e1] : 0;
            int local = c0 + c1;
            sh[tx] = local; __syncthreads();
            for (int off = 1; off < 512; off <<= 1) {
                int v = sh[tx];
                int u = (tx >= off) ? sh[tx - off] : 0;
                __syncthreads();
                sh[tx] = v + u;
                __syncthreads();
            }
            int excl = sh[tx] - local;
            if (e0 <= GRID3) outp[e0] = excl;
            if (e1 <= GRID3) outp[e1] = excl + c0;
            __syncthreads();
        }
        if (tx == 0) { __threadfence(); atomicAdd(&g_done[2], 1); }
        return;
    }
    b -= 1;

    if (b < prepCB) {
        // ===== prepC: scatter points | scatter queries ======================
        if (tx == 0) {
            while (atomicAdd(&g_done[2], 0) < 1) __nanosleep(64);
            __threadfence();
        }
        __syncthreads();
        if (b < ptsB) {
            int i = b * BS + tx;
            if (i < NS) {
                int cell = g_pcell[i];
                int pos = g_cellstart[cell] + atomicAdd(&g_cnts[2048 + cell], 1);
                g_sp4[pos] = g_s4[i];
                g_sidx[pos] = i;
            }
        } else {
            int i = (b - ptsB) * BS + tx;
            if (i < NQ) {
                int cell = g_qcell[i];
                int pos = g_qstart[cell] + atomicAdd(&g_cnts[3072 + cell], 1);
                g_qorder[pos] = i;
            }
        }
        return;
    }
    b -= prepCB;

    {
        // ================= gemm: 128x112 tile, 4x7 per thread ===============
        bool isXW = (b >= tilesFS1);
        const float* A  = isXW ? Axw : Afs;
        const float* Bm = isXW ? W1 : (W1 + CC * CC);
        int M  = isXW ? NQ : NS;
        int m0 = (isXW ? (b - tilesFS1) : b) * 128;

        float (*As)[136] = (float (*)[136])smraw;
        float (*Bs)[112] = (float (*)[112])(smraw + 15232);
        float* sgate = (float*)(smraw + 27776);
        float* sred  = (float*)(smraw + 28224);

        if (isXW) {
            if (tx == 0) {
                while (atomicAdd(&g_done[0], 0) < nparts) __nanosleep(64);
                __threadfence();
            }
            __syncthreads();
            if (tx < 256) sred[tx] = (tx < nparts) ? g_esum[tx] : 0.f;
            __syncthreads();
            if (tx < 128) sred[tx] += sred[tx + 128];
            __syncthreads();
            if (tx < 64) sred[tx] += sred[tx + 64];
            __syncthreads();
            if (tx < 32) {
                float v = sred[tx] + sred[tx + 32];
                #pragma unroll
                for (int o = 16; o; o >>= 1) v += __shfl_xor_sync(0xffffffffu, v, o);
                sred[tx] = v;
            }
            __syncthreads();
            float inv_es = 1.f / sred[0];
            if (tx < CC) {
                float s = 0.f;
                #pragma unroll 8
                for (int p = 0; p < nparts; p++) s += g_part[p * CC + tx];
                sgate[tx] = 1.f / (1.f + __expf(-s * inv_es));
            }
            __syncthreads();
        }

        float acc[4][7];
        #pragma unroll
        for (int i = 0; i < 4; i++)
            #pragma unroll
            for (int j = 0; j < 7; j++) acc[i][j] = 0.f;
        int rg = (tx >> 4) * 4;
        int cg = (tx & 15) * 7;

        for (int k0 = 0; k0 < CC; k0 += 28) {
            for (int idx = tx; idx < 128 * 7; idx += BS) {
                int r = idx / 7, k4 = idx - r * 7;
                int gr = m0 + r;
                float4 v = (gr < M) ? *(const float4*)&A[gr * CC + k0 + k4 * 4]
                                    : make_float4(0.f, 0.f, 0.f, 0.f);
                As[k4 * 4 + 0][r] = v.x;
                As[k4 * 4 + 1][r] = v.y;
                As[k4 * 4 + 2][r] = v.z;
                As[k4 * 4 + 3][r] = v.w;
            }
            for (int idx = tx; idx < 28 * 28; idx += BS) {
                int k = idx / 28, c4 = idx - k * 28;
                float4 v = *(const float4*)&Bm[(k0 + k) * CC + c4 * 4];
                if (isXW) {
                    float gsc = sgate[k0 + k];
                    v.x *= gsc; v.y *= gsc; v.z *= gsc; v.w *= gsc;
                }
                *(float4*)&Bs[k][c4 * 4] = v;
            }
            __syncthreads();
            #pragma unroll 4
            for (int k = 0; k < 28; k++) {
                float4 av = *(const float4*)&As[k][rg];
                float a[4] = {av.x, av.y, av.z, av.w};
                float bb[7];
                #pragma unroll
                for (int j = 0; j < 7; j++) bb[j] = Bs[k][cg + j];
                #pragma unroll
                for (int i = 0; i < 4; i++)
                    #pragma unroll
                    for (int j = 0; j < 7; j++)
                        acc[i][j] = fmaf(a[i], bb[j], acc[i][j]);
            }
            __syncthreads();
        }

        float* Cout = isXW ? g_XW : g_FS1;
        float cs[7];
        #pragma unroll
        for (int j = 0; j < 7; j++) cs[j] = colscale[cg + j];
        #pragma unroll
        for (int i = 0; i < 4; i++) {
            int gr = m0 + rg + i;
            if (gr < M) {
                #pragma unroll
                for (int j = 0; j < 7; j++)
                    Cout[(size_t)gr * CC + cg + j] = acc[i][j] * cs[j];
            }
        }
    }
}

// ---------------- K2: grid kNN scan + epilogue (no waits at all) -----------
__global__ void __launch_bounds__(BS)
k_scan(const float* __restrict__ coords_q,
       const float* __restrict__ beta,
       const float* __restrict__ bcls,
       float* __restrict__ out,
       int NQ, int NS)
{
    __shared__ float Wf[CC * CLSN];
    __shared__ float sbeta[CC];
    __shared__ float sb[CLSN];
    __shared__ int   scs[GRID3 + 1];
    int tx = threadIdx.x;
    int lane = tx & 31, wp = tx >> 5;

    for (int i = tx; i < CC * CLSN; i += BS) Wf[i] = g_Wf[i];
    if (tx < CC)   sbeta[tx] = beta[tx];
    if (tx < CLSN) sb[tx] = bcls[tx];
    for (int i = tx; i <= GRID3; i += BS) scs[i] = g_cellstart[i];
    __syncthreads();

    int wq = blockIdx.x * BS + wp * 32 + lane;
    bool valid = (wq < NQ);
    int q = valid ? g_qorder[wq] : 0;
    float qx = coords_q[q * 3 + 0];
    float qy = coords_q[q * 3 + 1];
    float qz = coords_q[q * 3 + 2];
    float nx = -2.f * qx, ny = -2.f * qy, nz = -2.f * qz;
    float q2 = qx * qx + qy * qy + qz * qz;
    int cx = min(GRID - 1, max(0, (int)(qx * INVH)));
    int cy = min(GRID - 1, max(0, (int)(qy * INVH)));
    int cz = min(GRID - 1, max(0, (int)(qz * INVH)));

    float b0 = 1e30f, b1 = 1e30f, b2 = 1e30f;

    // ring D <= 1 (27 cells; queries are cell-sorted so warps stay coherent)
    for (int dz = -1; dz <= 1; dz++)
    for (int dy = -1; dy <= 1; dy++)
    for (int dx = -1; dx <= 1; dx++) {
        int ux = cx + dx, uy = cy + dy, uz = cz + dz;
        bool ok = (ux >= 0) & (ux < GRID) & (uy >= 0) & (uy < GRID)
                & (uz >= 0) & (uz < GRID);
        int cell = (uz * GRID + uy) * GRID + ux;
        int p  = ok ? scs[cell] : 0;
        int pe = ok ? scs[cell + 1] : 0;
        for (; p < pe; p++) {
            float4 s = __ldg(&g_sp4[p]);
            int   si = __ldg(&g_sidx[p]);
            float v = fmaf(s.x, nx, fmaf(s.y, ny, fmaf(s.z, nz, s.w))) + q2;
            v = fmaxf(v, 0.f);
            float key = __uint_as_float((__float_as_uint(v) & KEYMASK) | (unsigned)si);
            ins3b(key, b0, b1, b2);
        }
    }
    // ring D == 2 (rare: only when 3rd-NN might exceed one cell width)
    float thr1 = CELLH * CELLH - 1.0f;
    if (__any_sync(0xffffffffu, b2 > thr1)) {
        for (int dz = -2; dz <= 2; dz++)
        for (int dy = -2; dy <= 2; dy++)
        for (int dx = -2; dx <= 2; dx++) {
            if (max(abs(dz), max(abs(dy), abs(dx))) != 2) continue;
            int ux = cx + dx, uy = cy + dy, uz = cz + dz;
            bool ok = (ux >= 0) & (ux < GRID) & (uy >= 0) & (uy < GRID)
                    & (uz >= 0) & (uz < GRID);
            int cell = (uz * GRID + uy) * GRID + ux;
            int p  = ok ? scs[cell] : 0;
            int pe = ok ? scs[cell + 1] : 0;
            for (; p < pe; p++) {
                float4 s = __ldg(&g_sp4[p]);
                int   si = __ldg(&g_sidx[p]);
                float v = fmaf(s.x, nx, fmaf(s.y, ny, fmaf(s.z, nz, s.w))) + q2;
                v = fmaxf(v, 0.f);
                float key = __uint_as_float((__float_as_uint(v) & KEYMASK) | (unsigned)si);
                ins3b(key, b0, b1, b2);
            }
        }
        // full fallback, skipping cells at chebyshev<=2 (essentially never)
        float thr2 = 4.f * CELLH * CELLH - 1.0f;
        if (__any_sync(0xffffffffu, b2 > thr2)) {
            for (int p = 0; p < NS; p++) {
                float4 s = g_sp4[p];
                int pcx = min(GRID - 1, max(0, (int)(s.x * INVH)));
                int pcy = min(GRID - 1, max(0, (int)(s.y * INVH)));
                int pcz = min(GRID - 1, max(0, (int)(s.z * INVH)));
                int ch = max(abs(pcx - cx), max(abs(pcy - cy), abs(pcz - cz)));
                float v = fmaf(s.x, nx, fmaf(s.y, ny, fmaf(s.z, nz, s.w))) + q2;
                v = fmaxf(v, 0.f);
                float key = __uint_as_float((__float_as_uint(v) & KEYMASK) | (unsigned)g_sidx[p]);
                if (ch <= 2) key = 1e30f;   // already counted; idempotent sentinel
                ins3b(key, b0, b1, b2);
            }
        }
    }

    if (!valid) return;

    int i0 = __float_as_uint(b0) & IDXMASK;
    int i1 = __float_as_uint(b1) & IDXMASK;
    int i2 = __float_as_uint(b2) & IDXMASK;

    // exact d2 recompute (fp32) for the selected 3
    float d[3];
    int idx3[3] = {i0, i1, i2};
    #pragma unroll
    for (int k = 0; k < 3; k++) {
        float4 s = g_s4[idx3[k]];
        d[k] = fmaf(s.x, nx, fmaf(s.y, ny, fmaf(s.z, nz, s.w))) + q2;
    }
    float mn = fminf(d[0], fminf(d[1], d[2]));
    float e0 = __expf(mn - d[0]);
    float e1 = __expf(mn - d[1]);
    float e2 = __expf(mn - d[2]);
    float inv = 1.f / (e0 + e1 + e2);
    float w0 = e0 * inv, w1 = e1 * inv, w2 = e2 * inv;

    const float4* xw = (const float4*)(g_XW + (size_t)q * CC);
    const float4* f0 = (const float4*)(g_FS1 + (size_t)i0 * CC);
    const float4* f1 = (const float4*)(g_FS1 + (size_t)i1 * CC);
    const float4* f2 = (const float4*)(g_FS1 + (size_t)i2 * CC);

    float acc[CLSN];
    #pragma unroll
    for (int o = 0; o < CLSN; o++) acc[o] = sb[o];

    for (int c4 = 0; c4 < CC / 4; c4++) {
        float4 x  = xw[c4];
        float4 a0 = f0[c4];
        float4 a1 = f1[c4];
        float4 a2 = f2[c4];
        int cb = c4 * 4;
        float h[4];
        h[0] = x.x + w0 * a0.x + w1 * a1.x + w2 * a2.x + sbeta[cb + 0];
        h[1] = x.y + w0 * a0.y + w1 * a1.y + w2 * a2.y + sbeta[cb + 1];
        h[2] = x.z + w0 * a0.z + w1 * a1.z + w2 * a2.z + sbeta[cb + 2];
        h[3] = x.w + w0 * a0.w + w1 * a1.w + w2 * a2.w + sbeta[cb + 3];
        #pragma unroll
        for (int u = 0; u < 4; u++) {
            float hv = fmaxf(h[u], 0.f);
            const float* wrow = &Wf[(cb + u) * CLSN];
            #pragma unroll
            for (int o = 0; o < CLSN; o++) acc[o] = fmaf(hv, wrow[o], acc[o]);
        }
    }

    float* op = out + (size_t)q * CLSN;
    #pragma unroll
    for (int o = 0; o < CLSN; o++) op[o] = acc[o];
}

// ---------------- launch ---------------------------------------------------
extern "C" void kernel_launch(void* const* d_in, const int* in_sizes, int n_in,
                              void* d_out, int out_size)
{
    const float* coords_q = (const float*)d_in[0];
    const float* coords_s = (const float*)d_in[1];
    const float* x7       = (const float*)d_in[2];
    const float* feat_s7  = (const float*)d_in[3];
    const float* feat_s   = (const float*)d_in[4];
    const float* w_attn   = (const float*)d_in[5];
    const float* W1       = (const float*)d_in[6];
    const float* gamma    = (const float*)d_in[7];
    const float* beta     = (const float*)d_in[8];
    const float* W2       = (const float*)d_in[9];
    const float* W_cls    = (const float*)d_in[10];
    const float* b_cls    = (const float*)d_in[11];
    float* out = (float*)d_out;

    int NQ = in_sizes[0] / 3;
    int NS = in_sizes[1] / 3;
    int nparts = (NS + 31) / 32;
    if (nparts > NPOOL) nparts = NPOOL;
    int ptsB = (NS + BS - 1) / BS;
    int qB   = (NQ + BS - 1) / BS;
    int wfB  = (CC * CLSN + BS - 1) / BS;
    int tilesFS1 = (NS + 127) / 128;
    int tilesXW  = (NQ + 127) / 128;
    int grid1 = nparts + (ptsB + qB + wfB) + 1 + (ptsB + qB)
              + (tilesFS1 + tilesXW);
    int grid2 = (NQ + BS - 1) / BS;

    int* cntsp; cudaGetSymbolAddress((void**)&cntsp, g_cnts);
    int* donep; cudaGetSymbolAddress((void**)&donep, g_done);
    cudaMemsetAsync(cntsp, 0, 4096 * sizeof(int));
    cudaMemsetAsync(donep, 0, 4 * sizeof(int));

    k_mega<<<grid1, BS>>>(feat_s7, w_attn, coords_s, W2, W_cls,
                          feat_s, x7, W1, gamma, coords_q,
                          NS, NQ, nparts, ptsB, qB, wfB,
                          tilesFS1, tilesXW);
    k_scan<<<grid2, BS>>>(coords_q, beta, b_cls, out, NQ, NS);
}

// round 15
// speedup vs baseline: 3.7997x; 1.1702x over previous
#include <cuda_runtime.h>

#define CC    112
#define CLSN  20
#define NSMAX 8192
#define NQMAX 20000
#define NPOOL 256
#define IDXMASK 0x1FFFu
#define KEYMASK 0xFFFFE000u
#define BS    512
#define SBS   128
#define GRID  10
#define GRID3 1000
#define CELLH 12.8f
#define INVH  0.078125f

// ---------------- scratch (device globals; no allocation) ----------------
__device__ float  g_part[NPOOL * CC];
__device__ float  g_esum[NPOOL];
__device__ float  g_Wf[CC * CLSN];
__device__ float4 g_s4[NSMAX];          // original order (x,y,z,|s|^2)
__device__ int    g_pcell[NSMAX];
__device__ float4 g_sp4[NSMAX];         // cell-sorted
__device__ int    g_sidx[NSMAX];        // original index, cell-sorted
__device__ int    g_qcell[NQMAX];
__device__ int    g_qorder[NQMAX];      // queries sorted by cell
__device__ int    g_cellstart[GRID3 + 1];
__device__ int    g_qstart[GRID3 + 1];
__device__ int    g_cnts[4096];         // cellcnt | +1024 qcnt | +2048 celloff | +3072 qoff
__device__ int    g_done[4];            // 0=pool 1=prepA 2=prepB
__device__ float  g_FS1[NSMAX * CC];
__device__ float  g_XW[NQMAX * CC];

// ---------------- helpers --------------------------------------------------
__device__ __forceinline__ void ins3b(float v, float& b0, float& b1, float& b2)
{
    float h0 = fmaxf(v, b0);  b0 = fminf(v, b0);
    float h1 = fmaxf(h0, b1); b1 = fminf(h0, b1);
    b2 = fminf(h1, b2);
}
__device__ __forceinline__ int cellof(float x, float y, float z)
{
    int cx = min(GRID - 1, max(0, (int)(x * INVH)));
    int cy = min(GRID - 1, max(0, (int)(y * INVH)));
    int cz = min(GRID - 1, max(0, (int)(z * INVH)));
    return (cz * GRID + cy) * GRID + cx;
}

// ---------------- K1: mega (pool | prepA | prepB | prepC | gemm) -----------
// Wait topology (proven): prepB<-prepA, prepC<-prepB, gemmXW<-pool.
__global__ void __launch_bounds__(BS, 2)
k_mega(const float* __restrict__ F,        // feat_s7
       const float* __restrict__ w,        // w_attn
       const float* __restrict__ coords_s,
       const float* __restrict__ W2,
       const float* __restrict__ Wcls,
       const float* __restrict__ Afs,      // feat_s
       const float* __restrict__ Axw,      // x7
       const float* __restrict__ W1,
       const float* __restrict__ colscale, // gamma
       const float* __restrict__ coords_q,
       int NS, int NQ, int nparts, int ptsB, int qB, int wfB,
       int tilesFS1, int tilesXW)
{
    __shared__ __align__(16) char smraw[29248];
    int tx = threadIdx.x;
    int b = blockIdx.x;
    int prepAB = ptsB + qB + wfB;
    int prepCB = ptsB + qB;

    if (b < nparts) {
        // ================= pool: 32 rows/block, 2 rows/warp =================
        float (*sacc)[CC] = (float (*)[CC])smraw;
        float* sesum = (float*)(smraw + 16 * CC * 4);
        int wp = tx >> 5, lane = tx & 31;
        float w0 = w[lane], w1 = w[lane + 32], w2 = w[lane + 64];
        float w3 = (lane < 16) ? w[lane + 96] : 0.f;
        float p0 = 0.f, p1 = 0.f, p2 = 0.f, p3 = 0.f, es = 0.f;
        int base = b * 32 + wp * 2;
        #pragma unroll
        for (int t = 0; t < 2; t++) {
            int i = base + t;
            if (i < NS) {
                const float* row = F + i * CC;
                float f0 = row[lane];
                float f1 = row[lane + 32];
                float f2 = row[lane + 64];
                float f3 = (lane < 16) ? row[lane + 96] : 0.f;
                float s = f0 * w0 + f1 * w1 + f2 * w2 + f3 * w3;
                #pragma unroll
                for (int o = 16; o; o >>= 1) s += __shfl_xor_sync(0xffffffffu, s, o);
                float e = __expf(s);
                es += e;
                p0 = fmaf(e, f0, p0);
                p1 = fmaf(e, f1, p1);
                p2 = fmaf(e, f2, p2);
                if (lane < 16) p3 = fmaf(e, f3, p3);
            }
        }
        sacc[wp][lane]      = p0;
        sacc[wp][lane + 32] = p1;
        sacc[wp][lane + 64] = p2;
        if (lane < 16) sacc[wp][lane + 96] = p3;
        if (lane == 0) sesum[wp] = es;
        __syncthreads();
        if (tx < CC) {
            float s = 0.f;
            #pragma unroll
            for (int k = 0; k < 16; k++) s += sacc[k][tx];
            g_part[b * CC + tx] = s;
        } else if (tx == CC) {
            float s = 0.f;
            #pragma unroll
            for (int k = 0; k < 16; k++) s += sesum[k];
            g_esum[b] = s;
        }
        __syncthreads();
        if (tx == 0) { __threadfence(); atomicAdd(&g_done[0], 1); }
        return;
    }
    b -= nparts;

    if (b < prepAB) {
        // ===== prepA: point s4+histogram | query cell+histogram | Wf ========
        if (b < ptsB) {
            int i = b * BS + tx;
            if (i < NS) {
                float x = coords_s[i * 3 + 0];
                float y = coords_s[i * 3 + 1];
                float z = coords_s[i * 3 + 2];
                g_s4[i] = make_float4(x, y, z, x * x + y * y + z * z);
                int cell = cellof(x, y, z);
                g_pcell[i] = cell;
                atomicAdd(&g_cnts[cell], 1);
            }
        } else if (b < ptsB + qB) {
            int i = (b - ptsB) * BS + tx;
            if (i < NQ) {
                float x = coords_q[i * 3 + 0];
                float y = coords_q[i * 3 + 1];
                float z = coords_q[i * 3 + 2];
                int cell = cellof(x, y, z);
                g_qcell[i] = cell;
                atomicAdd(&g_cnts[1024 + cell], 1);
            }
        } else {
            int j = (b - ptsB - qB) * BS + tx;
            if (j < CC * CLSN) {
                int c = j / CLSN, o = j % CLSN;
                float s = 0.f;
                #pragma unroll 8
                for (int k = 0; k < CC; k++)
                    s = fmaf(W2[c * CC + k], Wcls[k * CLSN + o], s);
                g_Wf[j] = s;
            }
        }
        __syncthreads();
        if (tx == 0) { __threadfence(); atomicAdd(&g_done[1], 1); }
        return;
    }
    b -= prepAB;

    if (b < 1) {
        // ===== prepB: exclusive prefix sums (points, queries) ===============
        if (tx == 0) {
            while (atomicAdd(&g_done[1], 0) < prepAB) __nanosleep(64);
            __threadfence();
        }
        __syncthreads();
        int* sh = (int*)smraw;
        for (int pass = 0; pass < 2; pass++) {
            int base = pass ? 1024 : 0;
            int* outp = pass ? g_qstart : g_cellstart;
            int e0 = 2 * tx, e1 = 2 * tx + 1;
            int c0 = (e0 < GRID3) ? g_cnts[base + e0] : 0;
            int c1 = (e1 < GRID3) ? g_cnts[base + e1] : 0;
            int local = c0 + c1;
            sh[tx] = local; __syncthreads();
            for (int off = 1; off < 512; off <<= 1) {
                int v = sh[tx];
                int u = (tx >= off) ? sh[tx - off] : 0;
                __syncthreads();
                sh[tx] = v + u;
                __syncthreads();
            }
            int excl = sh[tx] - local;
            if (e0 <= GRID3) outp[e0] = excl;
            if (e1 <= GRID3) outp[e1] = excl + c0;
            __syncthreads();
        }
        if (tx == 0) { __threadfence(); atomicAdd(&g_done[2], 1); }
        return;
    }
    b -= 1;

    if (b < prepCB) {
        // ===== prepC: scatter points | scatter queries ======================
        if (tx == 0) {
            while (atomicAdd(&g_done[2], 0) < 1) __nanosleep(64);
            __threadfence();
        }
        __syncthreads();
        if (b < ptsB) {
            int i = b * BS + tx;
            if (i < NS) {
                int cell = g_pcell[i];
                int pos = g_cellstart[cell] + atomicAdd(&g_cnts[2048 + cell], 1);
                g_sp4[pos] = g_s4[i];
                g_sidx[pos] = i;
            }
        } else {
            int i = (b - ptsB) * BS + tx;
            if (i < NQ) {
                int cell = g_qcell[i];
                int pos = g_qstart[cell] + atomicAdd(&g_cnts[3072 + cell], 1);
                g_qorder[pos] = i;
            }
        }
        return;
    }
    b -= prepCB;

    {
        // ================= gemm: 128x112 tile, 4x7 per thread ===============
        bool isXW = (b >= tilesFS1);
        const float* A  = isXW ? Axw : Afs;
        const float* Bm = isXW ? W1 : (W1 + CC * CC);
        int M  = isXW ? NQ : NS;
        int m0 = (isXW ? (b - tilesFS1) : b) * 128;

        float (*As)[136] = (float (*)[136])smraw;
        float (*Bs)[112] = (float (*)[112])(smraw + 15232);
        float* sgate = (float*)(smraw + 27776);
        float* sred  = (float*)(smraw + 28224);

        if (isXW) {
            if (tx == 0) {
                while (atomicAdd(&g_done[0], 0) < nparts) __nanosleep(64);
                __threadfence();
            }
            __syncthreads();
            if (tx < 256) sred[tx] = (tx < nparts) ? g_esum[tx] : 0.f;
            __syncthreads();
            if (tx < 128) sred[tx] += sred[tx + 128];
            __syncthreads();
            if (tx < 64) sred[tx] += sred[tx + 64];
            __syncthreads();
            if (tx < 32) {
                float v = sred[tx] + sred[tx + 32];
                #pragma unroll
                for (int o = 16; o; o >>= 1) v += __shfl_xor_sync(0xffffffffu, v, o);
                sred[tx] = v;
            }
            __syncthreads();
            float inv_es = 1.f / sred[0];
            if (tx < CC) {
                float s = 0.f;
                #pragma unroll 8
                for (int p = 0; p < nparts; p++) s += g_part[p * CC + tx];
                sgate[tx] = 1.f / (1.f + __expf(-s * inv_es));
            }
            __syncthreads();
        }

        float acc[4][7];
        #pragma unroll
        for (int i = 0; i < 4; i++)
            #pragma unroll
            for (int j = 0; j < 7; j++) acc[i][j] = 0.f;
        int rg = (tx >> 4) * 4;
        int cg = (tx & 15) * 7;

        for (int k0 = 0; k0 < CC; k0 += 28) {
            for (int idx = tx; idx < 128 * 7; idx += BS) {
                int r = idx / 7, k4 = idx - r * 7;
                int gr = m0 + r;
                float4 v = (gr < M) ? *(const float4*)&A[gr * CC + k0 + k4 * 4]
                                    : make_float4(0.f, 0.f, 0.f, 0.f);
                As[k4 * 4 + 0][r] = v.x;
                As[k4 * 4 + 1][r] = v.y;
                As[k4 * 4 + 2][r] = v.z;
                As[k4 * 4 + 3][r] = v.w;
            }
            for (int idx = tx; idx < 28 * 28; idx += BS) {
                int k = idx / 28, c4 = idx - k * 28;
                float4 v = *(const float4*)&Bm[(k0 + k) * CC + c4 * 4];
                if (isXW) {
                    float gsc = sgate[k0 + k];
                    v.x *= gsc; v.y *= gsc; v.z *= gsc; v.w *= gsc;
                }
                *(float4*)&Bs[k][c4 * 4] = v;
            }
            __syncthreads();
            #pragma unroll 4
            for (int k = 0; k < 28; k++) {
                float4 av = *(const float4*)&As[k][rg];
                float a[4] = {av.x, av.y, av.z, av.w};
                float bb[7];
                #pragma unroll
                for (int j = 0; j < 7; j++) bb[j] = Bs[k][cg + j];
                #pragma unroll
                for (int i = 0; i < 4; i++)
                    #pragma unroll
                    for (int j = 0; j < 7; j++)
                        acc[i][j] = fmaf(a[i], bb[j], acc[i][j]);
            }
            __syncthreads();
        }

        float* Cout = isXW ? g_XW : g_FS1;
        float cs[7];
        #pragma unroll
        for (int j = 0; j < 7; j++) cs[j] = colscale[cg + j];
        #pragma unroll
        for (int i = 0; i < 4; i++) {
            int gr = m0 + rg + i;
            if (gr < M) {
                #pragma unroll
                for (int j = 0; j < 7; j++)
                    Cout[(size_t)gr * CC + cg + j] = acc[i][j] * cs[j];
            }
        }
    }
}

// ---------------- K2: grid kNN scan + epilogue (128-thread blocks) ---------
__global__ void k_scan(const float* __restrict__ coords_q,
                       const float* __restrict__ beta,
                       const float* __restrict__ bcls,
                       float* __restrict__ out,
                       int NQ, int NS)
{
    __shared__ float Wf[CC * CLSN];
    __shared__ float sbeta[CC];
    __shared__ float sb[CLSN];
    __shared__ int   scs[GRID3 + 1];
    int tx = threadIdx.x;

    for (int i = tx; i < CC * CLSN; i += SBS) Wf[i] = g_Wf[i];
    if (tx < CC)   sbeta[tx] = beta[tx];
    if (tx < CLSN) sb[tx] = bcls[tx];
    for (int i = tx; i <= GRID3; i += SBS) scs[i] = g_cellstart[i];
    __syncthreads();

    int wq = blockIdx.x * SBS + tx;
    bool valid = (wq < NQ);
    int q = valid ? g_qorder[wq] : 0;
    float qx = coords_q[q * 3 + 0];
    float qy = coords_q[q * 3 + 1];
    float qz = coords_q[q * 3 + 2];
    float nx = -2.f * qx, ny = -2.f * qy, nz = -2.f * qz;
    float q2 = qx * qx + qy * qy + qz * qz;
    int cx = min(GRID - 1, max(0, (int)(qx * INVH)));
    int cy = min(GRID - 1, max(0, (int)(qy * INVH)));
    int cz = min(GRID - 1, max(0, (int)(qz * INVH)));

    float b0 = 1e30f, b1 = 1e30f, b2 = 1e30f;

    // ring D <= 1 (27 cells; queries are cell-sorted so warps stay coherent)
    for (int dz = -1; dz <= 1; dz++)
    for (int dy = -1; dy <= 1; dy++)
    for (int dx = -1; dx <= 1; dx++) {
        int ux = cx + dx, uy = cy + dy, uz = cz + dz;
        bool ok = (ux >= 0) & (ux < GRID) & (uy >= 0) & (uy < GRID)
                & (uz >= 0) & (uz < GRID);
        int cell = (uz * GRID + uy) * GRID + ux;
        int p  = ok ? scs[cell] : 0;
        int pe = ok ? scs[cell + 1] : 0;
        for (; p < pe; p++) {
            float4 s = __ldg(&g_sp4[p]);
            int   si = __ldg(&g_sidx[p]);
            float v = fmaf(s.x, nx, fmaf(s.y, ny, fmaf(s.z, nz, s.w))) + q2;
            v = fmaxf(v, 0.f);
            float key = __uint_as_float((__float_as_uint(v) & KEYMASK) | (unsigned)si);
            ins3b(key, b0, b1, b2);
        }
    }
    // ring D == 2 (rare: only when 3rd-NN might exceed one cell width)
    float thr1 = CELLH * CELLH - 1.0f;
    if (__any_sync(0xffffffffu, b2 > thr1)) {
        for (int dz = -2; dz <= 2; dz++)
        for (int dy = -2; dy <= 2; dy++)
        for (int dx = -2; dx <= 2; dx++) {
            if (max(abs(dz), max(abs(dy), abs(dx))) != 2) continue;
            int ux = cx + dx, uy = cy + dy, uz = cz + dz;
            bool ok = (ux >= 0) & (ux < GRID) & (uy >= 0) & (uy < GRID)
                    & (uz >= 0) & (uz < GRID);
            int cell = (uz * GRID + uy) * GRID + ux;
            int p  = ok ? scs[cell] : 0;
            int pe = ok ? scs[cell + 1] : 0;
            for (; p < pe; p++) {
                float4 s = __ldg(&g_sp4[p]);
                int   si = __ldg(&g_sidx[p]);
                float v = fmaf(s.x, nx, fmaf(s.y, ny, fmaf(s.z, nz, s.w))) + q2;
                v = fmaxf(v, 0.f);
                float key = __uint_as_float((__float_as_uint(v) & KEYMASK) | (unsigned)si);
                ins3b(key, b0, b1, b2);
            }
        }
        // full fallback, skipping cells at chebyshev<=2 (essentially never)
        float thr2 = 4.f * CELLH * CELLH - 1.0f;
        if (__any_sync(0xffffffffu, b2 > thr2)) {
            for (int p = 0; p < NS; p++) {
                float4 s = g_sp4[p];
                int pcx = min(GRID - 1, max(0, (int)(s.x * INVH)));
                int pcy = min(GRID - 1, max(0, (int)(s.y * INVH)));
                int pcz = min(GRID - 1, max(0, (int)(s.z * INVH)));
                int ch = max(abs(pcx - cx), max(abs(pcy - cy), abs(pcz - cz)));
                float v = fmaf(s.x, nx, fmaf(s.y, ny, fmaf(s.z, nz, s.w))) + q2;
                v = fmaxf(v, 0.f);
                float key = __uint_as_float((__float_as_uint(v) & KEYMASK) | (unsigned)g_sidx[p]);
                if (ch <= 2) key = 1e30f;   // already counted; idempotent sentinel
                ins3b(key, b0, b1, b2);
            }
        }
    }

    if (!valid) return;

    int i0 = __float_as_uint(b0) & IDXMASK;
    int i1 = __float_as_uint(b1) & IDXMASK;
    int i2 = __float_as_uint(b2) & IDXMASK;

    // exact d2 recompute (fp32) for the selected 3
    float d[3];
    int idx3[3] = {i0, i1, i2};
    #pragma unroll
    for (int k = 0; k < 3; k++) {
        float4 s = g_s4[idx3[k]];
        d[k] = fmaf(s.x, nx, fmaf(s.y, ny, fmaf(s.z, nz, s.w))) + q2;
    }
    float mn = fminf(d[0], fminf(d[1], d[2]));
    float e0 = __expf(mn - d[0]);
    float e1 = __expf(mn - d[1]);
    float e2 = __expf(mn - d[2]);
    float inv = 1.f / (e0 + e1 + e2);
    float w0 = e0 * inv, w1 = e1 * inv, w2 = e2 * inv;

    const float4* xw = (const float4*)(g_XW + (size_t)q * CC);
    const float4* f0 = (const float4*)(g_FS1 + (size_t)i0 * CC);
    const float4* f1 = (const float4*)(g_FS1 + (size_t)i1 * CC);
    const float4* f2 = (const float4*)(g_FS1 + (size_t)i2 * CC);

    float acc[CLSN];
    #pragma unroll
    for (int o = 0; o < CLSN; o++) acc[o] = sb[o];

    for (int c4 = 0; c4 < CC / 4; c4++) {
        float4 x  = xw[c4];
        float4 a0 = f0[c4];
        float4 a1 = f1[c4];
        float4 a2 = f2[c4];
        int cb = c4 * 4;
        float h[4];
        h[0] = x.x + w0 * a0.x + w1 * a1.x + w2 * a2.x + sbeta[cb + 0];
        h[1] = x.y + w0 * a0.y + w1 * a1.y + w2 * a2.y + sbeta[cb + 1];
        h[2] = x.z + w0 * a0.z + w1 * a1.z + w2 * a2.z + sbeta[cb + 2];
        h[3] = x.w + w0 * a0.w + w1 * a1.w + w2 * a2.w + sbeta[cb + 3];
        #pragma unroll
        for (int u = 0; u < 4; u++) {
            float hv = fmaxf(h[u], 0.f);
            const float* wrow = &Wf[(cb + u) * CLSN];
            #pragma unroll
            for (int o = 0; o < CLSN; o++) acc[o] = fmaf(hv, wrow[o], acc[o]);
        }
    }

    float* op = out + (size_t)q * CLSN;
    #pragma unroll
    for (int o = 0; o < CLSN; o++) op[o] = acc[o];
}

// ---------------- launch ---------------------------------------------------
extern "C" void kernel_launch(void* const* d_in, const int* in_sizes, int n_in,
                              void* d_out, int out_size)
{
    const float* coords_q = (const float*)d_in[0];
    const float* coords_s = (const float*)d_in[1];
    const float* x7       = (const float*)d_in[2];
    const float* feat_s7  = (const float*)d_in[3];
    const float* feat_s   = (const float*)d_in[4];
    const float* w_attn   = (const float*)d_in[5];
    const float* W1       = (const float*)d_in[6];
    const float* gamma    = (const float*)d_in[7];
    const float* beta     = (const float*)d_in[8];
    const float* W2       = (const float*)d_in[9];
    const float* W_cls    = (const float*)d_in[10];
    const float* b_cls    = (const float*)d_in[11];
    float* out = (float*)d_out;

    int NQ = in_sizes[0] / 3;
    int NS = in_sizes[1] / 3;
    int nparts = (NS + 31) / 32;
    if (nparts > NPOOL) nparts = NPOOL;
    int ptsB = (NS + BS - 1) / BS;
    int qB   = (NQ + BS - 1) / BS;
    int wfB  = (CC * CLSN + BS - 1) / BS;
    int tilesFS1 = (NS + 127) / 128;
    int tilesXW  = (NQ + 127) / 128;
    int grid1 = nparts + (ptsB + qB + wfB) + 1 + (ptsB + qB)
              + (tilesFS1 + tilesXW);
    int grid2 = (NQ + SBS - 1) / SBS;

    int* cntsp; cudaGetSymbolAddress((void**)&cntsp, g_cnts);
    int* donep; cudaGetSymbolAddress((void**)&donep, g_done);
    cudaMemsetAsync(cntsp, 0, 4096 * sizeof(int));
    cudaMemsetAsync(donep, 0, 4 * sizeof(int));

    k_mega<<<grid1, BS>>>(feat_s7, w_attn, coords_s, W2, W_cls,
                          feat_s, x7, W1, gamma, coords_q,
                          NS, NQ, nparts, ptsB, qB, wfB,
                          tilesFS1, tilesXW);
    k_scan<<<grid2, SBS>>>(coords_q, beta, b_cls, out, NQ, NS);
}

// round 16
// speedup vs baseline: 4.0544x; 1.0670x over previous
#include <cuda_runtime.h>

#define CC    112
#define CLSN  20
#define NSMAX 8192
#define NQMAX 20000
#define NPOOL 256
#define IDXMASK 0x1FFFu
#define KEYMASK 0xFFFFE000u
#define BS    512
#define SBS   128
#define GRID  10
#define GRID3 1000
#define CELLH 12.8f
#define INVH  0.078125f

// ---------------- scratch (device globals; no allocation) ----------------
__device__ float  g_part[NPOOL * CC];
__device__ float  g_esum[NPOOL];
__device__ float  g_Wf[CC * CLSN];
__device__ float4 g_s4[NSMAX];          // original order (x,y,z,|s|^2)
__device__ int    g_pcell[NSMAX];
__device__ float4 g_sp4[NSMAX];         // cell-sorted
__device__ int    g_sidx[NSMAX];        // original index, cell-sorted
__device__ int    g_qcell[NQMAX];
__device__ int    g_qorder[NQMAX];      // queries sorted by cell
__device__ int    g_cellstart[GRID3 + 1];
__device__ int    g_qstart[GRID3 + 1];
__device__ int    g_cnts[4096];         // cellcnt | +1024 qcnt | +2048 celloff | +3072 qoff
__device__ int    g_done[4];            // 0=pool 1=prepA 2=prepB
__device__ float  g_FS1[NSMAX * CC];
__device__ float  g_XW[NQMAX * CC];

// ---------------- helpers --------------------------------------------------
__device__ __forceinline__ void ins3b(float v, float& b0, float& b1, float& b2)
{
    float h0 = fmaxf(v, b0);  b0 = fminf(v, b0);
    float h1 = fmaxf(h0, b1); b1 = fminf(h0, b1);
    b2 = fminf(h1, b2);
}
__device__ __forceinline__ int cellof(float x, float y, float z)
{
    int cx = min(GRID - 1, max(0, (int)(x * INVH)));
    int cy = min(GRID - 1, max(0, (int)(y * INVH)));
    int cz = min(GRID - 1, max(0, (int)(z * INVH)));
    return (cz * GRID + cy) * GRID + cx;
}
// merge top-3 across the 4-lane subgroup (butterfly; all lanes converge)
__device__ __forceinline__ void merge4(float& b0, float& b1, float& b2)
{
    #pragma unroll
    for (int m = 1; m < 4; m <<= 1) {
        float o0 = __shfl_xor_sync(0xffffffffu, b0, m);
        float o1 = __shfl_xor_sync(0xffffffffu, b1, m);
        float o2 = __shfl_xor_sync(0xffffffffu, b2, m);
        ins3b(o0, b0, b1, b2);
        ins3b(o1, b0, b1, b2);
        ins3b(o2, b0, b1, b2);
    }
}

// ---------------- K1: mega (pool | prepA | prepB | prepC | gemm) -----------
// Wait topology (proven): prepB<-prepA, prepC<-prepB, gemmXW<-pool.
__global__ void __launch_bounds__(BS, 2)
k_mega(const float* __restrict__ F,        // feat_s7
       const float* __restrict__ w,        // w_attn
       const float* __restrict__ coords_s,
       const float* __restrict__ W2,
       const float* __restrict__ Wcls,
       const float* __restrict__ Afs,      // feat_s
       const float* __restrict__ Axw,      // x7
       const float* __restrict__ W1,
       const float* __restrict__ colscale, // gamma
       const float* __restrict__ coords_q,
       int NS, int NQ, int nparts, int ptsB, int qB, int wfB,
       int tilesFS1, int tilesXW)
{
    __shared__ __align__(16) char smraw[29248];
    int tx = threadIdx.x;
    int b = blockIdx.x;
    int prepAB = ptsB + qB + wfB;
    int prepCB = ptsB + qB;

    if (b < nparts) {
        // ================= pool: 32 rows/block, 2 rows/warp =================
        float (*sacc)[CC] = (float (*)[CC])smraw;
        float* sesum = (float*)(smraw + 16 * CC * 4);
        int wp = tx >> 5, lane = tx & 31;
        float w0 = w[lane], w1 = w[lane + 32], w2 = w[lane + 64];
        float w3 = (lane < 16) ? w[lane + 96] : 0.f;
        float p0 = 0.f, p1 = 0.f, p2 = 0.f, p3 = 0.f, es = 0.f;
        int base = b * 32 + wp * 2;
        #pragma unroll
        for (int t = 0; t < 2; t++) {
            int i = base + t;
            if (i < NS) {
                const float* row = F + i * CC;
                float f0 = row[lane];
                float f1 = row[lane + 32];
                float f2 = row[lane + 64];
                float f3 = (lane < 16) ? row[lane + 96] : 0.f;
                float s = f0 * w0 + f1 * w1 + f2 * w2 + f3 * w3;
                #pragma unroll
                for (int o = 16; o; o >>= 1) s += __shfl_xor_sync(0xffffffffu, s, o);
                float e = __expf(s);
                es += e;
                p0 = fmaf(e, f0, p0);
                p1 = fmaf(e, f1, p1);
                p2 = fmaf(e, f2, p2);
                if (lane < 16) p3 = fmaf(e, f3, p3);
            }
        }
        sacc[wp][lane]      = p0;
        sacc[wp][lane + 32] = p1;
        sacc[wp][lane + 64] = p2;
        if (lane < 16) sacc[wp][lane + 96] = p3;
        if (lane == 0) sesum[wp] = es;
        __syncthreads();
        if (tx < CC) {
            float s = 0.f;
            #pragma unroll
            for (int k = 0; k < 16; k++) s += sacc[k][tx];
            g_part[b * CC + tx] = s;
        } else if (tx == CC) {
            float s = 0.f;
            #pragma unroll
            for (int k = 0; k < 16; k++) s += sesum[k];
            g_esum[b] = s;
        }
        __syncthreads();
        if (tx == 0) { __threadfence(); atomicAdd(&g_done[0], 1); }
        return;
    }
    b -= nparts;

    if (b < prepAB) {
        // ===== prepA: point s4+histogram | query cell+histogram | Wf ========
        if (b < ptsB) {
            int i = b * BS + tx;
            if (i < NS) {
                float x = coords_s[i * 3 + 0];
                float y = coords_s[i * 3 + 1];
                float z = coords_s[i * 3 + 2];
                g_s4[i] = make_float4(x, y, z, x * x + y * y + z * z);
                int cell = cellof(x, y, z);
                g_pcell[i] = cell;
                atomicAdd(&g_cnts[cell], 1);
            }
        } else if (b < ptsB + qB) {
            int i = (b - ptsB) * BS + tx;
            if (i < NQ) {
                float x = coords_q[i * 3 + 0];
                float y = coords_q[i * 3 + 1];
                float z = coords_q[i * 3 + 2];
                int cell = cellof(x, y, z);
                g_qcell[i] = cell;
                atomicAdd(&g_cnts[1024 + cell], 1);
            }
        } else {
            int j = (b - ptsB - qB) * BS + tx;
            if (j < CC * CLSN) {
                int c = j / CLSN, o = j % CLSN;
                float s = 0.f;
                #pragma unroll 8
                for (int k = 0; k < CC; k++)
                    s = fmaf(W2[c * CC + k], Wcls[k * CLSN + o], s);
                g_Wf[j] = s;
            }
        }
        __syncthreads();
        if (tx == 0) { __threadfence(); atomicAdd(&g_done[1], 1); }
        return;
    }
    b -= prepAB;

    if (b < 1) {
        // ===== prepB: exclusive prefix sums (points, queries) ===============
        if (tx == 0) {
            while (atomicAdd(&g_done[1], 0) < prepAB) __nanosleep(64);
            __threadfence();
        }
        __syncthreads();
        int* sh = (int*)smraw;
        for (int pass = 0; pass < 2; pass++) {
            int base = pass ? 1024 : 0;
            int* outp = pass ? g_qstart : g_cellstart;
            int e0 = 2 * tx, e1 = 2 * tx + 1;
            int c0 = (e0 < GRID3) ? g_cnts[base + e0] : 0;
            int c1 = (e1 < GRID3) ? g_cnts[base + e1] : 0;
            int local = c0 + c1;
            sh[tx] = local; __syncthreads();
            for (int off = 1; off < 512; off <<= 1) {
                int v = sh[tx];
                int u = (tx >= off) ? sh[tx - off] : 0;
                __syncthreads();
                sh[tx] = v + u;
                __syncthreads();
            }
            int excl = sh[tx] - local;
            if (e0 <= GRID3) outp[e0] = excl;
            if (e1 <= GRID3) outp[e1] = excl + c0;
            __syncthreads();
        }
        if (tx == 0) { __threadfence(); atomicAdd(&g_done[2], 1); }
        return;
    }
    b -= 1;

    if (b < prepCB) {
        // ===== prepC: scatter points | scatter queries ======================
        if (tx == 0) {
            while (atomicAdd(&g_done[2], 0) < 1) __nanosleep(64);
            __threadfence();
        }
        __syncthreads();
        if (b < ptsB) {
            int i = b * BS + tx;
            if (i < NS) {
                int cell = g_pcell[i];
                int pos = g_cellstart[cell] + atomicAdd(&g_cnts[2048 + cell], 1);
                g_sp4[pos] = g_s4[i];
                g_sidx[pos] = i;
            }
        } else {
            int i = (b - ptsB) * BS + tx;
            if (i < NQ) {
                int cell = g_qcell[i];
                int pos = g_qstart[cell] + atomicAdd(&g_cnts[3072 + cell], 1);
                g_qorder[pos] = i;
            }
        }
        return;
    }
    b -= prepCB;

    {
        // ================= gemm: 128x112 tile, 4x7 per thread ===============
        bool isXW = (b >= tilesFS1);
        const float* A  = isXW ? Axw : Afs;
        const float* Bm = isXW ? W1 : (W1 + CC * CC);
        int M  = isXW ? NQ : NS;
        int m0 = (isXW ? (b - tilesFS1) : b) * 128;

        float (*As)[136] = (float (*)[136])smraw;
        float (*Bs)[112] = (float (*)[112])(smraw + 15232);
        float* sgate = (float*)(smraw + 27776);
        float* sred  = (float*)(smraw + 28224);

        if (isXW) {
            if (tx == 0) {
                while (atomicAdd(&g_done[0], 0) < nparts) __nanosleep(64);
                __threadfence();
            }
            __syncthreads();
            if (tx < 256) sred[tx] = (tx < nparts) ? g_esum[tx] : 0.f;
            __syncthreads();
            if (tx < 128) sred[tx] += sred[tx + 128];
            __syncthreads();
            if (tx < 64) sred[tx] += sred[tx + 64];
            __syncthreads();
            if (tx < 32) {
                float v = sred[tx] + sred[tx + 32];
                #pragma unroll
                for (int o = 16; o; o >>= 1) v += __shfl_xor_sync(0xffffffffu, v, o);
                sred[tx] = v;
            }
            __syncthreads();
            float inv_es = 1.f / sred[0];
            if (tx < CC) {
                float s = 0.f;
                #pragma unroll 8
                for (int p = 0; p < nparts; p++) s += g_part[p * CC + tx];
                sgate[tx] = 1.f / (1.f + __expf(-s * inv_es));
            }
            __syncthreads();
        }

        float acc[4][7];
        #pragma unroll
        for (int i = 0; i < 4; i++)
            #pragma unroll
            for (int j = 0; j < 7; j++) acc[i][j] = 0.f;
        int rg = (tx >> 4) * 4;
        int cg = (tx & 15) * 7;

        for (int k0 = 0; k0 < CC; k0 += 28) {
            for (int idx = tx; idx < 128 * 7; idx += BS) {
                int r = idx / 7, k4 = idx - r * 7;
                int gr = m0 + r;
                float4 v = (gr < M) ? *(const float4*)&A[gr * CC + k0 + k4 * 4]
                                    : make_float4(0.f, 0.f, 0.f, 0.f);
                As[k4 * 4 + 0][r] = v.x;
                As[k4 * 4 + 1][r] = v.y;
                As[k4 * 4 + 2][r] = v.z;
                As[k4 * 4 + 3][r] = v.w;
            }
            for (int idx = tx; idx < 28 * 28; idx += BS) {
                int k = idx / 28, c4 = idx - k * 28;
                float4 v = *(const float4*)&Bm[(k0 + k) * CC + c4 * 4];
                if (isXW) {
                    float gsc = sgate[k0 + k];
                    v.x *= gsc; v.y *= gsc; v.z *= gsc; v.w *= gsc;
                }
                *(float4*)&Bs[k][c4 * 4] = v;
            }
            __syncthreads();
            #pragma unroll 4
            for (int k = 0; k < 28; k++) {
                float4 av = *(const float4*)&As[k][rg];
                float a[4] = {av.x, av.y, av.z, av.w};
                float bb[7];
                #pragma unroll
                for (int j = 0; j < 7; j++) bb[j] = Bs[k][cg + j];
                #pragma unroll
                for (int i = 0; i < 4; i++)
                    #pragma unroll
                    for (int j = 0; j < 7; j++)
                        acc[i][j] = fmaf(a[i], bb[j], acc[i][j]);
            }
            __syncthreads();
        }

        float* Cout = isXW ? g_XW : g_FS1;
        float cs[7];
        #pragma unroll
        for (int j = 0; j < 7; j++) cs[j] = colscale[cg + j];
        #pragma unroll
        for (int i = 0; i < 4; i++) {
            int gr = m0 + rg + i;
            if (gr < M) {
                #pragma unroll
                for (int j = 0; j < 7; j++)
                    Cout[(size_t)gr * CC + cg + j] = acc[i][j] * cs[j];
            }
        }
    }
}

// ---------------- K2: grid kNN scan + epilogue, 4 threads per query --------
__global__ void k_scan(const float* __restrict__ coords_q,
                       const float* __restrict__ beta,
                       const float* __restrict__ bcls,
                       float* __restrict__ out,
                       int NQ, int NS)
{
    __shared__ float Wf[CC * CLSN];
    __shared__ float sbeta[CC];
    __shared__ float sb[CLSN];
    __shared__ int   scs[GRID3 + 1];
    int tx = threadIdx.x;

    for (int i = tx; i < CC * CLSN; i += SBS) Wf[i] = g_Wf[i];
    if (tx < CC)   sbeta[tx] = beta[tx];
    if (tx < CLSN) sb[tx] = bcls[tx];
    for (int i = tx; i <= GRID3; i += SBS) scs[i] = g_cellstart[i];
    __syncthreads();

    int slot = blockIdx.x * SBS + tx;
    int wq  = slot >> 2;            // query slot (cell-sorted order)
    int sub = slot & 3;             // sub-thread within query group
    bool valid = (wq < NQ);
    int q = valid ? g_qorder[wq] : 0;
    float qx = coords_q[q * 3 + 0];
    float qy = coords_q[q * 3 + 1];
    float qz = coords_q[q * 3 + 2];
    float nx = -2.f * qx, ny = -2.f * qy, nz = -2.f * qz;
    float q2 = qx * qx + qy * qy + qz * qz;
    int cx = min(GRID - 1, max(0, (int)(qx * INVH)));
    int cy = min(GRID - 1, max(0, (int)(qy * INVH)));
    int cz = min(GRID - 1, max(0, (int)(qz * INVH)));

    float b0 = 1e30f, b1 = 1e30f, b2 = 1e30f;

    // ring D <= 1: 27 cells dealt round-robin to the 4 sub-threads
    for (int c = sub; c < 27; c += 4) {
        int dz = c / 9 - 1, dy = (c / 3) % 3 - 1, dx = c % 3 - 1;
        int ux = cx + dx, uy = cy + dy, uz = cz + dz;
        bool ok = (ux >= 0) & (ux < GRID) & (uy >= 0) & (uy < GRID)
                & (uz >= 0) & (uz < GRID);
        int cell = (uz * GRID + uy) * GRID + ux;
        int p  = ok ? scs[cell] : 0;
        int pe = ok ? scs[cell + 1] : 0;
        for (; p < pe; p++) {
            float4 s = __ldg(&g_sp4[p]);
            int   si = __ldg(&g_sidx[p]);
            float v = fmaf(s.x, nx, fmaf(s.y, ny, fmaf(s.z, nz, s.w))) + q2;
            v = fmaxf(v, 0.f);
            float key = __uint_as_float((__float_as_uint(v) & KEYMASK) | (unsigned)si);
            ins3b(key, b0, b1, b2);
        }
    }
    merge4(b0, b1, b2);   // all 4 lanes now hold the query's merged top-3

    // ring D == 2 (rare)
    float thr1 = CELLH * CELLH - 1.0f;
    if (__any_sync(0xffffffffu, b2 > thr1)) {
        for (int c = sub; c < 125; c += 4) {
            int dz = c / 25 - 2, dy = (c / 5) % 5 - 2, dx = c % 5 - 2;
            if (max(abs(dz), max(abs(dy), abs(dx))) != 2) continue;
            int ux = cx + dx, uy = cy + dy, uz = cz + dz;
            bool ok = (ux >= 0) & (ux < GRID) & (uy >= 0) & (uy < GRID)
                    & (uz >= 0) & (uz < GRID);
            int cell = (uz * GRID + uy) * GRID + ux;
            int p  = ok ? scs[cell] : 0;
            int pe = ok ? scs[cell + 1] : 0;
            for (; p < pe; p++) {
                float4 s = __ldg(&g_sp4[p]);
                int   si = __ldg(&g_sidx[p]);
                float v = fmaf(s.x, nx, fmaf(s.y, ny, fmaf(s.z, nz, s.w))) + q2;
                v = fmaxf(v, 0.f);
                float key = __uint_as_float((__float_as_uint(v) & KEYMASK) | (unsigned)si);
                ins3b(key, b0, b1, b2);
            }
        }
        merge4(b0, b1, b2);
        // full fallback, skipping cells at chebyshev<=2 (essentially never)
        float thr2 = 4.f * CELLH * CELLH - 1.0f;
        if (__any_sync(0xffffffffu, b2 > thr2)) {
            for (int p = sub; p < NS; p += 4) {
                float4 s = g_sp4[p];
                int pcx = min(GRID - 1, max(0, (int)(s.x * INVH)));
                int pcy = min(GRID - 1, max(0, (int)(s.y * INVH)));
                int pcz = min(GRID - 1, max(0, (int)(s.z * INVH)));
                int ch = max(abs(pcx - cx), max(abs(pcy - cy), abs(pcz - cz)));
                float v = fmaf(s.x, nx, fmaf(s.y, ny, fmaf(s.z, nz, s.w))) + q2;
                v = fmaxf(v, 0.f);
                float key = __uint_as_float((__float_as_uint(v) & KEYMASK) | (unsigned)g_sidx[p]);
                if (ch <= 2) key = 1e30f;   // already counted; idempotent sentinel
                ins3b(key, b0, b1, b2);
            }
            merge4(b0, b1, b2);
        }
    }

    int i0 = __float_as_uint(b0) & IDXMASK;
    int i1 = __float_as_uint(b1) & IDXMASK;
    int i2 = __float_as_uint(b2) & IDXMASK;

    // exact d2 recompute (fp32) — all 4 lanes compute identically
    float d[3];
    int idx3[3] = {i0, i1, i2};
    #pragma unroll
    for (int k = 0; k < 3; k++) {
        float4 s = g_s4[idx3[k]];
        d[k] = fmaf(s.x, nx, fmaf(s.y, ny, fmaf(s.z, nz, s.w))) + q2;
    }
    float mn = fminf(d[0], fminf(d[1], d[2]));
    float e0 = __expf(mn - d[0]);
    float e1 = __expf(mn - d[1]);
    float e2 = __expf(mn - d[2]);
    float inv = 1.f / (e0 + e1 + e2);
    float w0 = e0 * inv, w1 = e1 * inv, w2 = e2 * inv;

    const float4* xw = (const float4*)(g_XW + (size_t)q * CC);
    const float4* f0 = (const float4*)(g_FS1 + (size_t)i0 * CC);
    const float4* f1 = (const float4*)(g_FS1 + (size_t)i1 * CC);
    const float4* f2 = (const float4*)(g_FS1 + (size_t)i2 * CC);

    float acc[CLSN];
    #pragma unroll
    for (int o = 0; o < CLSN; o++) acc[o] = 0.f;

    // split the 28 c4-iterations across the 4 sub-threads (7 each)
    for (int c4 = sub; c4 < CC / 4; c4 += 4) {
        float4 x  = xw[c4];
        float4 a0 = f0[c4];
        float4 a1 = f1[c4];
        float4 a2 = f2[c4];
        int cb = c4 * 4;
        float h[4];
        h[0] = x.x + w0 * a0.x + w1 * a1.x + w2 * a2.x + sbeta[cb + 0];
        h[1] = x.y + w0 * a0.y + w1 * a1.y + w2 * a2.y + sbeta[cb + 1];
        h[2] = x.z + w0 * a0.z + w1 * a1.z + w2 * a2.z + sbeta[cb + 2];
        h[3] = x.w + w0 * a0.w + w1 * a1.w + w2 * a2.w + sbeta[cb + 3];
        #pragma unroll
        for (int u = 0; u < 4; u++) {
            float hv = fmaxf(h[u], 0.f);
            const float* wrow = &Wf[(cb + u) * CLSN];
            #pragma unroll
            for (int o = 0; o < CLSN; o++) acc[o] = fmaf(hv, wrow[o], acc[o]);
        }
    }
    // reduce partial acc across the 4-lane group
    #pragma unroll
    for (int m = 1; m < 4; m <<= 1)
        #pragma unroll
        for (int o = 0; o < CLSN; o++)
            acc[o] += __shfl_xor_sync(0xffffffffu, acc[o], m);

    if (!valid || sub != 0) return;
    float* op = out + (size_t)q * CLSN;
    #pragma unroll
    for (int o = 0; o < CLSN; o++) op[o] = acc[o] + sb[o];
}

// ---------------- launch ---------------------------------------------------
extern "C" void kernel_launch(void* const* d_in, const int* in_sizes, int n_in,
                              void* d_out, int out_size)
{
    const float* coords_q = (const float*)d_in[0];
    const float* coords_s = (const float*)d_in[1];
    const float* x7       = (const float*)d_in[2];
    const float* feat_s7  = (const float*)d_in[3];
    const float* feat_s   = (const float*)d_in[4];
    const float* w_attn   = (const float*)d_in[5];
    const float* W1       = (const float*)d_in[6];
    const float* gamma    = (const float*)d_in[7];
    const float* beta     = (const float*)d_in[8];
    const float* W2       = (const float*)d_in[9];
    const float* W_cls    = (const float*)d_in[10];
    const float* b_cls    = (const float*)d_in[11];
    float* out = (float*)d_out;

    int NQ = in_sizes[0] / 3;
    int NS = in_sizes[1] / 3;
    int nparts = (NS + 31) / 32;
    if (nparts > NPOOL) nparts = NPOOL;
    int ptsB = (NS + BS - 1) / BS;
    int qB   = (NQ + BS - 1) / BS;
    int wfB  = (CC * CLSN + BS - 1) / BS;
    int tilesFS1 = (NS + 127) / 128;
    int tilesXW  = (NQ + 127) / 128;
    int grid1 = nparts + (ptsB + qB + wfB) + 1 + (ptsB + qB)
              + (tilesFS1 + tilesXW);
    int grid2 = (4 * NQ + SBS - 1) / SBS;

    int* cntsp; cudaGetSymbolAddress((void**)&cntsp, g_cnts);
    int* donep; cudaGetSymbolAddress((void**)&donep, g_done);
    cudaMemsetAsync(cntsp, 0, 4096 * sizeof(int));
    cudaMemsetAsync(donep, 0, 4 * sizeof(int));

    k_mega<<<grid1, BS>>>(feat_s7, w_attn, coords_s, W2, W_cls,
                          feat_s, x7, W1, gamma, coords_q,
                          NS, NQ, nparts, ptsB, qB, wfB,
                          tilesFS1, tilesXW);
    k_scan<<<grid2, SBS>>>(coords_q, beta, b_cls, out, NQ, NS);
}

// round 17
// speedup vs baseline: 4.4071x; 1.0870x over previous
#include <cuda_runtime.h>

#define CC    112
#define CLSN  20
#define NSMAX 8192
#define NQMAX 20000
#define NPOOL 256
#define IDXMASK 0x1FFFu
#define KEYMASK 0xFFFFE000u
#define BS    512
#define GRID  10
#define GRID3 1000
#define CELLH 12.8f
#define INVH  0.078125f

// ---------------- scratch (device globals; no allocation) ----------------
__device__ float  g_part[NPOOL * CC];
__device__ float  g_esum[NPOOL];
__device__ float  g_Wf[CC * CLSN];
__device__ float4 g_s4[NSMAX];          // original order (x,y,z,|s|^2)
__device__ int    g_pcell[NSMAX];
__device__ float4 g_sp4[NSMAX];         // cell-sorted
__device__ int    g_sidx[NSMAX];        // original index, cell-sorted
__device__ int    g_qcell[NQMAX];
__device__ int    g_qorder[NQMAX];      // queries sorted by cell
__device__ int    g_cellstart[GRID3 + 1];
__device__ int    g_qstart[GRID3 + 1];
__device__ int    g_cnts[4096];
__device__ int    g_done[4];            // 0=pool 1=prepA 2=prepB 3=prepC
__device__ float4 g_sel[NQMAX];         // packed top-3 keys per query
__device__ float  g_FS1[NSMAX * CC];
__device__ float  g_XW[NQMAX * CC];

// ---------------- helpers --------------------------------------------------
__device__ __forceinline__ void ins3b(float v, float& b0, float& b1, float& b2)
{
    float h0 = fmaxf(v, b0);  b0 = fminf(v, b0);
    float h1 = fmaxf(h0, b1); b1 = fminf(h0, b1);
    b2 = fminf(h1, b2);
}
__device__ __forceinline__ int cellof(float x, float y, float z)
{
    int cx = min(GRID - 1, max(0, (int)(x * INVH)));
    int cy = min(GRID - 1, max(0, (int)(y * INVH)));
    int cz = min(GRID - 1, max(0, (int)(z * INVH)));
    return (cz * GRID + cy) * GRID + cx;
}
// merge top-3 across 8-lane subgroup (butterfly; all lanes converge)
__device__ __forceinline__ void merge8(float& b0, float& b1, float& b2)
{
    #pragma unroll
    for (int m = 1; m < 8; m <<= 1) {
        float o0 = __shfl_xor_sync(0xffffffffu, b0, m);
        float o1 = __shfl_xor_sync(0xffffffffu, b1, m);
        float o2 = __shfl_xor_sync(0xffffffffu, b2, m);
        ins3b(o0, b0, b1, b2);
        ins3b(o1, b0, b1, b2);
        ins3b(o2, b0, b1, b2);
    }
}

// ---------------- K1: mega (pool | prepA | prepB | prepC | gemm | knn) -----
// Wait graph (all edges point to LOWER block IDs — provably deadlock-free):
//   prepB<-prepA, prepC<-prepB, gemmXW<-pool, knn<-prepC.
__global__ void __launch_bounds__(BS, 2)
k_mega(const float* __restrict__ F,        // feat_s7
       const float* __restrict__ w,        // w_attn
       const float* __restrict__ coords_s,
       const float* __restrict__ W2,
       const float* __restrict__ Wcls,
       const float* __restrict__ Afs,      // feat_s
       const float* __restrict__ Axw,      // x7
       const float* __restrict__ W1,
       const float* __restrict__ colscale, // gamma
       const float* __restrict__ coords_q,
       int NS, int NQ, int nparts, int ptsB, int qB, int wfB,
       int tilesFS1, int tilesXW)
{
    __shared__ __align__(16) char smraw[29248];
    int tx = threadIdx.x;
    int b = blockIdx.x;
    int prepAB = ptsB + qB + wfB;
    int prepCB = ptsB + qB;
    int ngemm = tilesFS1 + tilesXW;

    if (b < nparts) {
        // ================= pool =================
        float (*sacc)[CC] = (float (*)[CC])smraw;
        float* sesum = (float*)(smraw + 16 * CC * 4);
        int wp = tx >> 5, lane = tx & 31;
        float w0 = w[lane], w1 = w[lane + 32], w2 = w[lane + 64];
        float w3 = (lane < 16) ? w[lane + 96] : 0.f;
        float p0 = 0.f, p1 = 0.f, p2 = 0.f, p3 = 0.f, es = 0.f;
        int base = b * 32 + wp * 2;
        #pragma unroll
        for (int t = 0; t < 2; t++) {
            int i = base + t;
            if (i < NS) {
                const float* row = F + i * CC;
                float f0 = row[lane];
                float f1 = row[lane + 32];
                float f2 = row[lane + 64];
                float f3 = (lane < 16) ? row[lane + 96] : 0.f;
                float s = f0 * w0 + f1 * w1 + f2 * w2 + f3 * w3;
                #pragma unroll
                for (int o = 16; o; o >>= 1) s += __shfl_xor_sync(0xffffffffu, s, o);
                float e = __expf(s);
                es += e;
                p0 = fmaf(e, f0, p0);
                p1 = fmaf(e, f1, p1);
                p2 = fmaf(e, f2, p2);
                if (lane < 16) p3 = fmaf(e, f3, p3);
            }
        }
        sacc[wp][lane]      = p0;
        sacc[wp][lane + 32] = p1;
        sacc[wp][lane + 64] = p2;
        if (lane < 16) sacc[wp][lane + 96] = p3;
        if (lane == 0) sesum[wp] = es;
        __syncthreads();
        if (tx < CC) {
            float s = 0.f;
            #pragma unroll
            for (int k = 0; k < 16; k++) s += sacc[k][tx];
            g_part[b * CC + tx] = s;
        } else if (tx == CC) {
            float s = 0.f;
            #pragma unroll
            for (int k = 0; k < 16; k++) s += sesum[k];
            g_esum[b] = s;
        }
        __syncthreads();
        if (tx == 0) { __threadfence(); atomicAdd(&g_done[0], 1); }
        return;
    }
    b -= nparts;

    if (b < prepAB) {
        // ===== prepA =====
        if (b < ptsB) {
            int i = b * BS + tx;
            if (i < NS) {
                float x = coords_s[i * 3 + 0];
                float y = coords_s[i * 3 + 1];
                float z = coords_s[i * 3 + 2];
                g_s4[i] = make_float4(x, y, z, x * x + y * y + z * z);
                int cell = cellof(x, y, z);
                g_pcell[i] = cell;
                atomicAdd(&g_cnts[cell], 1);
            }
        } else if (b < ptsB + qB) {
            int i = (b - ptsB) * BS + tx;
            if (i < NQ) {
                float x = coords_q[i * 3 + 0];
                float y = coords_q[i * 3 + 1];
                float z = coords_q[i * 3 + 2];
                int cell = cellof(x, y, z);
                g_qcell[i] = cell;
                atomicAdd(&g_cnts[1024 + cell], 1);
            }
        } else {
            int j = (b - ptsB - qB) * BS + tx;
            if (j < CC * CLSN) {
                int c = j / CLSN, o = j % CLSN;
                float s = 0.f;
                #pragma unroll 8
                for (int k = 0; k < CC; k++)
                    s = fmaf(W2[c * CC + k], Wcls[k * CLSN + o], s);
                g_Wf[j] = s;
            }
        }
        __syncthreads();
        if (tx == 0) { __threadfence(); atomicAdd(&g_done[1], 1); }
        return;
    }
    b -= prepAB;

    if (b < 1) {
        // ===== prepB: prefix sums =====
        if (tx == 0) {
            while (atomicAdd(&g_done[1], 0) < prepAB) __nanosleep(64);
            __threadfence();
        }
        __syncthreads();
        int* sh = (int*)smraw;
        for (int pass = 0; pass < 2; pass++) {
            int base = pass ? 1024 : 0;
            int* outp = pass ? g_qstart : g_cellstart;
            int e0 = 2 * tx, e1 = 2 * tx + 1;
            int c0 = (e0 < GRID3) ? g_cnts[base + e0] : 0;
            int c1 = (e1 < GRID3) ? g_cnts[base + e1] : 0;
            int local = c0 + c1;
            sh[tx] = local; __syncthreads();
            for (int off = 1; off < 512; off <<= 1) {
                int v = sh[tx];
                int u = (tx >= off) ? sh[tx - off] : 0;
                __syncthreads();
                sh[tx] = v + u;
                __syncthreads();
            }
            int excl = sh[tx] - local;
            if (e0 <= GRID3) outp[e0] = excl;
            if (e1 <= GRID3) outp[e1] = excl + c0;
            __syncthreads();
        }
        if (tx == 0) { __threadfence(); atomicAdd(&g_done[2], 1); }
        return;
    }
    b -= 1;

    if (b < prepCB) {
        // ===== prepC: scatter =====
        if (tx == 0) {
            while (atomicAdd(&g_done[2], 0) < 1) __nanosleep(64);
            __threadfence();
        }
        __syncthreads();
        if (b < ptsB) {
            int i = b * BS + tx;
            if (i < NS) {
                int cell = g_pcell[i];
                int pos = g_cellstart[cell] + atomicAdd(&g_cnts[2048 + cell], 1);
                g_sp4[pos] = g_s4[i];
                g_sidx[pos] = i;
            }
        } else {
            int i = (b - ptsB) * BS + tx;
            if (i < NQ) {
                int cell = g_qcell[i];
                int pos = g_qstart[cell] + atomicAdd(&g_cnts[3072 + cell], 1);
                g_qorder[pos] = i;
            }
        }
        __syncthreads();
        if (tx == 0) { __threadfence(); atomicAdd(&g_done[3], 1); }
        return;
    }
    b -= prepCB;

    if (b < ngemm) {
        // ================= gemm: 128x112 tile, 4x7 per thread ===============
        bool isXW = (b >= tilesFS1);
        const float* A  = isXW ? Axw : Afs;
        const float* Bm = isXW ? W1 : (W1 + CC * CC);
        int M  = isXW ? NQ : NS;
        int m0 = (isXW ? (b - tilesFS1) : b) * 128;

        float (*As)[136] = (float (*)[136])smraw;
        float (*Bs)[112] = (float (*)[112])(smraw + 15232);
        float* sgate = (float*)(smraw + 27776);
        float* sred  = (float*)(smraw + 28224);

        if (isXW) {
            if (tx == 0) {
                while (atomicAdd(&g_done[0], 0) < nparts) __nanosleep(64);
                __threadfence();
            }
            __syncthreads();
            if (tx < 256) sred[tx] = (tx < nparts) ? g_esum[tx] : 0.f;
            __syncthreads();
            if (tx < 128) sred[tx] += sred[tx + 128];
            __syncthreads();
            if (tx < 64) sred[tx] += sred[tx + 64];
            __syncthreads();
            if (tx < 32) {
                float v = sred[tx] + sred[tx + 32];
                #pragma unroll
                for (int o = 16; o; o >>= 1) v += __shfl_xor_sync(0xffffffffu, v, o);
                sred[tx] = v;
            }
            __syncthreads();
            float inv_es = 1.f / sred[0];
            if (tx < CC) {
                float s = 0.f;
                #pragma unroll 8
                for (int p = 0; p < nparts; p++) s += g_part[p * CC + tx];
                sgate[tx] = 1.f / (1.f + __expf(-s * inv_es));
            }
            __syncthreads();
        }

        float acc[4][7];
        #pragma unroll
        for (int i = 0; i < 4; i++)
            #pragma unroll
            for (int j = 0; j < 7; j++) acc[i][j] = 0.f;
        int rg = (tx >> 4) * 4;
        int cg = (tx & 15) * 7;

        for (int k0 = 0; k0 < CC; k0 += 28) {
            for (int idx = tx; idx < 128 * 7; idx += BS) {
                int r = idx / 7, k4 = idx - r * 7;
                int gr = m0 + r;
                float4 v = (gr < M) ? *(const float4*)&A[gr * CC + k0 + k4 * 4]
                                    : make_float4(0.f, 0.f, 0.f, 0.f);
                As[k4 * 4 + 0][r] = v.x;
                As[k4 * 4 + 1][r] = v.y;
                As[k4 * 4 + 2][r] = v.z;
                As[k4 * 4 + 3][r] = v.w;
            }
            for (int idx = tx; idx < 28 * 28; idx += BS) {
                int k = idx / 28, c4 = idx - k * 28;
                float4 v = *(const float4*)&Bm[(k0 + k) * CC + c4 * 4];
                if (isXW) {
                    float gsc = sgate[k0 + k];
                    v.x *= gsc; v.y *= gsc; v.z *= gsc; v.w *= gsc;
                }
                *(float4*)&Bs[k][c4 * 4] = v;
            }
            __syncthreads();
            #pragma unroll 4
            for (int k = 0; k < 28; k++) {
                float4 av = *(const float4*)&As[k][rg];
                float a[4] = {av.x, av.y, av.z, av.w};
                float bb[7];
                #pragma unroll
                for (int j = 0; j < 7; j++) bb[j] = Bs[k][cg + j];
                #pragma unroll
                for (int i = 0; i < 4; i++)
                    #pragma unroll
                    for (int j = 0; j < 7; j++)
                        acc[i][j] = fmaf(a[i], bb[j], acc[i][j]);
            }
            __syncthreads();
        }

        float* Cout = isXW ? g_XW : g_FS1;
        float cs[7];
        #pragma unroll
        for (int j = 0; j < 7; j++) cs[j] = colscale[cg + j];
        #pragma unroll
        for (int i = 0; i < 4; i++) {
            int gr = m0 + rg + i;
            if (gr < M) {
                #pragma unroll
                for (int j = 0; j < 7; j++)
                    Cout[(size_t)gr * CC + cg + j] = acc[i][j] * cs[j];
            }
        }
        return;
    }
    b -= ngemm;

    // ================= knn: 8 threads/query, waits ONLY on prepC ===========
    {
        int* scs = (int*)smraw;   // cellstart cache (4004 B)
        if (tx == 0) {
            while (atomicAdd(&g_done[3], 0) < prepCB) __nanosleep(64);
            __threadfence();
        }
        __syncthreads();
        for (int i = tx; i <= GRID3; i += BS) scs[i] = g_cellstart[i];
        __syncthreads();

        int slot = b * BS + tx;
        int wq  = slot >> 3;
        int sub = slot & 7;
        bool valid = (wq < NQ);
        int q = valid ? g_qorder[wq] : 0;
        float qx = coords_q[q * 3 + 0];
        float qy = coords_q[q * 3 + 1];
        float qz = coords_q[q * 3 + 2];
        float nx = -2.f * qx, ny = -2.f * qy, nz = -2.f * qz;
        float q2 = qx * qx + qy * qy + qz * qz;
        int cx = min(GRID - 1, max(0, (int)(qx * INVH)));
        int cy = min(GRID - 1, max(0, (int)(qy * INVH)));
        int cz = min(GRID - 1, max(0, (int)(qz * INVH)));

        float b0 = 1e30f, b1 = 1e30f, b2 = 1e30f;

        for (int c = sub; c < 27; c += 8) {
            int dz = c / 9 - 1, dy = (c / 3) % 3 - 1, dx = c % 3 - 1;
            int ux = cx + dx, uy = cy + dy, uz = cz + dz;
            bool ok = (ux >= 0) & (ux < GRID) & (uy >= 0) & (uy < GRID)
                    & (uz >= 0) & (uz < GRID);
            int cell = (uz * GRID + uy) * GRID + ux;
            int p  = ok ? scs[cell] : 0;
            int pe = ok ? scs[cell + 1] : 0;
            for (; p < pe; p++) {
                float4 s = __ldg(&g_sp4[p]);
                int   si = __ldg(&g_sidx[p]);
                float v = fmaf(s.x, nx, fmaf(s.y, ny, fmaf(s.z, nz, s.w))) + q2;
                v = fmaxf(v, 0.f);
                float key = __uint_as_float((__float_as_uint(v) & KEYMASK) | (unsigned)si);
                ins3b(key, b0, b1, b2);
            }
        }
        merge8(b0, b1, b2);

        float thr1 = CELLH * CELLH - 1.0f;
        if (__any_sync(0xffffffffu, b2 > thr1)) {
            for (int c = sub; c < 125; c += 8) {
                int dz = c / 25 - 2, dy = (c / 5) % 5 - 2, dx = c % 5 - 2;
                if (max(abs(dz), max(abs(dy), abs(dx))) != 2) continue;
                int ux = cx + dx, uy = cy + dy, uz = cz + dz;
                bool ok = (ux >= 0) & (ux < GRID) & (uy >= 0) & (uy < GRID)
                        & (uz >= 0) & (uz < GRID);
                int cell = (uz * GRID + uy) * GRID + ux;
                int p  = ok ? scs[cell] : 0;
                int pe = ok ? scs[cell + 1] : 0;
                for (; p < pe; p++) {
                    float4 s = __ldg(&g_sp4[p]);
                    int   si = __ldg(&g_sidx[p]);
                    float v = fmaf(s.x, nx, fmaf(s.y, ny, fmaf(s.z, nz, s.w))) + q2;
                    v = fmaxf(v, 0.f);
                    float key = __uint_as_float((__float_as_uint(v) & KEYMASK) | (unsigned)si);
                    ins3b(key, b0, b1, b2);
                }
            }
            merge8(b0, b1, b2);
            float thr2 = 4.f * CELLH * CELLH - 1.0f;
            if (__any_sync(0xffffffffu, b2 > thr2)) {
                for (int p = sub; p < NS; p += 8) {
                    float4 s = g_sp4[p];
                    int pcx = min(GRID - 1, max(0, (int)(s.x * INVH)));
                    int pcy = min(GRID - 1, max(0, (int)(s.y * INVH)));
                    int pcz = min(GRID - 1, max(0, (int)(s.z * INVH)));
                    int ch = max(abs(pcx - cx), max(abs(pcy - cy), abs(pcz - cz)));
                    float v = fmaf(s.x, nx, fmaf(s.y, ny, fmaf(s.z, nz, s.w))) + q2;
                    v = fmaxf(v, 0.f);
                    float key = __uint_as_float((__float_as_uint(v) & KEYMASK) | (unsigned)g_sidx[p]);
                    if (ch <= 2) key = 1e30f;
                    ins3b(key, b0, b1, b2);
                }
                merge8(b0, b1, b2);
            }
        }

        if (valid && sub == 0)
            g_sel[q] = make_float4(b0, b1, b2, 0.f);
    }
}

// ---------------- K2: epilogue — 4 threads/query ---------------------------
__global__ void k_epi(const float* __restrict__ coords_q,
                      const float* __restrict__ beta,
                      const float* __restrict__ bcls,
                      float* __restrict__ out,
                      int NQ)
{
    __shared__ float Wf[CC * CLSN];
    __shared__ float sbeta[CC];
    __shared__ float sb[CLSN];
    int tx = threadIdx.x;
    for (int i = tx; i < CC * CLSN; i += 256) Wf[i] = g_Wf[i];
    if (tx < CC)   sbeta[tx] = beta[tx];
    if (tx < CLSN) sb[tx] = bcls[tx];
    __syncthreads();

    int slot = blockIdx.x * 256 + tx;
    int q   = slot >> 2;
    int sub = slot & 3;
    if (q >= NQ) return;

    float qx = coords_q[q * 3 + 0];
    float qy = coords_q[q * 3 + 1];
    float qz = coords_q[q * 3 + 2];
    float nx = -2.f * qx, ny = -2.f * qy, nz = -2.f * qz;
    float q2 = qx * qx + qy * qy + qz * qz;

    float4 sel = g_sel[q];
    int i0 = __float_as_uint(sel.x) & IDXMASK;
    int i1 = __float_as_uint(sel.y) & IDXMASK;
    int i2 = __float_as_uint(sel.z) & IDXMASK;

    // exact d2 recompute (fp32)
    float d[3];
    int idx3[3] = {i0, i1, i2};
    #pragma unroll
    for (int k = 0; k < 3; k++) {
        float4 s = g_s4[idx3[k]];
        d[k] = fmaf(s.x, nx, fmaf(s.y, ny, fmaf(s.z, nz, s.w))) + q2;
    }
    float mn = fminf(d[0], fminf(d[1], d[2]));
    float e0 = __expf(mn - d[0]);
    float e1 = __expf(mn - d[1]);
    float e2 = __expf(mn - d[2]);
    float inv = 1.f / (e0 + e1 + e2);
    float w0 = e0 * inv, w1 = e1 * inv, w2 = e2 * inv;

    const float4* xw = (const float4*)(g_XW + (size_t)q * CC);
    const float4* f0 = (const float4*)(g_FS1 + (size_t)i0 * CC);
    const float4* f1 = (const float4*)(g_FS1 + (size_t)i1 * CC);
    const float4* f2 = (const float4*)(g_FS1 + (size_t)i2 * CC);

    float acc[CLSN];
    #pragma unroll
    for (int o = 0; o < CLSN; o++) acc[o] = 0.f;

    for (int c4 = sub; c4 < CC / 4; c4 += 4) {
        float4 x  = xw[c4];
        float4 a0 = f0[c4];
        float4 a1 = f1[c4];
        float4 a2 = f2[c4];
        int cb = c4 * 4;
        float h[4];
        h[0] = x.x + w0 * a0.x + w1 * a1.x + w2 * a2.x + sbeta[cb + 0];
        h[1] = x.y + w0 * a0.y + w1 * a1.y + w2 * a2.y + sbeta[cb + 1];
        h[2] = x.z + w0 * a0.z + w1 * a1.z + w2 * a2.z + sbeta[cb + 2];
        h[3] = x.w + w0 * a0.w + w1 * a1.w + w2 * a2.w + sbeta[cb + 3];
        #pragma unroll
        for (int u = 0; u < 4; u++) {
            float hv = fmaxf(h[u], 0.f);
            const float* wrow = &Wf[(cb + u) * CLSN];
            #pragma unroll
            for (int o = 0; o < CLSN; o++) acc[o] = fmaf(hv, wrow[o], acc[o]);
        }
    }
    #pragma unroll
    for (int m = 1; m < 4; m <<= 1)
        #pragma unroll
        for (int o = 0; o < CLSN; o++)
            acc[o] += __shfl_xor_sync(0xffffffffu, acc[o], m);

    if (sub != 0) return;
    float* op = out + (size_t)q * CLSN;
    #pragma unroll
    for (int o = 0; o < CLSN; o++) op[o] = acc[o] + sb[o];
}

// ---------------- launch ---------------------------------------------------
extern "C" void kernel_launch(void* const* d_in, const int* in_sizes, int n_in,
                              void* d_out, int out_size)
{
    const float* coords_q = (const float*)d_in[0];
    const float* coords_s = (const float*)d_in[1];
    const float* x7       = (const float*)d_in[2];
    const float* feat_s7  = (const float*)d_in[3];
    const float* feat_s   = (const float*)d_in[4];
    const float* w_attn   = (const float*)d_in[5];
    const float* W1       = (const float*)d_in[6];
    const float* gamma    = (const float*)d_in[7];
    const float* beta     = (const float*)d_in[8];
    const float* W2       = (const float*)d_in[9];
    const float* W_cls    = (const float*)d_in[10];
    const float* b_cls    = (const float*)d_in[11];
    float* out = (float*)d_out;

    int NQ = in_sizes[0] / 3;
    int NS = in_sizes[1] / 3;
    int nparts = (NS + 31) / 32;
    if (nparts > NPOOL) nparts = NPOOL;
    int ptsB = (NS + BS - 1) / BS;
    int qB   = (NQ + BS - 1) / BS;
    int wfB  = (CC * CLSN + BS - 1) / BS;
    int tilesFS1 = (NS + 127) / 128;
    int tilesXW  = (NQ + 127) / 128;
    int knnB = (8 * NQ + BS - 1) / BS;
    int grid1 = nparts + (ptsB + qB + wfB) + 1 + (ptsB + qB)
              + (tilesFS1 + tilesXW) + knnB;
    int grid2 = (4 * NQ + 255) / 256;

    int* cntsp; cudaGetSymbolAddress((void**)&cntsp, g_cnts);
    int* donep; cudaGetSymbolAddress((void**)&donep, g_done);
    cudaMemsetAsync(cntsp, 0, 4096 * sizeof(int));
    cudaMemsetAsync(donep, 0, 4 * sizeof(int));

    k_mega<<<grid1, BS>>>(feat_s7, w_attn, coords_s, W2, W_cls,
                          feat_s, x7, W1, gamma, coords_q,
                          NS, NQ, nparts, ptsB, qB, wfB,
                          tilesFS1, tilesXW);
    k_epi<<<grid2, 256>>>(coords_q, beta, b_cls, out, NQ);
}